// round 1
// baseline (speedup 1.0000x reference)
#include <cuda_runtime.h>
#include <math.h>

// Problem constants
#define B_    4
#define S_    2048
#define E_    1024
#define H_    16
#define DH_   64
#define M_    (B_*S_)      // 8192 rows (B*S)
#define FF_   4096
#define NQKV_ 3072

// ---------------------------------------------------------------------------
// Scratch (static __device__ arrays -- no allocation allowed)
// ---------------------------------------------------------------------------
__device__ float g_lx  [(size_t)M_*E_];     // ln1(x)
__device__ float g_wqkv[(size_t)E_*NQKV_];  // packed [E, 3E] qkv weight
__device__ float g_qkv [(size_t)M_*NQKV_];  // q|k|v, head-concat columns
__device__ float g_o   [(size_t)M_*E_];     // attention output (head concat)
__device__ float g_x2  [(size_t)M_*E_];     // x + attn proj (residual 1)
__device__ float g_lx2 [(size_t)M_*E_];     // ln2(x2)
__device__ float g_ffh [(size_t)M_*FF_];    // relu(lx2 @ W1 + b1)

// ---------------------------------------------------------------------------
// LayerNorm: one block per row, 256 threads, 4 elems each
// ---------------------------------------------------------------------------
__global__ void ln_kernel(const float* __restrict__ x, const float* __restrict__ g,
                          const float* __restrict__ b, float* __restrict__ out)
{
    int row = blockIdx.x;
    int t = threadIdx.x;
    const float* xr = x + (size_t)row * E_;
    float v[4];
    float s = 0.f, s2 = 0.f;
#pragma unroll
    for (int i = 0; i < 4; i++) {
        v[i] = xr[t + 256*i];
        s += v[i];
        s2 += v[i]*v[i];
    }
#pragma unroll
    for (int m = 16; m; m >>= 1) {
        s  += __shfl_xor_sync(0xffffffffu, s,  m);
        s2 += __shfl_xor_sync(0xffffffffu, s2, m);
    }
    __shared__ float sh[2][8];
    if ((t & 31) == 0) { sh[0][t>>5] = s; sh[1][t>>5] = s2; }
    __syncthreads();
    s = 0.f; s2 = 0.f;
#pragma unroll
    for (int w = 0; w < 8; w++) { s += sh[0][w]; s2 += sh[1][w]; }
    float mu  = s * (1.f/E_);
    float var = s2 * (1.f/E_) - mu*mu;
    float r = rsqrtf(var + 1e-5f);
    float* orow = out + (size_t)row * E_;
#pragma unroll
    for (int i = 0; i < 4; i++) {
        int c = t + 256*i;
        orow[c] = (v[i]-mu)*r*g[c] + b[c];
    }
}

// ---------------------------------------------------------------------------
// Pack Wq/Wk/Wv (each [H,E,DH]) into a single row-major [E, 3E] matrix where
// column n = head-concat layout (h*64+d), q | k | v blocks of 1024 cols.
// ---------------------------------------------------------------------------
__global__ void pack_qkv_kernel(const float* __restrict__ Wq, const float* __restrict__ Wk,
                                const float* __restrict__ Wv, float* __restrict__ out)
{
    int idx = blockIdx.x*256 + threadIdx.x;          // < E_*NQKV_
    int e = idx / NQKV_;
    int n = idx - e*NQKV_;
    const float* W = (n < 1024) ? Wq : (n < 2048 ? Wk : Wv);
    int hd = n & 1023;
    out[idx] = W[(size_t)(hd >> 6)*(E_*DH_) + (size_t)e*DH_ + (hd & 63)];
}

// ---------------------------------------------------------------------------
// SGEMM: C[M,N] = A[M,K] @ B[K,N] (+epilogue). Row-major everything.
// Tiles: 128x128x16, 256 threads, 8x8 per-thread accumulator.
// EPI: 0 = none, 1 = +bias[col] + res[row,col], 2 = relu(+bias[col])
// All M,N divisible by 128, K divisible by 16 in this problem (no bounds).
// ---------------------------------------------------------------------------
template<int EPI>
__global__ void __launch_bounds__(256, 2) sgemm_kernel(
    const float* __restrict__ A, const float* __restrict__ Bm, float* __restrict__ C,
    const float* __restrict__ bias, const float* __restrict__ res, int K, int N)
{
    __shared__ float As[16][128];
    __shared__ float Bs[16][128];
    int tid = threadIdx.x;
    int mblk = blockIdx.y * 128, nblk = blockIdx.x * 128;
    int ty = tid >> 4, tx = tid & 15;
    int am = tid >> 2, ak = (tid & 3) << 2;     // A tile: 2 float4 per thread
    int bk = tid >> 5, bn = (tid & 31) << 2;    // B tile: 2 float4 per thread
    const float* Ap = A + (size_t)(mblk + am) * K + ak;
    const float* Bp = Bm + (size_t)bk * N + nblk + bn;

    float acc[8][8];
#pragma unroll
    for (int i = 0; i < 8; i++)
#pragma unroll
        for (int j = 0; j < 8; j++) acc[i][j] = 0.f;

    for (int k0 = 0; k0 < K; k0 += 16) {
        float4 a0 = *(const float4*)Ap;
        float4 a1 = *(const float4*)(Ap + (size_t)64*K);
        float4 b0 = *(const float4*)Bp;
        float4 b1 = *(const float4*)(Bp + (size_t)8*N);
        __syncthreads();
        As[ak+0][am]    = a0.x; As[ak+1][am]    = a0.y; As[ak+2][am]    = a0.z; As[ak+3][am]    = a0.w;
        As[ak+0][am+64] = a1.x; As[ak+1][am+64] = a1.y; As[ak+2][am+64] = a1.z; As[ak+3][am+64] = a1.w;
        *(float4*)&Bs[bk  ][bn] = b0;
        *(float4*)&Bs[bk+8][bn] = b1;
        __syncthreads();
#pragma unroll
        for (int kk = 0; kk < 16; kk++) {
            float ar[8], br[8];
            *(float4*)(ar)   = *(const float4*)&As[kk][ty*8];
            *(float4*)(ar+4) = *(const float4*)&As[kk][ty*8+4];
            *(float4*)(br)   = *(const float4*)&Bs[kk][tx*8];
            *(float4*)(br+4) = *(const float4*)&Bs[kk][tx*8+4];
#pragma unroll
            for (int i = 0; i < 8; i++)
#pragma unroll
                for (int j = 0; j < 8; j++)
                    acc[i][j] = fmaf(ar[i], br[j], acc[i][j]);
        }
        Ap += 16;
        Bp += (size_t)16*N;
    }

#pragma unroll
    for (int i = 0; i < 8; i++) {
        int row = mblk + ty*8 + i;
#pragma unroll
        for (int j = 0; j < 8; j++) {
            int col = nblk + tx*8 + j;
            float v = acc[i][j];
            if (EPI >= 1) v += bias[col];
            if (EPI == 1) v += res[(size_t)row*N + col];
            if (EPI == 2) v = fmaxf(v, 0.f);
            C[(size_t)row*N + col] = v;
        }
    }
}

// ---------------------------------------------------------------------------
// Flash attention, fp32, causal. One CTA per (query-tile of 64, b, h).
// Online softmax, 64x64 tiles, DH=64. 256 threads as 16x16; each thread owns
// a 4(row)x4(col) microtile for both the QK^T and PV GEMMs.
// Shared: qs [64][64], ksT [64][68] (k transposed -> contiguous float4 operand
// reads), vs [64][68], ps [64][68].
// ---------------------------------------------------------------------------
#define APAD 68
#define ATTN_SMEM ((64*64 + 3*64*APAD) * 4)   // 68608 bytes

__global__ void __launch_bounds__(256, 1) attn_kernel(const float* __restrict__ qkv,
                                                      float* __restrict__ o)
{
    extern __shared__ float smf[];
    float* qs  = smf;               // [64][64]   q[r][d]
    float* ksT = qs + 64*64;        // [64][APAD] kT[d][j]
    float* vs  = ksT + 64*APAD;     // [64][APAD] v[j][d]
    float* ps  = vs + 64*APAD;      // [64][APAD] p[r][j]

    int tid = threadIdx.x;
    int qt = blockIdx.x;                 // query tile (0..31)
    int b = blockIdx.y >> 4, h = blockIdx.y & 15;
    int ty = tid >> 4, tx = tid & 15;
    int r0 = ty*4, c0 = tx*4;
    size_t rowbase = (size_t)b * S_;
    int qcol = h*64, kcol = 1024 + h*64, vcol = 2048 + h*64;

    // load q tile [64 tokens x 64 d]
    for (int jj = ty; jj < 64; jj += 16) {
        float4 vq = *(const float4*)&qkv[(rowbase + (size_t)qt*64 + jj)*NQKV_ + qcol + tx*4];
        *(float4*)&qs[jj*64 + tx*4] = vq;
    }

    float mreg[4], lreg[4], oacc[4][4];
#pragma unroll
    for (int i = 0; i < 4; i++) {
        mreg[i] = -1e30f; lreg[i] = 0.f;
#pragma unroll
        for (int j = 0; j < 4; j++) oacc[i][j] = 0.f;
    }

    for (int t = 0; t <= qt; t++) {
        __syncthreads();   // previous iteration's ps/vs reads done before overwrite
        // load K (transposed) and V tiles
        for (int jj = ty; jj < 64; jj += 16) {
            size_t tok = (rowbase + (size_t)t*64 + jj) * NQKV_;
            float4 kv = *(const float4*)&qkv[tok + kcol + tx*4];
            ksT[(tx*4+0)*APAD + jj] = kv.x;
            ksT[(tx*4+1)*APAD + jj] = kv.y;
            ksT[(tx*4+2)*APAD + jj] = kv.z;
            ksT[(tx*4+3)*APAD + jj] = kv.w;
            float4 vv = *(const float4*)&qkv[tok + vcol + tx*4];
            *(float4*)&vs[jj*APAD + tx*4] = vv;
        }
        __syncthreads();

        // scores s[i][j] = sum_d q[r0+i][d] * k[c0+j][d]
        float s[4][4];
#pragma unroll
        for (int i = 0; i < 4; i++)
#pragma unroll
            for (int j = 0; j < 4; j++) s[i][j] = 0.f;
        for (int d = 0; d < 64; d++) {
            float a0 = qs[(r0+0)*64 + d];
            float a1 = qs[(r0+1)*64 + d];
            float a2 = qs[(r0+2)*64 + d];
            float a3 = qs[(r0+3)*64 + d];
            float4 bv = *(const float4*)&ksT[d*APAD + c0];
            s[0][0] = fmaf(a0, bv.x, s[0][0]); s[0][1] = fmaf(a0, bv.y, s[0][1]);
            s[0][2] = fmaf(a0, bv.z, s[0][2]); s[0][3] = fmaf(a0, bv.w, s[0][3]);
            s[1][0] = fmaf(a1, bv.x, s[1][0]); s[1][1] = fmaf(a1, bv.y, s[1][1]);
            s[1][2] = fmaf(a1, bv.z, s[1][2]); s[1][3] = fmaf(a1, bv.w, s[1][3]);
            s[2][0] = fmaf(a2, bv.x, s[2][0]); s[2][1] = fmaf(a2, bv.y, s[2][1]);
            s[2][2] = fmaf(a2, bv.z, s[2][2]); s[2][3] = fmaf(a2, bv.w, s[2][3]);
            s[3][0] = fmaf(a3, bv.x, s[3][0]); s[3][1] = fmaf(a3, bv.y, s[3][1]);
            s[3][2] = fmaf(a3, bv.z, s[3][2]); s[3][3] = fmaf(a3, bv.w, s[3][3]);
        }

        // scale + causal mask (only the diagonal tile needs masking)
#pragma unroll
        for (int i = 0; i < 4; i++)
#pragma unroll
            for (int j = 0; j < 4; j++) {
                float sv = s[i][j] * 0.125f;   // 1/sqrt(64)
                if (t == qt && (c0+j) > (r0+i)) sv = -1e30f;
                s[i][j] = sv;
            }

        // online softmax update; row reductions across the 16 tx lanes
#pragma unroll
        for (int i = 0; i < 4; i++) {
            float mm = fmaxf(fmaxf(s[i][0], s[i][1]), fmaxf(s[i][2], s[i][3]));
#pragma unroll
            for (int msk = 8; msk; msk >>= 1)
                mm = fmaxf(mm, __shfl_xor_sync(0xffffffffu, mm, msk));
            float mnew = fmaxf(mreg[i], mm);
            float alpha = expf(mreg[i] - mnew);
            float ls = 0.f;
#pragma unroll
            for (int j = 0; j < 4; j++) {
                float p = expf(s[i][j] - mnew);
                s[i][j] = p;
                ls += p;
            }
#pragma unroll
            for (int msk = 8; msk; msk >>= 1)
                ls += __shfl_xor_sync(0xffffffffu, ls, msk);
            lreg[i] = lreg[i]*alpha + ls;
            mreg[i] = mnew;
#pragma unroll
            for (int j = 0; j < 4; j++) oacc[i][j] *= alpha;
        }

        // stage p to shared for the PV GEMM
#pragma unroll
        for (int i = 0; i < 4; i++) {
            float4 pv = make_float4(s[i][0], s[i][1], s[i][2], s[i][3]);
            *(float4*)&ps[(r0+i)*APAD + c0] = pv;
        }
        __syncthreads();

        // oacc[i][j] += sum_k p[r0+i][k] * v[k][c0+j]
        for (int kkk = 0; kkk < 64; kkk++) {
            float a0 = ps[(r0+0)*APAD + kkk];
            float a1 = ps[(r0+1)*APAD + kkk];
            float a2 = ps[(r0+2)*APAD + kkk];
            float a3 = ps[(r0+3)*APAD + kkk];
            float4 bv = *(const float4*)&vs[kkk*APAD + c0];
            oacc[0][0] = fmaf(a0, bv.x, oacc[0][0]); oacc[0][1] = fmaf(a0, bv.y, oacc[0][1]);
            oacc[0][2] = fmaf(a0, bv.z, oacc[0][2]); oacc[0][3] = fmaf(a0, bv.w, oacc[0][3]);
            oacc[1][0] = fmaf(a1, bv.x, oacc[1][0]); oacc[1][1] = fmaf(a1, bv.y, oacc[1][1]);
            oacc[1][2] = fmaf(a1, bv.z, oacc[1][2]); oacc[1][3] = fmaf(a1, bv.w, oacc[1][3]);
            oacc[2][0] = fmaf(a2, bv.x, oacc[2][0]); oacc[2][1] = fmaf(a2, bv.y, oacc[2][1]);
            oacc[2][2] = fmaf(a2, bv.z, oacc[2][2]); oacc[2][3] = fmaf(a2, bv.w, oacc[2][3]);
            oacc[3][0] = fmaf(a3, bv.x, oacc[3][0]); oacc[3][1] = fmaf(a3, bv.y, oacc[3][1]);
            oacc[3][2] = fmaf(a3, bv.z, oacc[3][2]); oacc[3][3] = fmaf(a3, bv.w, oacc[3][3]);
        }
    }

    // normalize + write out (head-concat layout [B*S, E])
#pragma unroll
    for (int i = 0; i < 4; i++) {
        float inv = 1.f / lreg[i];
        size_t row = rowbase + (size_t)qt*64 + r0 + i;
        float4 ov = make_float4(oacc[i][0]*inv, oacc[i][1]*inv, oacc[i][2]*inv, oacc[i][3]*inv);
        *(float4*)&o[row*E_ + h*64 + c0] = ov;
    }
}

// ---------------------------------------------------------------------------
// Launch
// ---------------------------------------------------------------------------
extern "C" void kernel_launch(void* const* d_in, const int* in_sizes, int n_in,
                              void* d_out, int out_size)
{
    (void)in_sizes; (void)n_in; (void)out_size;
    const float* x   = (const float*)d_in[0];
    const float* Wq  = (const float*)d_in[1];
    const float* Wk  = (const float*)d_in[2];
    const float* Wv  = (const float*)d_in[3];
    const float* Wo  = (const float*)d_in[4];
    const float* bo  = (const float*)d_in[5];
    const float* g1  = (const float*)d_in[6];
    const float* be1 = (const float*)d_in[7];
    const float* g2  = (const float*)d_in[8];
    const float* be2 = (const float*)d_in[9];
    const float* W1  = (const float*)d_in[10];
    const float* bb1 = (const float*)d_in[11];
    const float* W2  = (const float*)d_in[12];
    const float* bb2 = (const float*)d_in[13];
    float* out = (float*)d_out;

    float *lx, *wqkv, *qkv, *o, *x2, *lx2, *ffh;
    cudaGetSymbolAddress((void**)&lx,   g_lx);
    cudaGetSymbolAddress((void**)&wqkv, g_wqkv);
    cudaGetSymbolAddress((void**)&qkv,  g_qkv);
    cudaGetSymbolAddress((void**)&o,    g_o);
    cudaGetSymbolAddress((void**)&x2,   g_x2);
    cudaGetSymbolAddress((void**)&lx2,  g_lx2);
    cudaGetSymbolAddress((void**)&ffh,  g_ffh);

    cudaFuncSetAttribute(attn_kernel, cudaFuncAttributeMaxDynamicSharedMemorySize, ATTN_SMEM);

    // 1. lx = LN1(x)
    ln_kernel<<<M_, 256>>>(x, g1, be1, lx);
    // 2. pack qkv weights -> [E, 3E]
    pack_qkv_kernel<<<(E_*NQKV_)/256, 256>>>(Wq, Wk, Wv, wqkv);
    // 3. qkv = lx @ Wqkv   [8192, 3072]
    sgemm_kernel<0><<<dim3(NQKV_/128, M_/128), 256>>>(lx, wqkv, qkv, nullptr, nullptr, E_, NQKV_);
    // 4. o = causal_attention(q, k, v)   [8192, 1024]
    attn_kernel<<<dim3(S_/64, B_*H_), 256, ATTN_SMEM>>>(qkv, o);
    // 5. x2 = x + o @ Wo + bo
    sgemm_kernel<1><<<dim3(E_/128, M_/128), 256>>>(o, Wo, x2, bo, x, E_, E_);
    // 6. lx2 = LN2(x2)
    ln_kernel<<<M_, 256>>>(x2, g2, be2, lx2);
    // 7. ffh = relu(lx2 @ W1 + b1)   [8192, 4096]
    sgemm_kernel<2><<<dim3(FF_/128, M_/128), 256>>>(lx2, W1, ffh, bb1, nullptr, E_, FF_);
    // 8. out = x2 + ffh @ W2 + b2
    sgemm_kernel<1><<<dim3(E_/128, M_/128), 256>>>(ffh, W2, out, bb2, x2, FF_, E_);
}

// round 3
// speedup vs baseline: 1.3829x; 1.3829x over previous
#include <cuda_runtime.h>
#include <math.h>
#include <stdint.h>

// Problem constants
#define B_    4
#define S_    2048
#define E_    1024
#define H_    16
#define DH_   64
#define M_    (B_*S_)      // 8192 rows
#define FF_   4096
#define NQKV_ 3072

// ---------------------------------------------------------------------------
// Scratch (static __device__ arrays)
// ---------------------------------------------------------------------------
__device__ float g_lx_h [(size_t)M_*E_];
__device__ float g_lx_l [(size_t)M_*E_];
__device__ float g_wqkv_h[(size_t)NQKV_*E_];   // [N=3072, K=1024]
__device__ float g_wqkv_l[(size_t)NQKV_*E_];
__device__ float g_qkv  [(size_t)M_*NQKV_];
__device__ float g_o_h  [(size_t)M_*E_];
__device__ float g_o_l  [(size_t)M_*E_];
__device__ float g_x2   [(size_t)M_*E_];
__device__ float g_lx2_h[(size_t)M_*E_];
__device__ float g_lx2_l[(size_t)M_*E_];
__device__ float g_ffh_h[(size_t)M_*FF_];
__device__ float g_ffh_l[(size_t)M_*FF_];
__device__ float g_WoT_h[(size_t)E_*E_];       // [N=1024, K=1024]
__device__ float g_WoT_l[(size_t)E_*E_];
__device__ float g_W1T_h[(size_t)FF_*E_];      // [N=4096, K=1024]
__device__ float g_W1T_l[(size_t)FF_*E_];
__device__ float g_W2T_h[(size_t)E_*FF_];      // [N=1024, K=4096]
__device__ float g_W2T_l[(size_t)E_*FF_];

// ---------------------------------------------------------------------------
// Helpers
// ---------------------------------------------------------------------------
static __device__ __forceinline__ float tf32_rna(float x) {
    uint32_t u;
    asm("cvt.rna.tf32.f32 %0, %1;" : "=r"(u) : "f"(x));
    return __uint_as_float(u);
}

static __device__ __forceinline__ uint32_t s2u(const void* p) {
    uint32_t a;
    asm("{ .reg .u64 t; cvta.to.shared.u64 t, %1; cvt.u32.u64 %0, t; }" : "=r"(a) : "l"(p));
    return a;
}

#define CP16(dst, src) \
    asm volatile("cp.async.cg.shared.global [%0], [%1], 16;" :: "r"(dst), "l"(src))
#define CP_COMMIT() asm volatile("cp.async.commit_group;")
#define CP_WAIT2()  asm volatile("cp.async.wait_group 2;")
#define CP_WAIT1()  asm volatile("cp.async.wait_group 1;")
#define CP_WAIT0()  asm volatile("cp.async.wait_group 0;")

#define LDSM4(r0, r1, r2, r3, addr) \
    asm volatile("ldmatrix.sync.aligned.m8n8.x4.shared.b16 {%0,%1,%2,%3}, [%4];" \
                 : "=r"(r0), "=r"(r1), "=r"(r2), "=r"(r3) : "r"(addr))

#define MMA_TF32(d0, d1, d2, d3, a0, a1, a2, a3, b0, b1) \
    asm volatile("mma.sync.aligned.m16n8k8.row.col.f32.tf32.tf32.f32 " \
                 "{%0,%1,%2,%3}, {%4,%5,%6,%7}, {%8,%9}, {%0,%1,%2,%3};" \
                 : "+f"(d0), "+f"(d1), "+f"(d2), "+f"(d3) \
                 : "r"(a0), "r"(a1), "r"(a2), "r"(a3), "r"(b0), "r"(b1))

// ---------------------------------------------------------------------------
// LayerNorm (fused hi/lo split output)
// ---------------------------------------------------------------------------
__global__ void ln_kernel(const float* __restrict__ x, const float* __restrict__ g,
                          const float* __restrict__ b,
                          float* __restrict__ oh, float* __restrict__ ol)
{
    int row = blockIdx.x;
    int t = threadIdx.x;
    const float* xr = x + (size_t)row * E_;
    float v[4];
    float s = 0.f, s2 = 0.f;
#pragma unroll
    for (int i = 0; i < 4; i++) {
        v[i] = xr[t + 256*i];
        s += v[i];
        s2 += v[i]*v[i];
    }
#pragma unroll
    for (int m = 16; m; m >>= 1) {
        s  += __shfl_xor_sync(0xffffffffu, s,  m);
        s2 += __shfl_xor_sync(0xffffffffu, s2, m);
    }
    __shared__ float sh[2][8];
    if ((t & 31) == 0) { sh[0][t>>5] = s; sh[1][t>>5] = s2; }
    __syncthreads();
    s = 0.f; s2 = 0.f;
#pragma unroll
    for (int w = 0; w < 8; w++) { s += sh[0][w]; s2 += sh[1][w]; }
    float mu  = s * (1.f/E_);
    float var = s2 * (1.f/E_) - mu*mu;
    float r = rsqrtf(var + 1e-5f);
    size_t rb = (size_t)row * E_;
#pragma unroll
    for (int i = 0; i < 4; i++) {
        int c = t + 256*i;
        float y = (v[i]-mu)*r*g[c] + b[c];
        float h = tf32_rna(y);
        oh[rb + c] = h;
        ol[rb + c] = tf32_rna(y - h);
    }
}

// ---------------------------------------------------------------------------
// Pack Wq/Wk/Wv into [N=3072, K=1024] hi/lo (K-major, head-concat columns)
// ---------------------------------------------------------------------------
__global__ void pack_qkv_kernel(const float* __restrict__ Wq, const float* __restrict__ Wk,
                                const float* __restrict__ Wv,
                                float* __restrict__ oh, float* __restrict__ ol)
{
    int idx = blockIdx.x*256 + threadIdx.x;
    int n = idx / E_;
    int e = idx - n*E_;
    const float* W = (n < 1024) ? Wq : (n < 2048 ? Wk : Wv);
    int hd = n & 1023;
    float v = W[(size_t)(hd >> 6)*(E_*DH_) + (size_t)e*DH_ + (hd & 63)];
    float h = tf32_rna(v);
    oh[idx] = h;
    ol[idx] = tf32_rna(v - h);
}

// ---------------------------------------------------------------------------
// Transpose + split: in [K,N] row-major -> out_hi/lo [N,K] row-major
// ---------------------------------------------------------------------------
__global__ void tsplit_kernel(const float* __restrict__ in, float* __restrict__ oh,
                              float* __restrict__ ol, int K, int N)
{
    __shared__ float t[32][33];
    int k0 = blockIdx.y*32, n0 = blockIdx.x*32;
    int tx = threadIdx.x, ty = threadIdx.y;
#pragma unroll
    for (int r = ty; r < 32; r += 8)
        t[r][tx] = in[(size_t)(k0+r)*N + n0+tx];
    __syncthreads();
#pragma unroll
    for (int r = ty; r < 32; r += 8) {
        float v = t[tx][r];
        float h = tf32_rna(v);
        size_t o = (size_t)(n0+r)*K + k0+tx;
        oh[o] = h;
        ol[o] = tf32_rna(v - h);
    }
}

// ---------------------------------------------------------------------------
// Split-TF32 GEMM via mma.sync (legacy tensor path, base sm_100 compatible).
// C[M,N] = (Ah+Al)[M,K] @ (Bh+Bl)^T,  B given [N,K] row-major.
// CTA 128x128, 8 warps (2m x 4n), warp tile 64x32, K-chunk 32, 3-stage
// cp.async pipeline, XOR-swizzled smem for conflict-free ldmatrix.
// EPI: 0 = plain, 1 = +bias[col]+res, 2 = relu(+bias) split to C(hi)/C2(lo)
// ---------------------------------------------------------------------------
#define STAGE_BYTES 65536
#define GSMEM (3*STAGE_BYTES)

template<int EPI>
__global__ void __launch_bounds__(256, 1) gemm_tf32(
    const float* __restrict__ Ah, const float* __restrict__ Al,
    const float* __restrict__ Bh, const float* __restrict__ Bl,
    float* __restrict__ C, float* __restrict__ C2,
    const float* __restrict__ bias, const float* __restrict__ res,
    int K, int N)
{
    extern __shared__ char smc[];
    uint32_t sb = s2u(smc);
    int tid = threadIdx.x;
    int wid = tid >> 5, lane = tid & 31;
    int wm = wid >> 2, wn = wid & 3;          // 2 x 4 warp grid
    int mblk = blockIdx.y * 128, nblk = blockIdx.x * 128;

    // ldmatrix per-lane row/chunk params
    int sub = lane >> 3, L = lane & 7;
    int rA = ((sub & 1) << 3) + L, cAadd = sub >> 1;   // A: m16k8 frag
    int rB = ((sub >> 1) << 3) + L, cBadd = sub & 1;   // B: two k8n8 frags

    uint32_t sAh[3], sAl[3], sBh[3], sBl[3];
#pragma unroll
    for (int b = 0; b < 3; b++) {
        uint32_t base = sb + b * STAGE_BYTES;
        sAh[b] = base;          sAl[b] = base + 16384;
        sBh[b] = base + 32768;  sBl[b] = base + 49152;
    }

    float acc[4][4][4];
#pragma unroll
    for (int mt = 0; mt < 4; mt++)
#pragma unroll
        for (int nt = 0; nt < 4; nt++)
#pragma unroll
            for (int q = 0; q < 4; q++) acc[mt][nt][q] = 0.f;

    auto load_stage = [&](int s, int b) {
        int k0 = s << 5;
        for (int idx = tid; idx < 1024; idx += 256) {   // 128 rows x 8 chunks
            int r = idx >> 3, q = idx & 7;
            uint32_t off = (uint32_t)(r*128 + ((q ^ (r & 7)) << 4));
            size_t gA = (size_t)(mblk + r) * K + k0 + q*4;
            size_t gB = (size_t)(nblk + r) * K + k0 + q*4;
            CP16(sAh[b] + off, Ah + gA);
            CP16(sAl[b] + off, Al + gA);
            CP16(sBh[b] + off, Bh + gB);
            CP16(sBl[b] + off, Bl + gB);
        }
        CP_COMMIT();
    };

    const int NS = K >> 5;
    load_stage(0, 0);
    load_stage(1, 1);
    load_stage(2, 2);

    int buf = 0;
    for (int i = 0; i < NS; i++) {
        if (i + 3 <= NS - 1)      CP_WAIT2();
        else if (i + 2 <= NS - 1) CP_WAIT1();
        else                      CP_WAIT0();
        __syncthreads();

#pragma unroll
        for (int ks = 0; ks < 4; ks++) {
            int c0 = 2*ks;
            uint32_t Af[4][4], Bhf[2][4], Blf[2][4];
            // A-hi fragments (4 x m16)
#pragma unroll
            for (int mt = 0; mt < 4; mt++) {
                int row = wm*64 + mt*16 + rA;
                int ch = c0 + cAadd;
                uint32_t a = sAh[buf] + row*128 + ((ch ^ (row & 7)) << 4);
                LDSM4(Af[mt][0], Af[mt][1], Af[mt][2], Af[mt][3], a);
            }
            // B-hi / B-lo fragments (2 x pair-of-n8)
#pragma unroll
            for (int np = 0; np < 2; np++) {
                int row = wn*32 + np*16 + rB;
                int ch = c0 + cBadd;
                uint32_t sw = (uint32_t)(row*128 + ((ch ^ (row & 7)) << 4));
                LDSM4(Bhf[np][0], Bhf[np][1], Bhf[np][2], Bhf[np][3], sBh[buf] + sw);
                LDSM4(Blf[np][0], Blf[np][1], Blf[np][2], Blf[np][3], sBl[buf] + sw);
            }
            // Ah * Bh
#pragma unroll
            for (int mt = 0; mt < 4; mt++)
#pragma unroll
                for (int nt = 0; nt < 4; nt++)
                    MMA_TF32(acc[mt][nt][0], acc[mt][nt][1], acc[mt][nt][2], acc[mt][nt][3],
                             Af[mt][0], Af[mt][1], Af[mt][2], Af[mt][3],
                             Bhf[nt>>1][(nt&1)*2], Bhf[nt>>1][(nt&1)*2+1]);
            // Ah * Bl
#pragma unroll
            for (int mt = 0; mt < 4; mt++)
#pragma unroll
                for (int nt = 0; nt < 4; nt++)
                    MMA_TF32(acc[mt][nt][0], acc[mt][nt][1], acc[mt][nt][2], acc[mt][nt][3],
                             Af[mt][0], Af[mt][1], Af[mt][2], Af[mt][3],
                             Blf[nt>>1][(nt&1)*2], Blf[nt>>1][(nt&1)*2+1]);
            // A-lo fragments (reuse Af), then Al * Bh
#pragma unroll
            for (int mt = 0; mt < 4; mt++) {
                int row = wm*64 + mt*16 + rA;
                int ch = c0 + cAadd;
                uint32_t a = sAl[buf] + row*128 + ((ch ^ (row & 7)) << 4);
                LDSM4(Af[mt][0], Af[mt][1], Af[mt][2], Af[mt][3], a);
            }
#pragma unroll
            for (int mt = 0; mt < 4; mt++)
#pragma unroll
                for (int nt = 0; nt < 4; nt++)
                    MMA_TF32(acc[mt][nt][0], acc[mt][nt][1], acc[mt][nt][2], acc[mt][nt][3],
                             Af[mt][0], Af[mt][1], Af[mt][2], Af[mt][3],
                             Bhf[nt>>1][(nt&1)*2], Bhf[nt>>1][(nt&1)*2+1]);
        }

        __syncthreads();
        if (i + 3 < NS) load_stage(i + 3, buf);
        buf = (buf == 2) ? 0 : buf + 1;
    }

    // Epilogue
    int g = lane >> 2, tg = lane & 3;
#pragma unroll
    for (int mt = 0; mt < 4; mt++) {
#pragma unroll
        for (int nt = 0; nt < 4; nt++) {
            int row0 = mblk + wm*64 + mt*16 + g;
            int col  = nblk + wn*32 + nt*8 + 2*tg;
#pragma unroll
            for (int half = 0; half < 2; half++) {
                int row = row0 + half*8;
                float v0 = acc[mt][nt][half*2+0];
                float v1 = acc[mt][nt][half*2+1];
                size_t gi = (size_t)row * N + col;
                if (EPI >= 1) { v0 += bias[col]; v1 += bias[col+1]; }
                if (EPI == 1) {
                    float2 rv = *(const float2*)&res[gi];
                    v0 += rv.x; v1 += rv.y;
                    float2 o; o.x = v0; o.y = v1;
                    *(float2*)&C[gi] = o;
                } else if (EPI == 2) {
                    v0 = fmaxf(v0, 0.f); v1 = fmaxf(v1, 0.f);
                    float h0 = tf32_rna(v0), h1 = tf32_rna(v1);
                    float2 hv; hv.x = h0; hv.y = h1;
                    float2 lv; lv.x = tf32_rna(v0 - h0); lv.y = tf32_rna(v1 - h1);
                    *(float2*)&C [gi] = hv;
                    *(float2*)&C2[gi] = lv;
                } else {
                    float2 o; o.x = v0; o.y = v1;
                    *(float2*)&C[gi] = o;
                }
            }
        }
    }
}

// ---------------------------------------------------------------------------
// Flash attention (fp32 FFMA; epilogue writes hi/lo split)
// ---------------------------------------------------------------------------
#define APAD 68
#define ATTN_SMEM ((64*64 + 3*64*APAD) * 4)

__global__ void __launch_bounds__(256, 1) attn_kernel(const float* __restrict__ qkv,
                                                      float* __restrict__ oh,
                                                      float* __restrict__ ol)
{
    extern __shared__ float smf[];
    float* qs  = smf;
    float* ksT = qs + 64*64;
    float* vs  = ksT + 64*APAD;
    float* ps  = vs + 64*APAD;

    int tid = threadIdx.x;
    int qt = blockIdx.x;
    int b = blockIdx.y >> 4, h = blockIdx.y & 15;
    int ty = tid >> 4, tx = tid & 15;
    int r0 = ty*4, c0 = tx*4;
    size_t rowbase = (size_t)b * S_;
    int qcol = h*64, kcol = 1024 + h*64, vcol = 2048 + h*64;

    for (int jj = ty; jj < 64; jj += 16) {
        float4 vq = *(const float4*)&qkv[(rowbase + (size_t)qt*64 + jj)*NQKV_ + qcol + tx*4];
        *(float4*)&qs[jj*64 + tx*4] = vq;
    }

    float mreg[4], lreg[4], oacc[4][4];
#pragma unroll
    for (int i = 0; i < 4; i++) {
        mreg[i] = -1e30f; lreg[i] = 0.f;
#pragma unroll
        for (int j = 0; j < 4; j++) oacc[i][j] = 0.f;
    }

    for (int t = 0; t <= qt; t++) {
        __syncthreads();
        for (int jj = ty; jj < 64; jj += 16) {
            size_t tok = (rowbase + (size_t)t*64 + jj) * NQKV_;
            float4 kv = *(const float4*)&qkv[tok + kcol + tx*4];
            ksT[(tx*4+0)*APAD + jj] = kv.x;
            ksT[(tx*4+1)*APAD + jj] = kv.y;
            ksT[(tx*4+2)*APAD + jj] = kv.z;
            ksT[(tx*4+3)*APAD + jj] = kv.w;
            float4 vv = *(const float4*)&qkv[tok + vcol + tx*4];
            *(float4*)&vs[jj*APAD + tx*4] = vv;
        }
        __syncthreads();

        float s[4][4];
#pragma unroll
        for (int i = 0; i < 4; i++)
#pragma unroll
            for (int j = 0; j < 4; j++) s[i][j] = 0.f;
        for (int d = 0; d < 64; d++) {
            float a0 = qs[(r0+0)*64 + d];
            float a1 = qs[(r0+1)*64 + d];
            float a2 = qs[(r0+2)*64 + d];
            float a3 = qs[(r0+3)*64 + d];
            float4 bv = *(const float4*)&ksT[d*APAD + c0];
            s[0][0] = fmaf(a0, bv.x, s[0][0]); s[0][1] = fmaf(a0, bv.y, s[0][1]);
            s[0][2] = fmaf(a0, bv.z, s[0][2]); s[0][3] = fmaf(a0, bv.w, s[0][3]);
            s[1][0] = fmaf(a1, bv.x, s[1][0]); s[1][1] = fmaf(a1, bv.y, s[1][1]);
            s[1][2] = fmaf(a1, bv.z, s[1][2]); s[1][3] = fmaf(a1, bv.w, s[1][3]);
            s[2][0] = fmaf(a2, bv.x, s[2][0]); s[2][1] = fmaf(a2, bv.y, s[2][1]);
            s[2][2] = fmaf(a2, bv.z, s[2][2]); s[2][3] = fmaf(a2, bv.w, s[2][3]);
            s[3][0] = fmaf(a3, bv.x, s[3][0]); s[3][1] = fmaf(a3, bv.y, s[3][1]);
            s[3][2] = fmaf(a3, bv.z, s[3][2]); s[3][3] = fmaf(a3, bv.w, s[3][3]);
        }

#pragma unroll
        for (int i = 0; i < 4; i++)
#pragma unroll
            for (int j = 0; j < 4; j++) {
                float sv = s[i][j] * 0.125f;
                if (t == qt && (c0+j) > (r0+i)) sv = -1e30f;
                s[i][j] = sv;
            }

#pragma unroll
        for (int i = 0; i < 4; i++) {
            float mm = fmaxf(fmaxf(s[i][0], s[i][1]), fmaxf(s[i][2], s[i][3]));
#pragma unroll
            for (int msk = 8; msk; msk >>= 1)
                mm = fmaxf(mm, __shfl_xor_sync(0xffffffffu, mm, msk));
            float mnew = fmaxf(mreg[i], mm);
            float alpha = expf(mreg[i] - mnew);
            float ls = 0.f;
#pragma unroll
            for (int j = 0; j < 4; j++) {
                float p = expf(s[i][j] - mnew);
                s[i][j] = p;
                ls += p;
            }
#pragma unroll
            for (int msk = 8; msk; msk >>= 1)
                ls += __shfl_xor_sync(0xffffffffu, ls, msk);
            lreg[i] = lreg[i]*alpha + ls;
            mreg[i] = mnew;
#pragma unroll
            for (int j = 0; j < 4; j++) oacc[i][j] *= alpha;
        }

#pragma unroll
        for (int i = 0; i < 4; i++) {
            float4 pv = make_float4(s[i][0], s[i][1], s[i][2], s[i][3]);
            *(float4*)&ps[(r0+i)*APAD + c0] = pv;
        }
        __syncthreads();

        for (int kkk = 0; kkk < 64; kkk++) {
            float a0 = ps[(r0+0)*APAD + kkk];
            float a1 = ps[(r0+1)*APAD + kkk];
            float a2 = ps[(r0+2)*APAD + kkk];
            float a3 = ps[(r0+3)*APAD + kkk];
            float4 bv = *(const float4*)&vs[kkk*APAD + c0];
            oacc[0][0] = fmaf(a0, bv.x, oacc[0][0]); oacc[0][1] = fmaf(a0, bv.y, oacc[0][1]);
            oacc[0][2] = fmaf(a0, bv.z, oacc[0][2]); oacc[0][3] = fmaf(a0, bv.w, oacc[0][3]);
            oacc[1][0] = fmaf(a1, bv.x, oacc[1][0]); oacc[1][1] = fmaf(a1, bv.y, oacc[1][1]);
            oacc[1][2] = fmaf(a1, bv.z, oacc[1][2]); oacc[1][3] = fmaf(a1, bv.w, oacc[1][3]);
            oacc[2][0] = fmaf(a2, bv.x, oacc[2][0]); oacc[2][1] = fmaf(a2, bv.y, oacc[2][1]);
            oacc[2][2] = fmaf(a2, bv.z, oacc[2][2]); oacc[2][3] = fmaf(a2, bv.w, oacc[2][3]);
            oacc[3][0] = fmaf(a3, bv.x, oacc[3][0]); oacc[3][1] = fmaf(a3, bv.y, oacc[3][1]);
            oacc[3][2] = fmaf(a3, bv.z, oacc[3][2]); oacc[3][3] = fmaf(a3, bv.w, oacc[3][3]);
        }
    }

#pragma unroll
    for (int i = 0; i < 4; i++) {
        float inv = 1.f / lreg[i];
        size_t row = rowbase + (size_t)qt*64 + r0 + i;
        float4 ov = make_float4(oacc[i][0]*inv, oacc[i][1]*inv, oacc[i][2]*inv, oacc[i][3]*inv);
        float4 hv, lv;
        hv.x = tf32_rna(ov.x); lv.x = tf32_rna(ov.x - hv.x);
        hv.y = tf32_rna(ov.y); lv.y = tf32_rna(ov.y - hv.y);
        hv.z = tf32_rna(ov.z); lv.z = tf32_rna(ov.z - hv.z);
        hv.w = tf32_rna(ov.w); lv.w = tf32_rna(ov.w - hv.w);
        *(float4*)&oh[row*E_ + h*64 + c0] = hv;
        *(float4*)&ol[row*E_ + h*64 + c0] = lv;
    }
}

// ---------------------------------------------------------------------------
// Launch
// ---------------------------------------------------------------------------
extern "C" void kernel_launch(void* const* d_in, const int* in_sizes, int n_in,
                              void* d_out, int out_size)
{
    (void)in_sizes; (void)n_in; (void)out_size;
    const float* x   = (const float*)d_in[0];
    const float* Wq  = (const float*)d_in[1];
    const float* Wk  = (const float*)d_in[2];
    const float* Wv  = (const float*)d_in[3];
    const float* Wo  = (const float*)d_in[4];
    const float* bo  = (const float*)d_in[5];
    const float* g1  = (const float*)d_in[6];
    const float* be1 = (const float*)d_in[7];
    const float* g2  = (const float*)d_in[8];
    const float* be2 = (const float*)d_in[9];
    const float* W1  = (const float*)d_in[10];
    const float* bb1 = (const float*)d_in[11];
    const float* W2  = (const float*)d_in[12];
    const float* bb2 = (const float*)d_in[13];
    float* out = (float*)d_out;

    float *lx_h, *lx_l, *wqkv_h, *wqkv_l, *qkv, *o_h, *o_l, *x2, *lx2_h, *lx2_l;
    float *ffh_h, *ffh_l, *WoT_h, *WoT_l, *W1T_h, *W1T_l, *W2T_h, *W2T_l;
    cudaGetSymbolAddress((void**)&lx_h,   g_lx_h);
    cudaGetSymbolAddress((void**)&lx_l,   g_lx_l);
    cudaGetSymbolAddress((void**)&wqkv_h, g_wqkv_h);
    cudaGetSymbolAddress((void**)&wqkv_l, g_wqkv_l);
    cudaGetSymbolAddress((void**)&qkv,    g_qkv);
    cudaGetSymbolAddress((void**)&o_h,    g_o_h);
    cudaGetSymbolAddress((void**)&o_l,    g_o_l);
    cudaGetSymbolAddress((void**)&x2,     g_x2);
    cudaGetSymbolAddress((void**)&lx2_h,  g_lx2_h);
    cudaGetSymbolAddress((void**)&lx2_l,  g_lx2_l);
    cudaGetSymbolAddress((void**)&ffh_h,  g_ffh_h);
    cudaGetSymbolAddress((void**)&ffh_l,  g_ffh_l);
    cudaGetSymbolAddress((void**)&WoT_h,  g_WoT_h);
    cudaGetSymbolAddress((void**)&WoT_l,  g_WoT_l);
    cudaGetSymbolAddress((void**)&W1T_h,  g_W1T_h);
    cudaGetSymbolAddress((void**)&W1T_l,  g_W1T_l);
    cudaGetSymbolAddress((void**)&W2T_h,  g_W2T_h);
    cudaGetSymbolAddress((void**)&W2T_l,  g_W2T_l);

    cudaFuncSetAttribute(attn_kernel, cudaFuncAttributeMaxDynamicSharedMemorySize, ATTN_SMEM);
    cudaFuncSetAttribute(gemm_tf32<0>, cudaFuncAttributeMaxDynamicSharedMemorySize, GSMEM);
    cudaFuncSetAttribute(gemm_tf32<1>, cudaFuncAttributeMaxDynamicSharedMemorySize, GSMEM);
    cudaFuncSetAttribute(gemm_tf32<2>, cudaFuncAttributeMaxDynamicSharedMemorySize, GSMEM);

    // 1. LN1 -> lx hi/lo
    ln_kernel<<<M_, 256>>>(x, g1, be1, lx_h, lx_l);
    // 2. weight prep
    pack_qkv_kernel<<<(NQKV_*E_)/256, 256>>>(Wq, Wk, Wv, wqkv_h, wqkv_l);
    tsplit_kernel<<<dim3(E_/32,  E_/32),  dim3(32,8)>>>(Wo, WoT_h, WoT_l, E_,  E_);
    tsplit_kernel<<<dim3(FF_/32, E_/32),  dim3(32,8)>>>(W1, W1T_h, W1T_l, E_,  FF_);
    tsplit_kernel<<<dim3(E_/32,  FF_/32), dim3(32,8)>>>(W2, W2T_h, W2T_l, FF_, E_);
    // 3. qkv = lx @ Wqkv
    gemm_tf32<0><<<dim3(NQKV_/128, M_/128), 256, GSMEM>>>(
        lx_h, lx_l, wqkv_h, wqkv_l, qkv, nullptr, nullptr, nullptr, E_, NQKV_);
    // 4. attention -> o hi/lo
    attn_kernel<<<dim3(S_/64, B_*H_), 256, ATTN_SMEM>>>(qkv, o_h, o_l);
    // 5. x2 = x + o @ Wo + bo
    gemm_tf32<1><<<dim3(E_/128, M_/128), 256, GSMEM>>>(
        o_h, o_l, WoT_h, WoT_l, x2, nullptr, bo, x, E_, E_);
    // 6. LN2 -> lx2 hi/lo
    ln_kernel<<<M_, 256>>>(x2, g2, be2, lx2_h, lx2_l);
    // 7. ffh = relu(lx2 @ W1 + b1) -> hi/lo
    gemm_tf32<2><<<dim3(FF_/128, M_/128), 256, GSMEM>>>(
        lx2_h, lx2_l, W1T_h, W1T_l, ffh_h, ffh_l, bb1, nullptr, E_, FF_);
    // 8. out = x2 + ffh @ W2 + b2
    gemm_tf32<1><<<dim3(E_/128, M_/128), 256, GSMEM>>>(
        ffh_h, ffh_l, W2T_h, W2T_l, out, nullptr, bb2, x2, FF_, E_);
}

// round 5
// speedup vs baseline: 1.7002x; 1.2294x over previous
#include <cuda_runtime.h>
#include <math.h>
#include <stdint.h>

// Problem constants
#define B_    4
#define S_    2048
#define E_    1024
#define H_    16
#define DH_   64
#define M_    (B_*S_)      // 8192 rows
#define FF_   4096
#define NQKV_ 3072

// ---------------------------------------------------------------------------
// Scratch (static __device__ arrays)
// ---------------------------------------------------------------------------
__device__ float g_lx_h [(size_t)M_*E_];
__device__ float g_lx_l [(size_t)M_*E_];
__device__ float g_wqkv_h[(size_t)NQKV_*E_];   // [N=3072, K=1024]
__device__ float g_wqkv_l[(size_t)NQKV_*E_];
__device__ float g_qkv  [(size_t)M_*NQKV_];
__device__ float g_o_h  [(size_t)M_*E_];
__device__ float g_o_l  [(size_t)M_*E_];
__device__ float g_x2   [(size_t)M_*E_];
__device__ float g_lx2_h[(size_t)M_*E_];
__device__ float g_lx2_l[(size_t)M_*E_];
__device__ float g_ffh_h[(size_t)M_*FF_];
__device__ float g_ffh_l[(size_t)M_*FF_];
__device__ float g_WoT_h[(size_t)E_*E_];       // [N=1024, K=1024]
__device__ float g_WoT_l[(size_t)E_*E_];
__device__ float g_W1T_h[(size_t)FF_*E_];      // [N=4096, K=1024]
__device__ float g_W1T_l[(size_t)FF_*E_];
__device__ float g_W2T_h[(size_t)E_*FF_];      // [N=1024, K=4096]
__device__ float g_W2T_l[(size_t)E_*FF_];

// ---------------------------------------------------------------------------
// Helpers
// ---------------------------------------------------------------------------
static __device__ __forceinline__ float tf32_rna(float x) {
    uint32_t u;
    asm("cvt.rna.tf32.f32 %0, %1;" : "=r"(u) : "f"(x));
    return __uint_as_float(u);
}

static __device__ __forceinline__ uint32_t s2u(const void* p) {
    uint32_t a;
    asm("{ .reg .u64 t; cvta.to.shared.u64 t, %1; cvt.u32.u64 %0, t; }" : "=r"(a) : "l"(p));
    return a;
}

#define CP16(dst, src) \
    asm volatile("cp.async.cg.shared.global [%0], [%1], 16;" :: "r"(dst), "l"(src))
#define CP_COMMIT() asm volatile("cp.async.commit_group;")
#define CP_WAIT2()  asm volatile("cp.async.wait_group 2;")
#define CP_WAIT1()  asm volatile("cp.async.wait_group 1;")
#define CP_WAIT0()  asm volatile("cp.async.wait_group 0;")

#define LDSM4(r0, r1, r2, r3, addr) \
    asm volatile("ldmatrix.sync.aligned.m8n8.x4.shared.b16 {%0,%1,%2,%3}, [%4];" \
                 : "=r"(r0), "=r"(r1), "=r"(r2), "=r"(r3) : "r"(addr))

#define MMA_TF32(d0, d1, d2, d3, a0, a1, a2, a3, b0, b1) \
    asm volatile("mma.sync.aligned.m16n8k8.row.col.f32.tf32.tf32.f32 " \
                 "{%0,%1,%2,%3}, {%4,%5,%6,%7}, {%8,%9}, {%0,%1,%2,%3};" \
                 : "+f"(d0), "+f"(d1), "+f"(d2), "+f"(d3) \
                 : "r"(a0), "r"(a1), "r"(a2), "r"(a3), "r"(b0), "r"(b1))

// ---------------------------------------------------------------------------
// LayerNorm (fused hi/lo split output)
// ---------------------------------------------------------------------------
__global__ void ln_kernel(const float* __restrict__ x, const float* __restrict__ g,
                          const float* __restrict__ b,
                          float* __restrict__ oh, float* __restrict__ ol)
{
    int row = blockIdx.x;
    int t = threadIdx.x;
    const float* xr = x + (size_t)row * E_;
    float v[4];
    float s = 0.f, s2 = 0.f;
#pragma unroll
    for (int i = 0; i < 4; i++) {
        v[i] = xr[t + 256*i];
        s += v[i];
        s2 += v[i]*v[i];
    }
#pragma unroll
    for (int m = 16; m; m >>= 1) {
        s  += __shfl_xor_sync(0xffffffffu, s,  m);
        s2 += __shfl_xor_sync(0xffffffffu, s2, m);
    }
    __shared__ float sh[2][8];
    if ((t & 31) == 0) { sh[0][t>>5] = s; sh[1][t>>5] = s2; }
    __syncthreads();
    s = 0.f; s2 = 0.f;
#pragma unroll
    for (int w = 0; w < 8; w++) { s += sh[0][w]; s2 += sh[1][w]; }
    float mu  = s * (1.f/E_);
    float var = s2 * (1.f/E_) - mu*mu;
    float r = rsqrtf(var + 1e-5f);
    size_t rb = (size_t)row * E_;
#pragma unroll
    for (int i = 0; i < 4; i++) {
        int c = t + 256*i;
        float y = (v[i]-mu)*r*g[c] + b[c];
        float h = tf32_rna(y);
        oh[rb + c] = h;
        ol[rb + c] = tf32_rna(y - h);
    }
}

// ---------------------------------------------------------------------------
// Pack Wq/Wk/Wv into [N=3072, K=1024] hi/lo (K-major, head-concat columns)
// ---------------------------------------------------------------------------
__global__ void pack_qkv_kernel(const float* __restrict__ Wq, const float* __restrict__ Wk,
                                const float* __restrict__ Wv,
                                float* __restrict__ oh, float* __restrict__ ol)
{
    int idx = blockIdx.x*256 + threadIdx.x;
    int n = idx / E_;
    int e = idx - n*E_;
    const float* W = (n < 1024) ? Wq : (n < 2048 ? Wk : Wv);
    int hd = n & 1023;
    float v = W[(size_t)(hd >> 6)*(E_*DH_) + (size_t)e*DH_ + (hd & 63)];
    float h = tf32_rna(v);
    oh[idx] = h;
    ol[idx] = tf32_rna(v - h);
}

// ---------------------------------------------------------------------------
// Transpose + split: in [K,N] row-major -> out_hi/lo [N,K] row-major
// ---------------------------------------------------------------------------
__global__ void tsplit_kernel(const float* __restrict__ in, float* __restrict__ oh,
                              float* __restrict__ ol, int K, int N)
{
    __shared__ float t[32][33];
    int k0 = blockIdx.y*32, n0 = blockIdx.x*32;
    int tx = threadIdx.x, ty = threadIdx.y;
#pragma unroll
    for (int r = ty; r < 32; r += 8)
        t[r][tx] = in[(size_t)(k0+r)*N + n0+tx];
    __syncthreads();
#pragma unroll
    for (int r = ty; r < 32; r += 8) {
        float v = t[tx][r];
        float h = tf32_rna(v);
        size_t o = (size_t)(n0+r)*K + k0+tx;
        oh[o] = h;
        ol[o] = tf32_rna(v - h);
    }
}

// ---------------------------------------------------------------------------
// Split-TF32 GEMM via mma.sync (validated round 3).
// ---------------------------------------------------------------------------
#define STAGE_BYTES 65536
#define GSMEM (3*STAGE_BYTES)

template<int EPI>
__global__ void __launch_bounds__(256, 1) gemm_tf32(
    const float* __restrict__ Ah, const float* __restrict__ Al,
    const float* __restrict__ Bh, const float* __restrict__ Bl,
    float* __restrict__ C, float* __restrict__ C2,
    const float* __restrict__ bias, const float* __restrict__ res,
    int K, int N)
{
    extern __shared__ char smc[];
    uint32_t sb = s2u(smc);
    int tid = threadIdx.x;
    int wid = tid >> 5, lane = tid & 31;
    int wm = wid >> 2, wn = wid & 3;
    int mblk = blockIdx.y * 128, nblk = blockIdx.x * 128;

    int sub = lane >> 3, L = lane & 7;
    int rA = ((sub & 1) << 3) + L, cAadd = sub >> 1;
    int rB = ((sub >> 1) << 3) + L, cBadd = sub & 1;

    uint32_t sAh[3], sAl[3], sBh[3], sBl[3];
#pragma unroll
    for (int b = 0; b < 3; b++) {
        uint32_t base = sb + b * STAGE_BYTES;
        sAh[b] = base;          sAl[b] = base + 16384;
        sBh[b] = base + 32768;  sBl[b] = base + 49152;
    }

    float acc[4][4][4];
#pragma unroll
    for (int mt = 0; mt < 4; mt++)
#pragma unroll
        for (int nt = 0; nt < 4; nt++)
#pragma unroll
            for (int q = 0; q < 4; q++) acc[mt][nt][q] = 0.f;

    auto load_stage = [&](int s, int b) {
        int k0 = s << 5;
        for (int idx = tid; idx < 1024; idx += 256) {
            int r = idx >> 3, q = idx & 7;
            uint32_t off = (uint32_t)(r*128 + ((q ^ (r & 7)) << 4));
            size_t gA = (size_t)(mblk + r) * K + k0 + q*4;
            size_t gB = (size_t)(nblk + r) * K + k0 + q*4;
            CP16(sAh[b] + off, Ah + gA);
            CP16(sAl[b] + off, Al + gA);
            CP16(sBh[b] + off, Bh + gB);
            CP16(sBl[b] + off, Bl + gB);
        }
        CP_COMMIT();
    };

    const int NS = K >> 5;
    load_stage(0, 0);
    load_stage(1, 1);
    load_stage(2, 2);

    int buf = 0;
    for (int i = 0; i < NS; i++) {
        if (i + 3 <= NS - 1)      CP_WAIT2();
        else if (i + 2 <= NS - 1) CP_WAIT1();
        else                      CP_WAIT0();
        __syncthreads();

#pragma unroll
        for (int ks = 0; ks < 4; ks++) {
            int c0 = 2*ks;
            uint32_t Af[4][4], Bhf[2][4], Blf[2][4];
#pragma unroll
            for (int mt = 0; mt < 4; mt++) {
                int row = wm*64 + mt*16 + rA;
                int ch = c0 + cAadd;
                uint32_t a = sAh[buf] + row*128 + ((ch ^ (row & 7)) << 4);
                LDSM4(Af[mt][0], Af[mt][1], Af[mt][2], Af[mt][3], a);
            }
#pragma unroll
            for (int np = 0; np < 2; np++) {
                int row = wn*32 + np*16 + rB;
                int ch = c0 + cBadd;
                uint32_t sw = (uint32_t)(row*128 + ((ch ^ (row & 7)) << 4));
                LDSM4(Bhf[np][0], Bhf[np][1], Bhf[np][2], Bhf[np][3], sBh[buf] + sw);
                LDSM4(Blf[np][0], Blf[np][1], Blf[np][2], Blf[np][3], sBl[buf] + sw);
            }
#pragma unroll
            for (int mt = 0; mt < 4; mt++)
#pragma unroll
                for (int nt = 0; nt < 4; nt++)
                    MMA_TF32(acc[mt][nt][0], acc[mt][nt][1], acc[mt][nt][2], acc[mt][nt][3],
                             Af[mt][0], Af[mt][1], Af[mt][2], Af[mt][3],
                             Bhf[nt>>1][(nt&1)*2], Bhf[nt>>1][(nt&1)*2+1]);
#pragma unroll
            for (int mt = 0; mt < 4; mt++)
#pragma unroll
                for (int nt = 0; nt < 4; nt++)
                    MMA_TF32(acc[mt][nt][0], acc[mt][nt][1], acc[mt][nt][2], acc[mt][nt][3],
                             Af[mt][0], Af[mt][1], Af[mt][2], Af[mt][3],
                             Blf[nt>>1][(nt&1)*2], Blf[nt>>1][(nt&1)*2+1]);
#pragma unroll
            for (int mt = 0; mt < 4; mt++) {
                int row = wm*64 + mt*16 + rA;
                int ch = c0 + cAadd;
                uint32_t a = sAl[buf] + row*128 + ((ch ^ (row & 7)) << 4);
                LDSM4(Af[mt][0], Af[mt][1], Af[mt][2], Af[mt][3], a);
            }
#pragma unroll
            for (int mt = 0; mt < 4; mt++)
#pragma unroll
                for (int nt = 0; nt < 4; nt++)
                    MMA_TF32(acc[mt][nt][0], acc[mt][nt][1], acc[mt][nt][2], acc[mt][nt][3],
                             Af[mt][0], Af[mt][1], Af[mt][2], Af[mt][3],
                             Bhf[nt>>1][(nt&1)*2], Bhf[nt>>1][(nt&1)*2+1]);
        }

        __syncthreads();
        if (i + 3 < NS) load_stage(i + 3, buf);
        buf = (buf == 2) ? 0 : buf + 1;
    }

    int g = lane >> 2, tg = lane & 3;
#pragma unroll
    for (int mt = 0; mt < 4; mt++) {
#pragma unroll
        for (int nt = 0; nt < 4; nt++) {
            int row0 = mblk + wm*64 + mt*16 + g;
            int col  = nblk + wn*32 + nt*8 + 2*tg;
#pragma unroll
            for (int half = 0; half < 2; half++) {
                int row = row0 + half*8;
                float v0 = acc[mt][nt][half*2+0];
                float v1 = acc[mt][nt][half*2+1];
                size_t gi = (size_t)row * N + col;
                if (EPI >= 1) { v0 += bias[col]; v1 += bias[col+1]; }
                if (EPI == 1) {
                    float2 rv = *(const float2*)&res[gi];
                    v0 += rv.x; v1 += rv.y;
                    float2 o; o.x = v0; o.y = v1;
                    *(float2*)&C[gi] = o;
                } else if (EPI == 2) {
                    v0 = fmaxf(v0, 0.f); v1 = fmaxf(v1, 0.f);
                    float h0 = tf32_rna(v0), h1 = tf32_rna(v1);
                    float2 hv; hv.x = h0; hv.y = h1;
                    float2 lv; lv.x = tf32_rna(v0 - h0); lv.y = tf32_rna(v1 - h1);
                    *(float2*)&C [gi] = hv;
                    *(float2*)&C2[gi] = lv;
                } else {
                    float2 o; o.x = v0; o.y = v1;
                    *(float2*)&C[gi] = o;
                }
            }
        }
    }
}

// ---------------------------------------------------------------------------
// Tensor-core flash attention (single-pass tf32 mma).
// Grid (16, B*H). 256 threads = 8 warps; each warp owns 16 query rows of a
// 128-row Q tile. Key/value tiles of 64. Row padding 68 floats -> conflict-
// free ldmatrix without swizzle. Q pre-scaled by 1/sqrt(DH), kept in regs.
// P staged per-warp through the (reused) Q smem slab; V stored transposed.
// ---------------------------------------------------------------------------
#define AP 68
#define ATTN2_SMEM ((128*AP + 64*AP + 64*AP) * 4)   // 69632 bytes

__global__ void __launch_bounds__(256, 2) attn2_kernel(const float* __restrict__ qkv,
                                                       float* __restrict__ oh,
                                                       float* __restrict__ ol)
{
    extern __shared__ float sm[];
    float* ps = sm;                 // [128][AP]: Q staging, then P
    float* ks = ps + 128*AP;        // [64][AP]:  K tile (rows=key, cols=d)
    float* vT = ks + 64*AP;         // [64][AP]:  V transposed (rows=d, cols=key)
    uint32_t ps_u = s2u(ps), ks_u = s2u(ks), vT_u = s2u(vT);

    int tid = threadIdx.x;
    int wid = tid >> 5, lane = tid & 31;
    int qt = (int)(gridDim.x - 1) - (int)blockIdx.x;   // heavy tiles first
    int b = blockIdx.y >> 4, h = blockIdx.y & 15;
    size_t rowbase = (size_t)b * S_;
    int qcol = h*64, kcol = 1024 + h*64, vcol = 2048 + h*64;

    int sub = lane >> 3, L = lane & 7;
    int rA = ((sub & 1) << 3) + L, cA = sub >> 1;
    int rB = ((sub >> 1) << 3) + L, cB = sub & 1;
    int g = lane >> 2, tg = lane & 3;

    // ---- stage Q (scaled by 1/8, tf32-rounded) ----
    for (int idx = tid; idx < 128*16; idx += 256) {
        int r = idx >> 4, q4 = idx & 15;
        float4 v = *(const float4*)&qkv[(rowbase + (size_t)qt*128 + r)*NQKV_ + qcol + q4*4];
        float4 w;
        w.x = tf32_rna(v.x * 0.125f); w.y = tf32_rna(v.y * 0.125f);
        w.z = tf32_rna(v.z * 0.125f); w.w = tf32_rna(v.w * 0.125f);
        *(float4*)&ps[r*AP + q4*4] = w;
    }
    __syncthreads();

    uint32_t qf[8][4];
#pragma unroll
    for (int k8 = 0; k8 < 8; k8++) {
        uint32_t a = ps_u + (uint32_t)((wid*16 + rA)*AP*4 + (2*k8 + cA)*16);
        LDSM4(qf[k8][0], qf[k8][1], qf[k8][2], qf[k8][3], a);
    }

    float m0 = -1e30f, m1 = -1e30f, l0 = 0.f, l1 = 0.f;
    float of[8][4];
#pragma unroll
    for (int nt = 0; nt < 8; nt++)
#pragma unroll
        for (int j = 0; j < 4; j++) of[nt][j] = 0.f;

    int tmax = 2*qt + 1;
    for (int t = 0; t <= tmax; t++) {
        __syncthreads();   // ks/vT consumed by all warps before overwrite
        // load K tile + V tile (transposed), tf32-rounded
        for (int idx = tid; idx < 64*16; idx += 256) {
            int r = idx >> 4, q4 = idx & 15;
            size_t tok = (rowbase + (size_t)t*64 + r) * NQKV_;
            float4 kv = *(const float4*)&qkv[tok + kcol + q4*4];
            float4 kw;
            kw.x = tf32_rna(kv.x); kw.y = tf32_rna(kv.y);
            kw.z = tf32_rna(kv.z); kw.w = tf32_rna(kv.w);
            *(float4*)&ks[r*AP + q4*4] = kw;
            float4 vv = *(const float4*)&qkv[tok + vcol + q4*4];
            vT[(q4*4+0)*AP + r] = tf32_rna(vv.x);
            vT[(q4*4+1)*AP + r] = tf32_rna(vv.y);
            vT[(q4*4+2)*AP + r] = tf32_rna(vv.z);
            vT[(q4*4+3)*AP + r] = tf32_rna(vv.w);
        }
        __syncthreads();

        // last diagonal tile fully masks warps 0-3 (rows < 64 of the block)
        bool active = !(t == 2*qt + 1 && wid < 4);
        if (active) {
            // ---- S = Q K^T (pre-scaled) ----
            float s[8][4];
#pragma unroll
            for (int nt = 0; nt < 8; nt++)
#pragma unroll
                for (int j = 0; j < 4; j++) s[nt][j] = 0.f;
#pragma unroll
            for (int k8 = 0; k8 < 8; k8++) {
#pragma unroll
                for (int np = 0; np < 4; np++) {
                    uint32_t bf0, bf1, bf2, bf3;
                    uint32_t a = ks_u + (uint32_t)((np*16 + rB)*AP*4 + (2*k8 + cB)*16);
                    LDSM4(bf0, bf1, bf2, bf3, a);
                    MMA_TF32(s[np*2][0], s[np*2][1], s[np*2][2], s[np*2][3],
                             qf[k8][0], qf[k8][1], qf[k8][2], qf[k8][3], bf0, bf1);
                    MMA_TF32(s[np*2+1][0], s[np*2+1][1], s[np*2+1][2], s[np*2+1][3],
                             qf[k8][0], qf[k8][1], qf[k8][2], qf[k8][3], bf2, bf3);
                }
            }

            // ---- causal mask (only the two diagonal tiles) ----
            if (t >= 2*qt) {
                int qr0 = qt*128 + wid*16 + g;
#pragma unroll
                for (int nt = 0; nt < 8; nt++) {
                    int c0 = t*64 + nt*8 + 2*tg;
                    if (c0     > qr0)   s[nt][0] = -1e30f;
                    if (c0 + 1 > qr0)   s[nt][1] = -1e30f;
                    if (c0     > qr0+8) s[nt][2] = -1e30f;
                    if (c0 + 1 > qr0+8) s[nt][3] = -1e30f;
                }
            }

            // ---- online softmax (rows g, g+8; quad-shuffle reductions) ----
            float mm0 = -1e30f, mm1 = -1e30f;
#pragma unroll
            for (int nt = 0; nt < 8; nt++) {
                mm0 = fmaxf(mm0, fmaxf(s[nt][0], s[nt][1]));
                mm1 = fmaxf(mm1, fmaxf(s[nt][2], s[nt][3]));
            }
            mm0 = fmaxf(mm0, __shfl_xor_sync(0xffffffffu, mm0, 1));
            mm0 = fmaxf(mm0, __shfl_xor_sync(0xffffffffu, mm0, 2));
            mm1 = fmaxf(mm1, __shfl_xor_sync(0xffffffffu, mm1, 1));
            mm1 = fmaxf(mm1, __shfl_xor_sync(0xffffffffu, mm1, 2));
            float mn0 = fmaxf(m0, mm0), mn1 = fmaxf(m1, mm1);
            float a0 = expf(m0 - mn0), a1 = expf(m1 - mn1);
            float sum0 = 0.f, sum1 = 0.f;
#pragma unroll
            for (int nt = 0; nt < 8; nt++) {
                s[nt][0] = expf(s[nt][0] - mn0);
                s[nt][1] = expf(s[nt][1] - mn0);
                s[nt][2] = expf(s[nt][2] - mn1);
                s[nt][3] = expf(s[nt][3] - mn1);
                sum0 += s[nt][0] + s[nt][1];
                sum1 += s[nt][2] + s[nt][3];
            }
            sum0 += __shfl_xor_sync(0xffffffffu, sum0, 1);
            sum0 += __shfl_xor_sync(0xffffffffu, sum0, 2);
            sum1 += __shfl_xor_sync(0xffffffffu, sum1, 1);
            sum1 += __shfl_xor_sync(0xffffffffu, sum1, 2);
            l0 = l0*a0 + sum0; m0 = mn0;
            l1 = l1*a1 + sum1; m1 = mn1;
#pragma unroll
            for (int nt = 0; nt < 8; nt++) {
                of[nt][0] *= a0; of[nt][1] *= a0;
                of[nt][2] *= a1; of[nt][3] *= a1;
            }

            // ---- stage P (own 16-row slab of ps; tf32-rounded) ----
            int pr0 = (wid*16 + g) * AP;
#pragma unroll
            for (int nt = 0; nt < 8; nt++) {
                int c = nt*8 + 2*tg;
                float2 p0; p0.x = tf32_rna(s[nt][0]); p0.y = tf32_rna(s[nt][1]);
                float2 p1; p1.x = tf32_rna(s[nt][2]); p1.y = tf32_rna(s[nt][3]);
                *(float2*)&ps[pr0 + c]        = p0;
                *(float2*)&ps[pr0 + 8*AP + c] = p1;
            }
            __syncwarp();

            // ---- O += P V ----
#pragma unroll
            for (int k8 = 0; k8 < 8; k8++) {
                uint32_t pf0, pf1, pf2, pf3;
                uint32_t pa = ps_u + (uint32_t)((wid*16 + rA)*AP*4 + (2*k8 + cA)*16);
                LDSM4(pf0, pf1, pf2, pf3, pa);
#pragma unroll
                for (int np = 0; np < 4; np++) {
                    uint32_t bf0, bf1, bf2, bf3;
                    uint32_t a = vT_u + (uint32_t)((np*16 + rB)*AP*4 + (2*k8 + cB)*16);
                    LDSM4(bf0, bf1, bf2, bf3, a);
                    MMA_TF32(of[np*2][0], of[np*2][1], of[np*2][2], of[np*2][3],
                             pf0, pf1, pf2, pf3, bf0, bf1);
                    MMA_TF32(of[np*2+1][0], of[np*2+1][1], of[np*2+1][2], of[np*2+1][3],
                             pf0, pf1, pf2, pf3, bf2, bf3);
                }
            }
        }
    }

    // ---- epilogue: normalize, hi/lo split, write head-concat layout ----
    float inv0 = 1.f / l0, inv1 = 1.f / l1;
    size_t ro0 = rowbase + (size_t)qt*128 + wid*16 + g;
    size_t ro1 = ro0 + 8;
#pragma unroll
    for (int nt = 0; nt < 8; nt++) {
        int col = h*64 + nt*8 + 2*tg;
        float v0 = of[nt][0]*inv0, v1 = of[nt][1]*inv0;
        float v2 = of[nt][2]*inv1, v3 = of[nt][3]*inv1;
        float h0 = tf32_rna(v0), h1 = tf32_rna(v1);
        float h2 = tf32_rna(v2), h3 = tf32_rna(v3);
        float2 hv0; hv0.x = h0; hv0.y = h1;
        float2 lv0; lv0.x = tf32_rna(v0 - h0); lv0.y = tf32_rna(v1 - h1);
        float2 hv1; hv1.x = h2; hv1.y = h3;
        float2 lv1; lv1.x = tf32_rna(v2 - h2); lv1.y = tf32_rna(v3 - h3);
        *(float2*)&oh[ro0*E_ + col] = hv0;
        *(float2*)&ol[ro0*E_ + col] = lv0;
        *(float2*)&oh[ro1*E_ + col] = hv1;
        *(float2*)&ol[ro1*E_ + col] = lv1;
    }
}

// ---------------------------------------------------------------------------
// Launch
// ---------------------------------------------------------------------------
extern "C" void kernel_launch(void* const* d_in, const int* in_sizes, int n_in,
                              void* d_out, int out_size)
{
    (void)in_sizes; (void)n_in; (void)out_size;
    const float* x   = (const float*)d_in[0];
    const float* Wq  = (const float*)d_in[1];
    const float* Wk  = (const float*)d_in[2];
    const float* Wv  = (const float*)d_in[3];
    const float* Wo  = (const float*)d_in[4];
    const float* bo  = (const float*)d_in[5];
    const float* g1  = (const float*)d_in[6];
    const float* be1 = (const float*)d_in[7];
    const float* g2  = (const float*)d_in[8];
    const float* be2 = (const float*)d_in[9];
    const float* W1  = (const float*)d_in[10];
    const float* bb1 = (const float*)d_in[11];
    const float* W2  = (const float*)d_in[12];
    const float* bb2 = (const float*)d_in[13];
    float* out = (float*)d_out;

    float *lx_h, *lx_l, *wqkv_h, *wqkv_l, *qkv, *o_h, *o_l, *x2, *lx2_h, *lx2_l;
    float *ffh_h, *ffh_l, *WoT_h, *WoT_l, *W1T_h, *W1T_l, *W2T_h, *W2T_l;
    cudaGetSymbolAddress((void**)&lx_h,   g_lx_h);
    cudaGetSymbolAddress((void**)&lx_l,   g_lx_l);
    cudaGetSymbolAddress((void**)&wqkv_h, g_wqkv_h);
    cudaGetSymbolAddress((void**)&wqkv_l, g_wqkv_l);
    cudaGetSymbolAddress((void**)&qkv,    g_qkv);
    cudaGetSymbolAddress((void**)&o_h,    g_o_h);
    cudaGetSymbolAddress((void**)&o_l,    g_o_l);
    cudaGetSymbolAddress((void**)&x2,     g_x2);
    cudaGetSymbolAddress((void**)&lx2_h,  g_lx2_h);
    cudaGetSymbolAddress((void**)&lx2_l,  g_lx2_l);
    cudaGetSymbolAddress((void**)&ffh_h,  g_ffh_h);
    cudaGetSymbolAddress((void**)&ffh_l,  g_ffh_l);
    cudaGetSymbolAddress((void**)&WoT_h,  g_WoT_h);
    cudaGetSymbolAddress((void**)&WoT_l,  g_WoT_l);
    cudaGetSymbolAddress((void**)&W1T_h,  g_W1T_h);
    cudaGetSymbolAddress((void**)&W1T_l,  g_W1T_l);
    cudaGetSymbolAddress((void**)&W2T_h,  g_W2T_h);
    cudaGetSymbolAddress((void**)&W2T_l,  g_W2T_l);

    cudaFuncSetAttribute(attn2_kernel, cudaFuncAttributeMaxDynamicSharedMemorySize, ATTN2_SMEM);
    cudaFuncSetAttribute(gemm_tf32<0>, cudaFuncAttributeMaxDynamicSharedMemorySize, GSMEM);
    cudaFuncSetAttribute(gemm_tf32<1>, cudaFuncAttributeMaxDynamicSharedMemorySize, GSMEM);
    cudaFuncSetAttribute(gemm_tf32<2>, cudaFuncAttributeMaxDynamicSharedMemorySize, GSMEM);

    // 1. LN1 -> lx hi/lo
    ln_kernel<<<M_, 256>>>(x, g1, be1, lx_h, lx_l);
    // 2. weight prep
    pack_qkv_kernel<<<(NQKV_*E_)/256, 256>>>(Wq, Wk, Wv, wqkv_h, wqkv_l);
    tsplit_kernel<<<dim3(E_/32,  E_/32),  dim3(32,8)>>>(Wo, WoT_h, WoT_l, E_,  E_);
    tsplit_kernel<<<dim3(FF_/32, E_/32),  dim3(32,8)>>>(W1, W1T_h, W1T_l, E_,  FF_);
    tsplit_kernel<<<dim3(E_/32,  FF_/32), dim3(32,8)>>>(W2, W2T_h, W2T_l, FF_, E_);
    // 3. qkv = lx @ Wqkv
    gemm_tf32<0><<<dim3(NQKV_/128, M_/128), 256, GSMEM>>>(
        lx_h, lx_l, wqkv_h, wqkv_l, qkv, nullptr, nullptr, nullptr, E_, NQKV_);
    // 4. attention -> o hi/lo (tensor-core flash attention)
    attn2_kernel<<<dim3(S_/128, B_*H_), 256, ATTN2_SMEM>>>(qkv, o_h, o_l);
    // 5. x2 = x + o @ Wo + bo
    gemm_tf32<1><<<dim3(E_/128, M_/128), 256, GSMEM>>>(
        o_h, o_l, WoT_h, WoT_l, x2, nullptr, bo, x, E_, E_);
    // 6. LN2 -> lx2 hi/lo
    ln_kernel<<<M_, 256>>>(x2, g2, be2, lx2_h, lx2_l);
    // 7. ffh = relu(lx2 @ W1 + b1) -> hi/lo
    gemm_tf32<2><<<dim3(FF_/128, M_/128), 256, GSMEM>>>(
        lx2_h, lx2_l, W1T_h, W1T_l, ffh_h, ffh_l, bb1, nullptr, E_, FF_);
    // 8. out = x2 + ffh @ W2 + b2
    gemm_tf32<1><<<dim3(E_/128, M_/128), 256, GSMEM>>>(
        ffh_h, ffh_l, W2T_h, W2T_l, out, nullptr, bb2, x2, FF_, E_);
}

// round 6
// speedup vs baseline: 1.7790x; 1.0464x over previous
#include <cuda_runtime.h>
#include <math.h>
#include <stdint.h>

// Problem constants
#define B_    4
#define S_    2048
#define E_    1024
#define H_    16
#define DH_   64
#define M_    (B_*S_)      // 8192 rows
#define FF_   4096
#define NQKV_ 3072

// ---------------------------------------------------------------------------
// Scratch (static __device__ arrays)
// ---------------------------------------------------------------------------
__device__ float g_lx_h [(size_t)M_*E_];
__device__ float g_lx_l [(size_t)M_*E_];
__device__ float g_wqkv_h[(size_t)NQKV_*E_];   // [N=3072, K=1024]
__device__ float g_wqkv_l[(size_t)NQKV_*E_];
__device__ float g_qkv  [(size_t)M_*NQKV_];
__device__ float g_o_h  [(size_t)M_*E_];
__device__ float g_o_l  [(size_t)M_*E_];
__device__ float g_x2   [(size_t)M_*E_];
__device__ float g_lx2_h[(size_t)M_*E_];
__device__ float g_lx2_l[(size_t)M_*E_];
__device__ float g_ffh_h[(size_t)M_*FF_];
__device__ float g_ffh_l[(size_t)M_*FF_];
__device__ float g_WoT_h[(size_t)E_*E_];       // [N=1024, K=1024]
__device__ float g_WoT_l[(size_t)E_*E_];
__device__ float g_W1T_h[(size_t)FF_*E_];      // [N=4096, K=1024]
__device__ float g_W1T_l[(size_t)FF_*E_];
__device__ float g_W2T_h[(size_t)E_*FF_];      // [N=1024, K=4096]
__device__ float g_W2T_l[(size_t)E_*FF_];

// ---------------------------------------------------------------------------
// Helpers
// ---------------------------------------------------------------------------
static __device__ __forceinline__ float tf32_rna(float x) {
    uint32_t u;
    asm("cvt.rna.tf32.f32 %0, %1;" : "=r"(u) : "f"(x));
    return __uint_as_float(u);
}

static __device__ __forceinline__ uint32_t s2u(const void* p) {
    uint32_t a;
    asm("{ .reg .u64 t; cvta.to.shared.u64 t, %1; cvt.u32.u64 %0, t; }" : "=r"(a) : "l"(p));
    return a;
}

#define CP16(dst, src) \
    asm volatile("cp.async.cg.shared.global [%0], [%1], 16;" :: "r"(dst), "l"(src))
#define CP_COMMIT() asm volatile("cp.async.commit_group;")
#define CP_WAIT1()  asm volatile("cp.async.wait_group 1;")
#define CP_WAIT0()  asm volatile("cp.async.wait_group 0;")

#define LDSM4(r0, r1, r2, r3, addr) \
    asm volatile("ldmatrix.sync.aligned.m8n8.x4.shared.b16 {%0,%1,%2,%3}, [%4];" \
                 : "=r"(r0), "=r"(r1), "=r"(r2), "=r"(r3) : "r"(addr))

#define MMA_TF32(d0, d1, d2, d3, a0, a1, a2, a3, b0, b1) \
    asm volatile("mma.sync.aligned.m16n8k8.row.col.f32.tf32.tf32.f32 " \
                 "{%0,%1,%2,%3}, {%4,%5,%6,%7}, {%8,%9}, {%0,%1,%2,%3};" \
                 : "+f"(d0), "+f"(d1), "+f"(d2), "+f"(d3) \
                 : "r"(a0), "r"(a1), "r"(a2), "r"(a3), "r"(b0), "r"(b1))

// ---------------------------------------------------------------------------
// LayerNorm (fused hi/lo split output)
// ---------------------------------------------------------------------------
__global__ void ln_kernel(const float* __restrict__ x, const float* __restrict__ g,
                          const float* __restrict__ b,
                          float* __restrict__ oh, float* __restrict__ ol)
{
    int row = blockIdx.x;
    int t = threadIdx.x;
    const float* xr = x + (size_t)row * E_;
    float v[4];
    float s = 0.f, s2 = 0.f;
#pragma unroll
    for (int i = 0; i < 4; i++) {
        v[i] = xr[t + 256*i];
        s += v[i];
        s2 += v[i]*v[i];
    }
#pragma unroll
    for (int m = 16; m; m >>= 1) {
        s  += __shfl_xor_sync(0xffffffffu, s,  m);
        s2 += __shfl_xor_sync(0xffffffffu, s2, m);
    }
    __shared__ float sh[2][8];
    if ((t & 31) == 0) { sh[0][t>>5] = s; sh[1][t>>5] = s2; }
    __syncthreads();
    s = 0.f; s2 = 0.f;
#pragma unroll
    for (int w = 0; w < 8; w++) { s += sh[0][w]; s2 += sh[1][w]; }
    float mu  = s * (1.f/E_);
    float var = s2 * (1.f/E_) - mu*mu;
    float r = rsqrtf(var + 1e-5f);
    size_t rb = (size_t)row * E_;
#pragma unroll
    for (int i = 0; i < 4; i++) {
        int c = t + 256*i;
        float y = (v[i]-mu)*r*g[c] + b[c];
        float h = tf32_rna(y);
        oh[rb + c] = h;
        ol[rb + c] = tf32_rna(y - h);
    }
}

// ---------------------------------------------------------------------------
// Pack Wq/Wk/Wv into [N=3072, K=1024] hi/lo (K-major, head-concat columns)
// ---------------------------------------------------------------------------
__global__ void pack_qkv_kernel(const float* __restrict__ Wq, const float* __restrict__ Wk,
                                const float* __restrict__ Wv,
                                float* __restrict__ oh, float* __restrict__ ol)
{
    int idx = blockIdx.x*256 + threadIdx.x;
    int n = idx / E_;
    int e = idx - n*E_;
    const float* W = (n < 1024) ? Wq : (n < 2048 ? Wk : Wv);
    int hd = n & 1023;
    float v = W[(size_t)(hd >> 6)*(E_*DH_) + (size_t)e*DH_ + (hd & 63)];
    float h = tf32_rna(v);
    oh[idx] = h;
    ol[idx] = tf32_rna(v - h);
}

// ---------------------------------------------------------------------------
// Transpose + split: in [K,N] row-major -> out_hi/lo [N,K] row-major
// ---------------------------------------------------------------------------
__global__ void tsplit_kernel(const float* __restrict__ in, float* __restrict__ oh,
                              float* __restrict__ ol, int K, int N)
{
    __shared__ float t[32][33];
    int k0 = blockIdx.y*32, n0 = blockIdx.x*32;
    int tx = threadIdx.x, ty = threadIdx.y;
#pragma unroll
    for (int r = ty; r < 32; r += 8)
        t[r][tx] = in[(size_t)(k0+r)*N + n0+tx];
    __syncthreads();
#pragma unroll
    for (int r = ty; r < 32; r += 8) {
        float v = t[tx][r];
        float h = tf32_rna(v);
        size_t o = (size_t)(n0+r)*K + k0+tx;
        oh[o] = h;
        ol[o] = tf32_rna(v - h);
    }
}

// ---------------------------------------------------------------------------
// Split-TF32 GEMM via mma.sync. CTA tile 128(M) x 256(N), 8 warps as 2x4,
// warp tile 64x64. K-chunk 32, 2-stage cp.async pipeline (96 KB/stage).
// XOR-swizzled smem, conflict-free ldmatrix. B given [N,K] row-major.
// EPI: 0 = plain, 1 = +bias[col]+res, 2 = relu(+bias) split to C(hi)/C2(lo)
// ---------------------------------------------------------------------------
#define STAGE_BYTES 98304        // Ah 16K | Al 16K | Bh 32K | Bl 32K
#define GSMEM (2*STAGE_BYTES)    // 196608

template<int EPI>
__global__ void __launch_bounds__(256, 1) gemm_tf32(
    const float* __restrict__ Ah, const float* __restrict__ Al,
    const float* __restrict__ Bh, const float* __restrict__ Bl,
    float* __restrict__ C, float* __restrict__ C2,
    const float* __restrict__ bias, const float* __restrict__ res,
    int K, int N)
{
    extern __shared__ char smc[];
    uint32_t sb = s2u(smc);
    int tid = threadIdx.x;
    int wid = tid >> 5, lane = tid & 31;
    int wm = wid >> 2, wn = wid & 3;          // 2 x 4 warp grid
    int mblk = blockIdx.y * 128, nblk = blockIdx.x * 256;

    int sub = lane >> 3, L = lane & 7;
    int rA = ((sub & 1) << 3) + L, cAadd = sub >> 1;
    int rB = ((sub >> 1) << 3) + L, cBadd = sub & 1;

    uint32_t sAh[2], sAl[2], sBh[2], sBl[2];
#pragma unroll
    for (int b = 0; b < 2; b++) {
        uint32_t base = sb + b * STAGE_BYTES;
        sAh[b] = base;          sAl[b] = base + 16384;
        sBh[b] = base + 32768;  sBl[b] = base + 65536;
    }

    float acc[4][8][4];
#pragma unroll
    for (int mt = 0; mt < 4; mt++)
#pragma unroll
        for (int nt = 0; nt < 8; nt++)
#pragma unroll
            for (int q = 0; q < 4; q++) acc[mt][nt][q] = 0.f;

    auto load_stage = [&](int s, int b) {
        int k0 = s << 5;
        for (int idx = tid; idx < 1024; idx += 256) {     // A: 128 rows x 8 chunks
            int r = idx >> 3, q = idx & 7;
            uint32_t off = (uint32_t)(r*128 + ((q ^ (r & 7)) << 4));
            size_t gA = (size_t)(mblk + r) * K + k0 + q*4;
            CP16(sAh[b] + off, Ah + gA);
            CP16(sAl[b] + off, Al + gA);
        }
        for (int idx = tid; idx < 2048; idx += 256) {     // B: 256 rows x 8 chunks
            int r = idx >> 3, q = idx & 7;
            uint32_t off = (uint32_t)(r*128 + ((q ^ (r & 7)) << 4));
            size_t gB = (size_t)(nblk + r) * K + k0 + q*4;
            CP16(sBh[b] + off, Bh + gB);
            CP16(sBl[b] + off, Bl + gB);
        }
        CP_COMMIT();
    };

    const int NS = K >> 5;
    load_stage(0, 0);
    load_stage(1, 1);

    for (int i = 0; i < NS; i++) {
        int buf = i & 1;
        if (i + 2 <= NS - 1) CP_WAIT1(); else CP_WAIT0();
        __syncthreads();

#pragma unroll
        for (int ks = 0; ks < 4; ks++) {
            int c0 = 2*ks;
            uint32_t Af[4][4], Bhf[4][4], Blf[4][4];
            // A-hi fragments (4 x m16)
#pragma unroll
            for (int mt = 0; mt < 4; mt++) {
                int row = wm*64 + mt*16 + rA;
                int ch = c0 + cAadd;
                uint32_t a = sAh[buf] + row*128 + ((ch ^ (row & 7)) << 4);
                LDSM4(Af[mt][0], Af[mt][1], Af[mt][2], Af[mt][3], a);
            }
            // B-hi fragments (4 x pair-of-n8 covering 64 cols)
#pragma unroll
            for (int np = 0; np < 4; np++) {
                int row = wn*64 + np*16 + rB;
                int ch = c0 + cBadd;
                uint32_t sw = (uint32_t)(row*128 + ((ch ^ (row & 7)) << 4));
                LDSM4(Bhf[np][0], Bhf[np][1], Bhf[np][2], Bhf[np][3], sBh[buf] + sw);
            }
            // Ah * Bh
#pragma unroll
            for (int mt = 0; mt < 4; mt++)
#pragma unroll
                for (int nt = 0; nt < 8; nt++)
                    MMA_TF32(acc[mt][nt][0], acc[mt][nt][1], acc[mt][nt][2], acc[mt][nt][3],
                             Af[mt][0], Af[mt][1], Af[mt][2], Af[mt][3],
                             Bhf[nt>>1][(nt&1)*2], Bhf[nt>>1][(nt&1)*2+1]);
            // B-lo fragments, Ah * Bl
#pragma unroll
            for (int np = 0; np < 4; np++) {
                int row = wn*64 + np*16 + rB;
                int ch = c0 + cBadd;
                uint32_t sw = (uint32_t)(row*128 + ((ch ^ (row & 7)) << 4));
                LDSM4(Blf[np][0], Blf[np][1], Blf[np][2], Blf[np][3], sBl[buf] + sw);
            }
#pragma unroll
            for (int mt = 0; mt < 4; mt++)
#pragma unroll
                for (int nt = 0; nt < 8; nt++)
                    MMA_TF32(acc[mt][nt][0], acc[mt][nt][1], acc[mt][nt][2], acc[mt][nt][3],
                             Af[mt][0], Af[mt][1], Af[mt][2], Af[mt][3],
                             Blf[nt>>1][(nt&1)*2], Blf[nt>>1][(nt&1)*2+1]);
            // A-lo fragments (reuse Af), Al * Bh
#pragma unroll
            for (int mt = 0; mt < 4; mt++) {
                int row = wm*64 + mt*16 + rA;
                int ch = c0 + cAadd;
                uint32_t a = sAl[buf] + row*128 + ((ch ^ (row & 7)) << 4);
                LDSM4(Af[mt][0], Af[mt][1], Af[mt][2], Af[mt][3], a);
            }
#pragma unroll
            for (int mt = 0; mt < 4; mt++)
#pragma unroll
                for (int nt = 0; nt < 8; nt++)
                    MMA_TF32(acc[mt][nt][0], acc[mt][nt][1], acc[mt][nt][2], acc[mt][nt][3],
                             Af[mt][0], Af[mt][1], Af[mt][2], Af[mt][3],
                             Bhf[nt>>1][(nt&1)*2], Bhf[nt>>1][(nt&1)*2+1]);
        }

        __syncthreads();
        if (i + 2 < NS) load_stage(i + 2, buf);
    }

    // Epilogue
    int g = lane >> 2, tg = lane & 3;
#pragma unroll
    for (int mt = 0; mt < 4; mt++) {
#pragma unroll
        for (int nt = 0; nt < 8; nt++) {
            int row0 = mblk + wm*64 + mt*16 + g;
            int col  = nblk + wn*64 + nt*8 + 2*tg;
#pragma unroll
            for (int half = 0; half < 2; half++) {
                int row = row0 + half*8;
                float v0 = acc[mt][nt][half*2+0];
                float v1 = acc[mt][nt][half*2+1];
                size_t gi = (size_t)row * N + col;
                if (EPI >= 1) { v0 += bias[col]; v1 += bias[col+1]; }
                if (EPI == 1) {
                    float2 rv = *(const float2*)&res[gi];
                    v0 += rv.x; v1 += rv.y;
                    float2 o; o.x = v0; o.y = v1;
                    *(float2*)&C[gi] = o;
                } else if (EPI == 2) {
                    v0 = fmaxf(v0, 0.f); v1 = fmaxf(v1, 0.f);
                    float h0 = tf32_rna(v0), h1 = tf32_rna(v1);
                    float2 hv; hv.x = h0; hv.y = h1;
                    float2 lv; lv.x = tf32_rna(v0 - h0); lv.y = tf32_rna(v1 - h1);
                    *(float2*)&C [gi] = hv;
                    *(float2*)&C2[gi] = lv;
                } else {
                    float2 o; o.x = v0; o.y = v1;
                    *(float2*)&C[gi] = o;
                }
            }
        }
    }
}

// ---------------------------------------------------------------------------
// Tensor-core flash attention (single-pass tf32 mma). Validated round 5.
// ---------------------------------------------------------------------------
#define AP 68
#define ATTN2_SMEM ((128*AP + 64*AP + 64*AP) * 4)   // 69632 bytes

__global__ void __launch_bounds__(256, 2) attn2_kernel(const float* __restrict__ qkv,
                                                       float* __restrict__ oh,
                                                       float* __restrict__ ol)
{
    extern __shared__ float sm[];
    float* ps = sm;                 // [128][AP]: Q staging, then P
    float* ks = ps + 128*AP;        // [64][AP]:  K tile
    float* vT = ks + 64*AP;         // [64][AP]:  V transposed
    uint32_t ps_u = s2u(ps), ks_u = s2u(ks), vT_u = s2u(vT);

    int tid = threadIdx.x;
    int wid = tid >> 5, lane = tid & 31;
    int qt = (int)(gridDim.x - 1) - (int)blockIdx.x;   // heavy tiles first
    int b = blockIdx.y >> 4, h = blockIdx.y & 15;
    size_t rowbase = (size_t)b * S_;
    int qcol = h*64, kcol = 1024 + h*64, vcol = 2048 + h*64;

    int sub = lane >> 3, L = lane & 7;
    int rA = ((sub & 1) << 3) + L, cA = sub >> 1;
    int rB = ((sub >> 1) << 3) + L, cB = sub & 1;
    int g = lane >> 2, tg = lane & 3;

    for (int idx = tid; idx < 128*16; idx += 256) {
        int r = idx >> 4, q4 = idx & 15;
        float4 v = *(const float4*)&qkv[(rowbase + (size_t)qt*128 + r)*NQKV_ + qcol + q4*4];
        float4 w;
        w.x = tf32_rna(v.x * 0.125f); w.y = tf32_rna(v.y * 0.125f);
        w.z = tf32_rna(v.z * 0.125f); w.w = tf32_rna(v.w * 0.125f);
        *(float4*)&ps[r*AP + q4*4] = w;
    }
    __syncthreads();

    uint32_t qf[8][4];
#pragma unroll
    for (int k8 = 0; k8 < 8; k8++) {
        uint32_t a = ps_u + (uint32_t)((wid*16 + rA)*AP*4 + (2*k8 + cA)*16);
        LDSM4(qf[k8][0], qf[k8][1], qf[k8][2], qf[k8][3], a);
    }

    float m0 = -1e30f, m1 = -1e30f, l0 = 0.f, l1 = 0.f;
    float of[8][4];
#pragma unroll
    for (int nt = 0; nt < 8; nt++)
#pragma unroll
        for (int j = 0; j < 4; j++) of[nt][j] = 0.f;

    int tmax = 2*qt + 1;
    for (int t = 0; t <= tmax; t++) {
        __syncthreads();
        for (int idx = tid; idx < 64*16; idx += 256) {
            int r = idx >> 4, q4 = idx & 15;
            size_t tok = (rowbase + (size_t)t*64 + r) * NQKV_;
            float4 kv = *(const float4*)&qkv[tok + kcol + q4*4];
            float4 kw;
            kw.x = tf32_rna(kv.x); kw.y = tf32_rna(kv.y);
            kw.z = tf32_rna(kv.z); kw.w = tf32_rna(kv.w);
            *(float4*)&ks[r*AP + q4*4] = kw;
            float4 vv = *(const float4*)&qkv[tok + vcol + q4*4];
            vT[(q4*4+0)*AP + r] = tf32_rna(vv.x);
            vT[(q4*4+1)*AP + r] = tf32_rna(vv.y);
            vT[(q4*4+2)*AP + r] = tf32_rna(vv.z);
            vT[(q4*4+3)*AP + r] = tf32_rna(vv.w);
        }
        __syncthreads();

        bool active = !(t == 2*qt + 1 && wid < 4);
        if (active) {
            float s[8][4];
#pragma unroll
            for (int nt = 0; nt < 8; nt++)
#pragma unroll
                for (int j = 0; j < 4; j++) s[nt][j] = 0.f;
#pragma unroll
            for (int k8 = 0; k8 < 8; k8++) {
#pragma unroll
                for (int np = 0; np < 4; np++) {
                    uint32_t bf0, bf1, bf2, bf3;
                    uint32_t a = ks_u + (uint32_t)((np*16 + rB)*AP*4 + (2*k8 + cB)*16);
                    LDSM4(bf0, bf1, bf2, bf3, a);
                    MMA_TF32(s[np*2][0], s[np*2][1], s[np*2][2], s[np*2][3],
                             qf[k8][0], qf[k8][1], qf[k8][2], qf[k8][3], bf0, bf1);
                    MMA_TF32(s[np*2+1][0], s[np*2+1][1], s[np*2+1][2], s[np*2+1][3],
                             qf[k8][0], qf[k8][1], qf[k8][2], qf[k8][3], bf2, bf3);
                }
            }

            if (t >= 2*qt) {
                int qr0 = qt*128 + wid*16 + g;
#pragma unroll
                for (int nt = 0; nt < 8; nt++) {
                    int c0 = t*64 + nt*8 + 2*tg;
                    if (c0     > qr0)   s[nt][0] = -1e30f;
                    if (c0 + 1 > qr0)   s[nt][1] = -1e30f;
                    if (c0     > qr0+8) s[nt][2] = -1e30f;
                    if (c0 + 1 > qr0+8) s[nt][3] = -1e30f;
                }
            }

            float mm0 = -1e30f, mm1 = -1e30f;
#pragma unroll
            for (int nt = 0; nt < 8; nt++) {
                mm0 = fmaxf(mm0, fmaxf(s[nt][0], s[nt][1]));
                mm1 = fmaxf(mm1, fmaxf(s[nt][2], s[nt][3]));
            }
            mm0 = fmaxf(mm0, __shfl_xor_sync(0xffffffffu, mm0, 1));
            mm0 = fmaxf(mm0, __shfl_xor_sync(0xffffffffu, mm0, 2));
            mm1 = fmaxf(mm1, __shfl_xor_sync(0xffffffffu, mm1, 1));
            mm1 = fmaxf(mm1, __shfl_xor_sync(0xffffffffu, mm1, 2));
            float mn0 = fmaxf(m0, mm0), mn1 = fmaxf(m1, mm1);
            float a0 = expf(m0 - mn0), a1 = expf(m1 - mn1);
            float sum0 = 0.f, sum1 = 0.f;
#pragma unroll
            for (int nt = 0; nt < 8; nt++) {
                s[nt][0] = expf(s[nt][0] - mn0);
                s[nt][1] = expf(s[nt][1] - mn0);
                s[nt][2] = expf(s[nt][2] - mn1);
                s[nt][3] = expf(s[nt][3] - mn1);
                sum0 += s[nt][0] + s[nt][1];
                sum1 += s[nt][2] + s[nt][3];
            }
            sum0 += __shfl_xor_sync(0xffffffffu, sum0, 1);
            sum0 += __shfl_xor_sync(0xffffffffu, sum0, 2);
            sum1 += __shfl_xor_sync(0xffffffffu, sum1, 1);
            sum1 += __shfl_xor_sync(0xffffffffu, sum1, 2);
            l0 = l0*a0 + sum0; m0 = mn0;
            l1 = l1*a1 + sum1; m1 = mn1;
#pragma unroll
            for (int nt = 0; nt < 8; nt++) {
                of[nt][0] *= a0; of[nt][1] *= a0;
                of[nt][2] *= a1; of[nt][3] *= a1;
            }

            int pr0 = (wid*16 + g) * AP;
#pragma unroll
            for (int nt = 0; nt < 8; nt++) {
                int c = nt*8 + 2*tg;
                float2 p0; p0.x = tf32_rna(s[nt][0]); p0.y = tf32_rna(s[nt][1]);
                float2 p1; p1.x = tf32_rna(s[nt][2]); p1.y = tf32_rna(s[nt][3]);
                *(float2*)&ps[pr0 + c]        = p0;
                *(float2*)&ps[pr0 + 8*AP + c] = p1;
            }
            __syncwarp();

#pragma unroll
            for (int k8 = 0; k8 < 8; k8++) {
                uint32_t pf0, pf1, pf2, pf3;
                uint32_t pa = ps_u + (uint32_t)((wid*16 + rA)*AP*4 + (2*k8 + cA)*16);
                LDSM4(pf0, pf1, pf2, pf3, pa);
#pragma unroll
                for (int np = 0; np < 4; np++) {
                    uint32_t bf0, bf1, bf2, bf3;
                    uint32_t a = vT_u + (uint32_t)((np*16 + rB)*AP*4 + (2*k8 + cB)*16);
                    LDSM4(bf0, bf1, bf2, bf3, a);
                    MMA_TF32(of[np*2][0], of[np*2][1], of[np*2][2], of[np*2][3],
                             pf0, pf1, pf2, pf3, bf0, bf1);
                    MMA_TF32(of[np*2+1][0], of[np*2+1][1], of[np*2+1][2], of[np*2+1][3],
                             pf0, pf1, pf2, pf3, bf2, bf3);
                }
            }
        }
    }

    float inv0 = 1.f / l0, inv1 = 1.f / l1;
    size_t ro0 = rowbase + (size_t)qt*128 + wid*16 + g;
    size_t ro1 = ro0 + 8;
#pragma unroll
    for (int nt = 0; nt < 8; nt++) {
        int col = h*64 + nt*8 + 2*tg;
        float v0 = of[nt][0]*inv0, v1 = of[nt][1]*inv0;
        float v2 = of[nt][2]*inv1, v3 = of[nt][3]*inv1;
        float h0 = tf32_rna(v0), h1 = tf32_rna(v1);
        float h2 = tf32_rna(v2), h3 = tf32_rna(v3);
        float2 hv0; hv0.x = h0; hv0.y = h1;
        float2 lv0; lv0.x = tf32_rna(v0 - h0); lv0.y = tf32_rna(v1 - h1);
        float2 hv1; hv1.x = h2; hv1.y = h3;
        float2 lv1; lv1.x = tf32_rna(v2 - h2); lv1.y = tf32_rna(v3 - h3);
        *(float2*)&oh[ro0*E_ + col] = hv0;
        *(float2*)&ol[ro0*E_ + col] = lv0;
        *(float2*)&oh[ro1*E_ + col] = hv1;
        *(float2*)&ol[ro1*E_ + col] = lv1;
    }
}

// ---------------------------------------------------------------------------
// Launch
// ---------------------------------------------------------------------------
extern "C" void kernel_launch(void* const* d_in, const int* in_sizes, int n_in,
                              void* d_out, int out_size)
{
    (void)in_sizes; (void)n_in; (void)out_size;
    const float* x   = (const float*)d_in[0];
    const float* Wq  = (const float*)d_in[1];
    const float* Wk  = (const float*)d_in[2];
    const float* Wv  = (const float*)d_in[3];
    const float* Wo  = (const float*)d_in[4];
    const float* bo  = (const float*)d_in[5];
    const float* g1  = (const float*)d_in[6];
    const float* be1 = (const float*)d_in[7];
    const float* g2  = (const float*)d_in[8];
    const float* be2 = (const float*)d_in[9];
    const float* W1  = (const float*)d_in[10];
    const float* bb1 = (const float*)d_in[11];
    const float* W2  = (const float*)d_in[12];
    const float* bb2 = (const float*)d_in[13];
    float* out = (float*)d_out;

    float *lx_h, *lx_l, *wqkv_h, *wqkv_l, *qkv, *o_h, *o_l, *x2, *lx2_h, *lx2_l;
    float *ffh_h, *ffh_l, *WoT_h, *WoT_l, *W1T_h, *W1T_l, *W2T_h, *W2T_l;
    cudaGetSymbolAddress((void**)&lx_h,   g_lx_h);
    cudaGetSymbolAddress((void**)&lx_l,   g_lx_l);
    cudaGetSymbolAddress((void**)&wqkv_h, g_wqkv_h);
    cudaGetSymbolAddress((void**)&wqkv_l, g_wqkv_l);
    cudaGetSymbolAddress((void**)&qkv,    g_qkv);
    cudaGetSymbolAddress((void**)&o_h,    g_o_h);
    cudaGetSymbolAddress((void**)&o_l,    g_o_l);
    cudaGetSymbolAddress((void**)&x2,     g_x2);
    cudaGetSymbolAddress((void**)&lx2_h,  g_lx2_h);
    cudaGetSymbolAddress((void**)&lx2_l,  g_lx2_l);
    cudaGetSymbolAddress((void**)&ffh_h,  g_ffh_h);
    cudaGetSymbolAddress((void**)&ffh_l,  g_ffh_l);
    cudaGetSymbolAddress((void**)&WoT_h,  g_WoT_h);
    cudaGetSymbolAddress((void**)&WoT_l,  g_WoT_l);
    cudaGetSymbolAddress((void**)&W1T_h,  g_W1T_h);
    cudaGetSymbolAddress((void**)&W1T_l,  g_W1T_l);
    cudaGetSymbolAddress((void**)&W2T_h,  g_W2T_h);
    cudaGetSymbolAddress((void**)&W2T_l,  g_W2T_l);

    cudaFuncSetAttribute(attn2_kernel, cudaFuncAttributeMaxDynamicSharedMemorySize, ATTN2_SMEM);
    cudaFuncSetAttribute(gemm_tf32<0>, cudaFuncAttributeMaxDynamicSharedMemorySize, GSMEM);
    cudaFuncSetAttribute(gemm_tf32<1>, cudaFuncAttributeMaxDynamicSharedMemorySize, GSMEM);
    cudaFuncSetAttribute(gemm_tf32<2>, cudaFuncAttributeMaxDynamicSharedMemorySize, GSMEM);

    // 1. LN1 -> lx hi/lo
    ln_kernel<<<M_, 256>>>(x, g1, be1, lx_h, lx_l);
    // 2. weight prep
    pack_qkv_kernel<<<(NQKV_*E_)/256, 256>>>(Wq, Wk, Wv, wqkv_h, wqkv_l);
    tsplit_kernel<<<dim3(E_/32,  E_/32),  dim3(32,8)>>>(Wo, WoT_h, WoT_l, E_,  E_);
    tsplit_kernel<<<dim3(FF_/32, E_/32),  dim3(32,8)>>>(W1, W1T_h, W1T_l, E_,  FF_);
    tsplit_kernel<<<dim3(E_/32,  FF_/32), dim3(32,8)>>>(W2, W2T_h, W2T_l, FF_, E_);
    // 3. qkv = lx @ Wqkv
    gemm_tf32<0><<<dim3(NQKV_/256, M_/128), 256, GSMEM>>>(
        lx_h, lx_l, wqkv_h, wqkv_l, qkv, nullptr, nullptr, nullptr, E_, NQKV_);
    // 4. attention -> o hi/lo
    attn2_kernel<<<dim3(S_/128, B_*H_), 256, ATTN2_SMEM>>>(qkv, o_h, o_l);
    // 5. x2 = x + o @ Wo + bo
    gemm_tf32<1><<<dim3(E_/256, M_/128), 256, GSMEM>>>(
        o_h, o_l, WoT_h, WoT_l, x2, nullptr, bo, x, E_, E_);
    // 6. LN2 -> lx2 hi/lo
    ln_kernel<<<M_, 256>>>(x2, g2, be2, lx2_h, lx2_l);
    // 7. ffh = relu(lx2 @ W1 + b1) -> hi/lo
    gemm_tf32<2><<<dim3(FF_/256, M_/128), 256, GSMEM>>>(
        lx2_h, lx2_l, W1T_h, W1T_l, ffh_h, ffh_l, bb1, nullptr, E_, FF_);
    // 8. out = x2 + ffh @ W2 + b2
    gemm_tf32<1><<<dim3(E_/256, M_/128), 256, GSMEM>>>(
        ffh_h, ffh_l, W2T_h, W2T_l, out, nullptr, bb2, x2, FF_, E_);
}

// round 7
// speedup vs baseline: 3.0020x; 1.6875x over previous
#include <cuda_runtime.h>
#include <cuda_bf16.h>
#include <math.h>
#include <stdint.h>

// Problem constants
#define B_    4
#define S_    2048
#define E_    1024
#define H_    16
#define DH_   64
#define M_    (B_*S_)      // 8192 rows
#define FF_   4096
#define NQKV_ 3072

typedef __nv_bfloat16 bf16;
typedef __nv_bfloat162 bf162;

// ---------------------------------------------------------------------------
// Scratch (static __device__ arrays)
// ---------------------------------------------------------------------------
__device__ bf16  g_lx_h [(size_t)M_*E_];
__device__ bf16  g_lx_l [(size_t)M_*E_];
__device__ bf16  g_wqkv_h[(size_t)NQKV_*E_];   // [N=3072, K=1024]
__device__ bf16  g_wqkv_l[(size_t)NQKV_*E_];
__device__ float g_qkv  [(size_t)M_*NQKV_];
__device__ bf16  g_o_h  [(size_t)M_*E_];
__device__ bf16  g_o_l  [(size_t)M_*E_];
__device__ float g_x2   [(size_t)M_*E_];
__device__ bf16  g_lx2_h[(size_t)M_*E_];
__device__ bf16  g_lx2_l[(size_t)M_*E_];
__device__ bf16  g_ffh_h[(size_t)M_*FF_];
__device__ bf16  g_ffh_l[(size_t)M_*FF_];
__device__ bf16  g_WoT_h[(size_t)E_*E_];       // [N=1024, K=1024]
__device__ bf16  g_WoT_l[(size_t)E_*E_];
__device__ bf16  g_W1T_h[(size_t)FF_*E_];      // [N=4096, K=1024]
__device__ bf16  g_W1T_l[(size_t)FF_*E_];
__device__ bf16  g_W2T_h[(size_t)E_*FF_];      // [N=1024, K=4096]
__device__ bf16  g_W2T_l[(size_t)E_*FF_];

// ---------------------------------------------------------------------------
// Helpers
// ---------------------------------------------------------------------------
static __device__ __forceinline__ float tf32_rna(float x) {
    uint32_t u;
    asm("cvt.rna.tf32.f32 %0, %1;" : "=r"(u) : "f"(x));
    return __uint_as_float(u);
}

static __device__ __forceinline__ void bsplit(float x, bf16& h, bf16& l) {
    h = __float2bfloat16_rn(x);
    l = __float2bfloat16_rn(x - __bfloat162float(h));
}

static __device__ __forceinline__ uint32_t s2u(const void* p) {
    uint32_t a;
    asm("{ .reg .u64 t; cvta.to.shared.u64 t, %1; cvt.u32.u64 %0, t; }" : "=r"(a) : "l"(p));
    return a;
}

#define CP16(dst, src) \
    asm volatile("cp.async.cg.shared.global [%0], [%1], 16;" :: "r"(dst), "l"(src))
#define CP_COMMIT() asm volatile("cp.async.commit_group;")
#define CP_WAIT1()  asm volatile("cp.async.wait_group 1;")
#define CP_WAIT0()  asm volatile("cp.async.wait_group 0;")

#define LDSM4(r0, r1, r2, r3, addr) \
    asm volatile("ldmatrix.sync.aligned.m8n8.x4.shared.b16 {%0,%1,%2,%3}, [%4];" \
                 : "=r"(r0), "=r"(r1), "=r"(r2), "=r"(r3) : "r"(addr))

#define MMA_TF32(d0, d1, d2, d3, a0, a1, a2, a3, b0, b1) \
    asm volatile("mma.sync.aligned.m16n8k8.row.col.f32.tf32.tf32.f32 " \
                 "{%0,%1,%2,%3}, {%4,%5,%6,%7}, {%8,%9}, {%0,%1,%2,%3};" \
                 : "+f"(d0), "+f"(d1), "+f"(d2), "+f"(d3) \
                 : "r"(a0), "r"(a1), "r"(a2), "r"(a3), "r"(b0), "r"(b1))

#define MMA_BF16(d0, d1, d2, d3, a0, a1, a2, a3, b0, b1) \
    asm volatile("mma.sync.aligned.m16n8k16.row.col.f32.bf16.bf16.f32 " \
                 "{%0,%1,%2,%3}, {%4,%5,%6,%7}, {%8,%9}, {%0,%1,%2,%3};" \
                 : "+f"(d0), "+f"(d1), "+f"(d2), "+f"(d3) \
                 : "r"(a0), "r"(a1), "r"(a2), "r"(a3), "r"(b0), "r"(b1))

// ---------------------------------------------------------------------------
// LayerNorm (fused bf16 hi/lo split output)
// ---------------------------------------------------------------------------
__global__ void ln_kernel(const float* __restrict__ x, const float* __restrict__ g,
                          const float* __restrict__ b,
                          bf16* __restrict__ oh, bf16* __restrict__ ol)
{
    int row = blockIdx.x;
    int t = threadIdx.x;
    const float* xr = x + (size_t)row * E_;
    float v[4];
    float s = 0.f, s2 = 0.f;
#pragma unroll
    for (int i = 0; i < 4; i++) {
        v[i] = xr[t + 256*i];
        s += v[i];
        s2 += v[i]*v[i];
    }
#pragma unroll
    for (int m = 16; m; m >>= 1) {
        s  += __shfl_xor_sync(0xffffffffu, s,  m);
        s2 += __shfl_xor_sync(0xffffffffu, s2, m);
    }
    __shared__ float sh[2][8];
    if ((t & 31) == 0) { sh[0][t>>5] = s; sh[1][t>>5] = s2; }
    __syncthreads();
    s = 0.f; s2 = 0.f;
#pragma unroll
    for (int w = 0; w < 8; w++) { s += sh[0][w]; s2 += sh[1][w]; }
    float mu  = s * (1.f/E_);
    float var = s2 * (1.f/E_) - mu*mu;
    float r = rsqrtf(var + 1e-5f);
    size_t rb = (size_t)row * E_;
#pragma unroll
    for (int i = 0; i < 4; i++) {
        int c = t + 256*i;
        float y = (v[i]-mu)*r*g[c] + b[c];
        bf16 h, l;
        bsplit(y, h, l);
        oh[rb + c] = h;
        ol[rb + c] = l;
    }
}

// ---------------------------------------------------------------------------
// Pack Wq/Wk/Wv into [N=3072, K=1024] bf16 hi/lo (K-major, head-concat cols)
// ---------------------------------------------------------------------------
__global__ void pack_qkv_kernel(const float* __restrict__ Wq, const float* __restrict__ Wk,
                                const float* __restrict__ Wv,
                                bf16* __restrict__ oh, bf16* __restrict__ ol)
{
    int idx = blockIdx.x*256 + threadIdx.x;
    int n = idx / E_;
    int e = idx - n*E_;
    const float* W = (n < 1024) ? Wq : (n < 2048 ? Wk : Wv);
    int hd = n & 1023;
    float v = W[(size_t)(hd >> 6)*(E_*DH_) + (size_t)e*DH_ + (hd & 63)];
    bf16 h, l;
    bsplit(v, h, l);
    oh[idx] = h;
    ol[idx] = l;
}

// ---------------------------------------------------------------------------
// Transpose + split: in [K,N] row-major -> out_hi/lo [N,K] bf16 row-major
// ---------------------------------------------------------------------------
__global__ void tsplit_kernel(const float* __restrict__ in, bf16* __restrict__ oh,
                              bf16* __restrict__ ol, int K, int N)
{
    __shared__ float t[32][33];
    int k0 = blockIdx.y*32, n0 = blockIdx.x*32;
    int tx = threadIdx.x, ty = threadIdx.y;
#pragma unroll
    for (int r = ty; r < 32; r += 8)
        t[r][tx] = in[(size_t)(k0+r)*N + n0+tx];
    __syncthreads();
#pragma unroll
    for (int r = ty; r < 32; r += 8) {
        float v = t[tx][r];
        bf16 h, l;
        bsplit(v, h, l);
        size_t o = (size_t)(n0+r)*K + k0+tx;
        oh[o] = h;
        ol[o] = l;
    }
}

// ---------------------------------------------------------------------------
// Split-BF16 GEMM via mma.sync.m16n8k16. CTA tile 128(M) x 256(N), 8 warps
// as 2x4, warp tile 64x64. K-chunk 64 (128B bf16 rows, XOR swizzle), 2-stage
// cp.async pipeline (96 KB/stage). B given [N,K] row-major.
// 3 passes: Ah*Bh + Ah*Bl + Al*Bh (drop lo*lo).
// EPI: 0 = plain->C(f32), 1 = +bias+res->C(f32), 2 = relu(+bias)->Ch/Cl bf16
// ---------------------------------------------------------------------------
#define STAGE_BYTES 98304        // Ah 16K | Al 16K | Bh 32K | Bl 32K
#define GSMEM (2*STAGE_BYTES)    // 196608

template<int EPI>
__global__ void __launch_bounds__(256, 1) gemm_bf16s(
    const bf16* __restrict__ Ah, const bf16* __restrict__ Al,
    const bf16* __restrict__ Bh, const bf16* __restrict__ Bl,
    float* __restrict__ C, bf16* __restrict__ Ch, bf16* __restrict__ Cl,
    const float* __restrict__ bias, const float* __restrict__ res,
    int K, int N)
{
    extern __shared__ char smc[];
    uint32_t sb = s2u(smc);
    int tid = threadIdx.x;
    int wid = tid >> 5, lane = tid & 31;
    int wm = wid >> 2, wn = wid & 3;          // 2 x 4 warp grid
    int mblk = blockIdx.y * 128, nblk = blockIdx.x * 256;

    int sub = lane >> 3, L = lane & 7;
    int rA = ((sub & 1) << 3) + L, cAadd = sub >> 1;   // A m16k16 frag
    int rB = ((sub >> 1) << 3) + L, cBadd = sub & 1;   // B two k16n8 frags

    uint32_t sAh[2], sAl[2], sBh[2], sBl[2];
#pragma unroll
    for (int b = 0; b < 2; b++) {
        uint32_t base = sb + b * STAGE_BYTES;
        sAh[b] = base;          sAl[b] = base + 16384;
        sBh[b] = base + 32768;  sBl[b] = base + 65536;
    }

    float acc[4][8][4];
#pragma unroll
    for (int mt = 0; mt < 4; mt++)
#pragma unroll
        for (int nt = 0; nt < 8; nt++)
#pragma unroll
            for (int q = 0; q < 4; q++) acc[mt][nt][q] = 0.f;

    auto load_stage = [&](int s, int b) {
        int k0 = s << 6;                                 // 64 bf16 per stage
        for (int idx = tid; idx < 1024; idx += 256) {    // A: 128 rows x 8 chunks
            int r = idx >> 3, q = idx & 7;
            uint32_t off = (uint32_t)(r*128 + ((q ^ (r & 7)) << 4));
            size_t gA = (size_t)(mblk + r) * K + k0 + q*8;
            CP16(sAh[b] + off, Ah + gA);
            CP16(sAl[b] + off, Al + gA);
        }
        for (int idx = tid; idx < 2048; idx += 256) {    // B: 256 rows x 8 chunks
            int r = idx >> 3, q = idx & 7;
            uint32_t off = (uint32_t)(r*128 + ((q ^ (r & 7)) << 4));
            size_t gB = (size_t)(nblk + r) * K + k0 + q*8;
            CP16(sBh[b] + off, Bh + gB);
            CP16(sBl[b] + off, Bl + gB);
        }
        CP_COMMIT();
    };

    const int NS = K >> 6;
    load_stage(0, 0);
    load_stage(1, 1);

    for (int i = 0; i < NS; i++) {
        int buf = i & 1;
        if (i + 2 <= NS - 1) CP_WAIT1(); else CP_WAIT0();
        __syncthreads();

#pragma unroll
        for (int ks = 0; ks < 4; ks++) {                 // 4 k16 steps
            int c0 = 2*ks;
            uint32_t Af[4][4], Bhf[4][4], Blf[4][4];
            // A-hi fragments (4 x m16k16)
#pragma unroll
            for (int mt = 0; mt < 4; mt++) {
                int row = wm*64 + mt*16 + rA;
                int ch = c0 + cAadd;
                uint32_t a = sAh[buf] + row*128 + ((ch ^ (row & 7)) << 4);
                LDSM4(Af[mt][0], Af[mt][1], Af[mt][2], Af[mt][3], a);
            }
            // B-hi fragments (4 x two-k16n8 covering 64 cols)
#pragma unroll
            for (int np = 0; np < 4; np++) {
                int row = wn*64 + np*16 + rB;
                int ch = c0 + cBadd;
                uint32_t sw = (uint32_t)(row*128 + ((ch ^ (row & 7)) << 4));
                LDSM4(Bhf[np][0], Bhf[np][1], Bhf[np][2], Bhf[np][3], sBh[buf] + sw);
            }
            // Ah * Bh
#pragma unroll
            for (int mt = 0; mt < 4; mt++)
#pragma unroll
                for (int nt = 0; nt < 8; nt++)
                    MMA_BF16(acc[mt][nt][0], acc[mt][nt][1], acc[mt][nt][2], acc[mt][nt][3],
                             Af[mt][0], Af[mt][1], Af[mt][2], Af[mt][3],
                             Bhf[nt>>1][(nt&1)*2], Bhf[nt>>1][(nt&1)*2+1]);
            // B-lo fragments, Ah * Bl
#pragma unroll
            for (int np = 0; np < 4; np++) {
                int row = wn*64 + np*16 + rB;
                int ch = c0 + cBadd;
                uint32_t sw = (uint32_t)(row*128 + ((ch ^ (row & 7)) << 4));
                LDSM4(Blf[np][0], Blf[np][1], Blf[np][2], Blf[np][3], sBl[buf] + sw);
            }
#pragma unroll
            for (int mt = 0; mt < 4; mt++)
#pragma unroll
                for (int nt = 0; nt < 8; nt++)
                    MMA_BF16(acc[mt][nt][0], acc[mt][nt][1], acc[mt][nt][2], acc[mt][nt][3],
                             Af[mt][0], Af[mt][1], Af[mt][2], Af[mt][3],
                             Blf[nt>>1][(nt&1)*2], Blf[nt>>1][(nt&1)*2+1]);
            // A-lo fragments (reuse Af), Al * Bh
#pragma unroll
            for (int mt = 0; mt < 4; mt++) {
                int row = wm*64 + mt*16 + rA;
                int ch = c0 + cAadd;
                uint32_t a = sAl[buf] + row*128 + ((ch ^ (row & 7)) << 4);
                LDSM4(Af[mt][0], Af[mt][1], Af[mt][2], Af[mt][3], a);
            }
#pragma unroll
            for (int mt = 0; mt < 4; mt++)
#pragma unroll
                for (int nt = 0; nt < 8; nt++)
                    MMA_BF16(acc[mt][nt][0], acc[mt][nt][1], acc[mt][nt][2], acc[mt][nt][3],
                             Af[mt][0], Af[mt][1], Af[mt][2], Af[mt][3],
                             Bhf[nt>>1][(nt&1)*2], Bhf[nt>>1][(nt&1)*2+1]);
        }

        __syncthreads();
        if (i + 2 < NS) load_stage(i + 2, buf);
    }

    // Epilogue
    int g = lane >> 2, tg = lane & 3;
#pragma unroll
    for (int mt = 0; mt < 4; mt++) {
#pragma unroll
        for (int nt = 0; nt < 8; nt++) {
            int row0 = mblk + wm*64 + mt*16 + g;
            int col  = nblk + wn*64 + nt*8 + 2*tg;
#pragma unroll
            for (int half = 0; half < 2; half++) {
                int row = row0 + half*8;
                float v0 = acc[mt][nt][half*2+0];
                float v1 = acc[mt][nt][half*2+1];
                size_t gi = (size_t)row * N + col;
                if (EPI >= 1) { v0 += bias[col]; v1 += bias[col+1]; }
                if (EPI == 1) {
                    float2 rv = *(const float2*)&res[gi];
                    v0 += rv.x; v1 += rv.y;
                    float2 o; o.x = v0; o.y = v1;
                    *(float2*)&C[gi] = o;
                } else if (EPI == 2) {
                    v0 = fmaxf(v0, 0.f); v1 = fmaxf(v1, 0.f);
                    bf162 hv, lv;
                    bsplit(v0, hv.x, lv.x);
                    bsplit(v1, hv.y, lv.y);
                    *(bf162*)&Ch[gi] = hv;
                    *(bf162*)&Cl[gi] = lv;
                } else {
                    float2 o; o.x = v0; o.y = v1;
                    *(float2*)&C[gi] = o;
                }
            }
        }
    }
}

// ---------------------------------------------------------------------------
// Tensor-core flash attention (single-pass tf32 mma). Validated round 5.
// Epilogue now emits bf16 hi/lo.
// ---------------------------------------------------------------------------
#define AP 68
#define ATTN2_SMEM ((128*AP + 64*AP + 64*AP) * 4)   // 69632 bytes

__global__ void __launch_bounds__(256, 2) attn2_kernel(const float* __restrict__ qkv,
                                                       bf16* __restrict__ oh,
                                                       bf16* __restrict__ ol)
{
    extern __shared__ float sm[];
    float* ps = sm;                 // [128][AP]: Q staging, then P
    float* ks = ps + 128*AP;        // [64][AP]:  K tile
    float* vT = ks + 64*AP;         // [64][AP]:  V transposed
    uint32_t ps_u = s2u(ps), ks_u = s2u(ks), vT_u = s2u(vT);

    int tid = threadIdx.x;
    int wid = tid >> 5, lane = tid & 31;
    int qt = (int)(gridDim.x - 1) - (int)blockIdx.x;   // heavy tiles first
    int b = blockIdx.y >> 4, h = blockIdx.y & 15;
    size_t rowbase = (size_t)b * S_;
    int qcol = h*64, kcol = 1024 + h*64, vcol = 2048 + h*64;

    int sub = lane >> 3, L = lane & 7;
    int rA = ((sub & 1) << 3) + L, cA = sub >> 1;
    int rB = ((sub >> 1) << 3) + L, cB = sub & 1;
    int g = lane >> 2, tg = lane & 3;

    for (int idx = tid; idx < 128*16; idx += 256) {
        int r = idx >> 4, q4 = idx & 15;
        float4 v = *(const float4*)&qkv[(rowbase + (size_t)qt*128 + r)*NQKV_ + qcol + q4*4];
        float4 w;
        w.x = tf32_rna(v.x * 0.125f); w.y = tf32_rna(v.y * 0.125f);
        w.z = tf32_rna(v.z * 0.125f); w.w = tf32_rna(v.w * 0.125f);
        *(float4*)&ps[r*AP + q4*4] = w;
    }
    __syncthreads();

    uint32_t qf[8][4];
#pragma unroll
    for (int k8 = 0; k8 < 8; k8++) {
        uint32_t a = ps_u + (uint32_t)((wid*16 + rA)*AP*4 + (2*k8 + cA)*16);
        LDSM4(qf[k8][0], qf[k8][1], qf[k8][2], qf[k8][3], a);
    }

    float m0 = -1e30f, m1 = -1e30f, l0 = 0.f, l1 = 0.f;
    float of[8][4];
#pragma unroll
    for (int nt = 0; nt < 8; nt++)
#pragma unroll
        for (int j = 0; j < 4; j++) of[nt][j] = 0.f;

    int tmax = 2*qt + 1;
    for (int t = 0; t <= tmax; t++) {
        __syncthreads();
        for (int idx = tid; idx < 64*16; idx += 256) {
            int r = idx >> 4, q4 = idx & 15;
            size_t tok = (rowbase + (size_t)t*64 + r) * NQKV_;
            float4 kv = *(const float4*)&qkv[tok + kcol + q4*4];
            float4 kw;
            kw.x = tf32_rna(kv.x); kw.y = tf32_rna(kv.y);
            kw.z = tf32_rna(kv.z); kw.w = tf32_rna(kv.w);
            *(float4*)&ks[r*AP + q4*4] = kw;
            float4 vv = *(const float4*)&qkv[tok + vcol + q4*4];
            vT[(q4*4+0)*AP + r] = tf32_rna(vv.x);
            vT[(q4*4+1)*AP + r] = tf32_rna(vv.y);
            vT[(q4*4+2)*AP + r] = tf32_rna(vv.z);
            vT[(q4*4+3)*AP + r] = tf32_rna(vv.w);
        }
        __syncthreads();

        bool active = !(t == 2*qt + 1 && wid < 4);
        if (active) {
            float s[8][4];
#pragma unroll
            for (int nt = 0; nt < 8; nt++)
#pragma unroll
                for (int j = 0; j < 4; j++) s[nt][j] = 0.f;
#pragma unroll
            for (int k8 = 0; k8 < 8; k8++) {
#pragma unroll
                for (int np = 0; np < 4; np++) {
                    uint32_t bf0, bf1, bf2, bf3;
                    uint32_t a = ks_u + (uint32_t)((np*16 + rB)*AP*4 + (2*k8 + cB)*16);
                    LDSM4(bf0, bf1, bf2, bf3, a);
                    MMA_TF32(s[np*2][0], s[np*2][1], s[np*2][2], s[np*2][3],
                             qf[k8][0], qf[k8][1], qf[k8][2], qf[k8][3], bf0, bf1);
                    MMA_TF32(s[np*2+1][0], s[np*2+1][1], s[np*2+1][2], s[np*2+1][3],
                             qf[k8][0], qf[k8][1], qf[k8][2], qf[k8][3], bf2, bf3);
                }
            }

            if (t >= 2*qt) {
                int qr0 = qt*128 + wid*16 + g;
#pragma unroll
                for (int nt = 0; nt < 8; nt++) {
                    int c0 = t*64 + nt*8 + 2*tg;
                    if (c0     > qr0)   s[nt][0] = -1e30f;
                    if (c0 + 1 > qr0)   s[nt][1] = -1e30f;
                    if (c0     > qr0+8) s[nt][2] = -1e30f;
                    if (c0 + 1 > qr0+8) s[nt][3] = -1e30f;
                }
            }

            float mm0 = -1e30f, mm1 = -1e30f;
#pragma unroll
            for (int nt = 0; nt < 8; nt++) {
                mm0 = fmaxf(mm0, fmaxf(s[nt][0], s[nt][1]));
                mm1 = fmaxf(mm1, fmaxf(s[nt][2], s[nt][3]));
            }
            mm0 = fmaxf(mm0, __shfl_xor_sync(0xffffffffu, mm0, 1));
            mm0 = fmaxf(mm0, __shfl_xor_sync(0xffffffffu, mm0, 2));
            mm1 = fmaxf(mm1, __shfl_xor_sync(0xffffffffu, mm1, 1));
            mm1 = fmaxf(mm1, __shfl_xor_sync(0xffffffffu, mm1, 2));
            float mn0 = fmaxf(m0, mm0), mn1 = fmaxf(m1, mm1);
            float a0 = expf(m0 - mn0), a1 = expf(m1 - mn1);
            float sum0 = 0.f, sum1 = 0.f;
#pragma unroll
            for (int nt = 0; nt < 8; nt++) {
                s[nt][0] = expf(s[nt][0] - mn0);
                s[nt][1] = expf(s[nt][1] - mn0);
                s[nt][2] = expf(s[nt][2] - mn1);
                s[nt][3] = expf(s[nt][3] - mn1);
                sum0 += s[nt][0] + s[nt][1];
                sum1 += s[nt][2] + s[nt][3];
            }
            sum0 += __shfl_xor_sync(0xffffffffu, sum0, 1);
            sum0 += __shfl_xor_sync(0xffffffffu, sum0, 2);
            sum1 += __shfl_xor_sync(0xffffffffu, sum1, 1);
            sum1 += __shfl_xor_sync(0xffffffffu, sum1, 2);
            l0 = l0*a0 + sum0; m0 = mn0;
            l1 = l1*a1 + sum1; m1 = mn1;
#pragma unroll
            for (int nt = 0; nt < 8; nt++) {
                of[nt][0] *= a0; of[nt][1] *= a0;
                of[nt][2] *= a1; of[nt][3] *= a1;
            }

            int pr0 = (wid*16 + g) * AP;
#pragma unroll
            for (int nt = 0; nt < 8; nt++) {
                int c = nt*8 + 2*tg;
                float2 p0; p0.x = tf32_rna(s[nt][0]); p0.y = tf32_rna(s[nt][1]);
                float2 p1; p1.x = tf32_rna(s[nt][2]); p1.y = tf32_rna(s[nt][3]);
                *(float2*)&ps[pr0 + c]        = p0;
                *(float2*)&ps[pr0 + 8*AP + c] = p1;
            }
            __syncwarp();

#pragma unroll
            for (int k8 = 0; k8 < 8; k8++) {
                uint32_t pf0, pf1, pf2, pf3;
                uint32_t pa = ps_u + (uint32_t)((wid*16 + rA)*AP*4 + (2*k8 + cA)*16);
                LDSM4(pf0, pf1, pf2, pf3, pa);
#pragma unroll
                for (int np = 0; np < 4; np++) {
                    uint32_t bf0, bf1, bf2, bf3;
                    uint32_t a = vT_u + (uint32_t)((np*16 + rB)*AP*4 + (2*k8 + cB)*16);
                    LDSM4(bf0, bf1, bf2, bf3, a);
                    MMA_TF32(of[np*2][0], of[np*2][1], of[np*2][2], of[np*2][3],
                             pf0, pf1, pf2, pf3, bf0, bf1);
                    MMA_TF32(of[np*2+1][0], of[np*2+1][1], of[np*2+1][2], of[np*2+1][3],
                             pf0, pf1, pf2, pf3, bf2, bf3);
                }
            }
        }
    }

    float inv0 = 1.f / l0, inv1 = 1.f / l1;
    size_t ro0 = rowbase + (size_t)qt*128 + wid*16 + g;
    size_t ro1 = ro0 + 8;
#pragma unroll
    for (int nt = 0; nt < 8; nt++) {
        int col = h*64 + nt*8 + 2*tg;
        float v0 = of[nt][0]*inv0, v1 = of[nt][1]*inv0;
        float v2 = of[nt][2]*inv1, v3 = of[nt][3]*inv1;
        bf162 hv0, lv0, hv1, lv1;
        bsplit(v0, hv0.x, lv0.x);
        bsplit(v1, hv0.y, lv0.y);
        bsplit(v2, hv1.x, lv1.x);
        bsplit(v3, hv1.y, lv1.y);
        *(bf162*)&oh[ro0*E_ + col] = hv0;
        *(bf162*)&ol[ro0*E_ + col] = lv0;
        *(bf162*)&oh[ro1*E_ + col] = hv1;
        *(bf162*)&ol[ro1*E_ + col] = lv1;
    }
}

// ---------------------------------------------------------------------------
// Launch
// ---------------------------------------------------------------------------
extern "C" void kernel_launch(void* const* d_in, const int* in_sizes, int n_in,
                              void* d_out, int out_size)
{
    (void)in_sizes; (void)n_in; (void)out_size;
    const float* x   = (const float*)d_in[0];
    const float* Wq  = (const float*)d_in[1];
    const float* Wk  = (const float*)d_in[2];
    const float* Wv  = (const float*)d_in[3];
    const float* Wo  = (const float*)d_in[4];
    const float* bo  = (const float*)d_in[5];
    const float* g1  = (const float*)d_in[6];
    const float* be1 = (const float*)d_in[7];
    const float* g2  = (const float*)d_in[8];
    const float* be2 = (const float*)d_in[9];
    const float* W1  = (const float*)d_in[10];
    const float* bb1 = (const float*)d_in[11];
    const float* W2  = (const float*)d_in[12];
    const float* bb2 = (const float*)d_in[13];
    float* out = (float*)d_out;

    bf16 *lx_h, *lx_l, *wqkv_h, *wqkv_l, *o_h, *o_l, *lx2_h, *lx2_l;
    bf16 *ffh_h, *ffh_l, *WoT_h, *WoT_l, *W1T_h, *W1T_l, *W2T_h, *W2T_l;
    float *qkv, *x2;
    cudaGetSymbolAddress((void**)&lx_h,   g_lx_h);
    cudaGetSymbolAddress((void**)&lx_l,   g_lx_l);
    cudaGetSymbolAddress((void**)&wqkv_h, g_wqkv_h);
    cudaGetSymbolAddress((void**)&wqkv_l, g_wqkv_l);
    cudaGetSymbolAddress((void**)&qkv,    g_qkv);
    cudaGetSymbolAddress((void**)&o_h,    g_o_h);
    cudaGetSymbolAddress((void**)&o_l,    g_o_l);
    cudaGetSymbolAddress((void**)&x2,     g_x2);
    cudaGetSymbolAddress((void**)&lx2_h,  g_lx2_h);
    cudaGetSymbolAddress((void**)&lx2_l,  g_lx2_l);
    cudaGetSymbolAddress((void**)&ffh_h,  g_ffh_h);
    cudaGetSymbolAddress((void**)&ffh_l,  g_ffh_l);
    cudaGetSymbolAddress((void**)&WoT_h,  g_WoT_h);
    cudaGetSymbolAddress((void**)&WoT_l,  g_WoT_l);
    cudaGetSymbolAddress((void**)&W1T_h,  g_W1T_h);
    cudaGetSymbolAddress((void**)&W1T_l,  g_W1T_l);
    cudaGetSymbolAddress((void**)&W2T_h,  g_W2T_h);
    cudaGetSymbolAddress((void**)&W2T_l,  g_W2T_l);

    cudaFuncSetAttribute(attn2_kernel, cudaFuncAttributeMaxDynamicSharedMemorySize, ATTN2_SMEM);
    cudaFuncSetAttribute(gemm_bf16s<0>, cudaFuncAttributeMaxDynamicSharedMemorySize, GSMEM);
    cudaFuncSetAttribute(gemm_bf16s<1>, cudaFuncAttributeMaxDynamicSharedMemorySize, GSMEM);
    cudaFuncSetAttribute(gemm_bf16s<2>, cudaFuncAttributeMaxDynamicSharedMemorySize, GSMEM);

    // 1. LN1 -> lx hi/lo (bf16)
    ln_kernel<<<M_, 256>>>(x, g1, be1, lx_h, lx_l);
    // 2. weight prep (bf16 hi/lo)
    pack_qkv_kernel<<<(NQKV_*E_)/256, 256>>>(Wq, Wk, Wv, wqkv_h, wqkv_l);
    tsplit_kernel<<<dim3(E_/32,  E_/32),  dim3(32,8)>>>(Wo, WoT_h, WoT_l, E_,  E_);
    tsplit_kernel<<<dim3(FF_/32, E_/32),  dim3(32,8)>>>(W1, W1T_h, W1T_l, E_,  FF_);
    tsplit_kernel<<<dim3(E_/32,  FF_/32), dim3(32,8)>>>(W2, W2T_h, W2T_l, FF_, E_);
    // 3. qkv = lx @ Wqkv (f32 out)
    gemm_bf16s<0><<<dim3(NQKV_/256, M_/128), 256, GSMEM>>>(
        lx_h, lx_l, wqkv_h, wqkv_l, qkv, nullptr, nullptr, nullptr, nullptr, E_, NQKV_);
    // 4. attention -> o hi/lo (bf16)
    attn2_kernel<<<dim3(S_/128, B_*H_), 256, ATTN2_SMEM>>>(qkv, o_h, o_l);
    // 5. x2 = x + o @ Wo + bo (f32 out)
    gemm_bf16s<1><<<dim3(E_/256, M_/128), 256, GSMEM>>>(
        o_h, o_l, WoT_h, WoT_l, x2, nullptr, nullptr, bo, x, E_, E_);
    // 6. LN2 -> lx2 hi/lo (bf16)
    ln_kernel<<<M_, 256>>>(x2, g2, be2, lx2_h, lx2_l);
    // 7. ffh = relu(lx2 @ W1 + b1) -> bf16 hi/lo
    gemm_bf16s<2><<<dim3(FF_/256, M_/128), 256, GSMEM>>>(
        lx2_h, lx2_l, W1T_h, W1T_l, nullptr, ffh_h, ffh_l, bb1, nullptr, E_, FF_);
    // 8. out = x2 + ffh @ W2 + b2 (f32 out)
    gemm_bf16s<1><<<dim3(E_/256, M_/128), 256, GSMEM>>>(
        ffh_h, ffh_l, W2T_h, W2T_l, out, nullptr, nullptr, bb2, x2, FF_, E_);
}

// round 8
// speedup vs baseline: 3.2649x; 1.0876x over previous
#include <cuda_runtime.h>
#include <cuda_bf16.h>
#include <cuda_fp16.h>
#include <math.h>
#include <stdint.h>

// Problem constants
#define B_    4
#define S_    2048
#define E_    1024
#define H_    16
#define DH_   64
#define M_    (B_*S_)      // 8192 rows
#define FF_   4096
#define NQKV_ 3072

typedef __nv_bfloat16 bf16;
typedef __nv_bfloat162 bf162;

// ---------------------------------------------------------------------------
// Scratch (static __device__ arrays)
// ---------------------------------------------------------------------------
__device__ bf16   g_lx_h [(size_t)M_*E_];
__device__ bf16   g_lx_l [(size_t)M_*E_];
__device__ bf16   g_wqkv_h[(size_t)NQKV_*E_];   // [N=3072, K=1024]
__device__ bf16   g_wqkv_l[(size_t)NQKV_*E_];
__device__ __half g_qkv  [(size_t)M_*NQKV_];    // fp16, q-cols pre-scaled
__device__ bf16   g_o_h  [(size_t)M_*E_];
__device__ bf16   g_o_l  [(size_t)M_*E_];
__device__ float  g_x2   [(size_t)M_*E_];
__device__ bf16   g_lx2_h[(size_t)M_*E_];
__device__ bf16   g_lx2_l[(size_t)M_*E_];
__device__ bf16   g_ffh_h[(size_t)M_*FF_];
__device__ bf16   g_ffh_l[(size_t)M_*FF_];
__device__ bf16   g_WoT_h[(size_t)E_*E_];       // [N=1024, K=1024]
__device__ bf16   g_WoT_l[(size_t)E_*E_];
__device__ bf16   g_W1T_h[(size_t)FF_*E_];      // [N=4096, K=1024]
__device__ bf16   g_W1T_l[(size_t)FF_*E_];
__device__ bf16   g_W2T_h[(size_t)E_*FF_];      // [N=1024, K=4096]
__device__ bf16   g_W2T_l[(size_t)E_*FF_];

// ---------------------------------------------------------------------------
// Helpers
// ---------------------------------------------------------------------------
static __device__ __forceinline__ void bsplit(float x, bf16& h, bf16& l) {
    h = __float2bfloat16_rn(x);
    l = __float2bfloat16_rn(x - __bfloat162float(h));
}

static __device__ __forceinline__ uint32_t s2u(const void* p) {
    uint32_t a;
    asm("{ .reg .u64 t; cvta.to.shared.u64 t, %1; cvt.u32.u64 %0, t; }" : "=r"(a) : "l"(p));
    return a;
}

#define CP16(dst, src) \
    asm volatile("cp.async.cg.shared.global [%0], [%1], 16;" :: "r"(dst), "l"(src))
#define CP_COMMIT() asm volatile("cp.async.commit_group;")
#define CP_WAIT1()  asm volatile("cp.async.wait_group 1;")
#define CP_WAIT0()  asm volatile("cp.async.wait_group 0;")

#define LDSM4(r0, r1, r2, r3, addr) \
    asm volatile("ldmatrix.sync.aligned.m8n8.x4.shared.b16 {%0,%1,%2,%3}, [%4];" \
                 : "=r"(r0), "=r"(r1), "=r"(r2), "=r"(r3) : "r"(addr))

#define MMA_BF16(d0, d1, d2, d3, a0, a1, a2, a3, b0, b1) \
    asm volatile("mma.sync.aligned.m16n8k16.row.col.f32.bf16.bf16.f32 " \
                 "{%0,%1,%2,%3}, {%4,%5,%6,%7}, {%8,%9}, {%0,%1,%2,%3};" \
                 : "+f"(d0), "+f"(d1), "+f"(d2), "+f"(d3) \
                 : "r"(a0), "r"(a1), "r"(a2), "r"(a3), "r"(b0), "r"(b1))

#define MMA_F16(d0, d1, d2, d3, a0, a1, a2, a3, b0, b1) \
    asm volatile("mma.sync.aligned.m16n8k16.row.col.f32.f16.f16.f32 " \
                 "{%0,%1,%2,%3}, {%4,%5,%6,%7}, {%8,%9}, {%0,%1,%2,%3};" \
                 : "+f"(d0), "+f"(d1), "+f"(d2), "+f"(d3) \
                 : "r"(a0), "r"(a1), "r"(a2), "r"(a3), "r"(b0), "r"(b1))

// ---------------------------------------------------------------------------
// LayerNorm (fused bf16 hi/lo split output)
// ---------------------------------------------------------------------------
__global__ void ln_kernel(const float* __restrict__ x, const float* __restrict__ g,
                          const float* __restrict__ b,
                          bf16* __restrict__ oh, bf16* __restrict__ ol)
{
    int row = blockIdx.x;
    int t = threadIdx.x;
    const float* xr = x + (size_t)row * E_;
    float v[4];
    float s = 0.f, s2 = 0.f;
#pragma unroll
    for (int i = 0; i < 4; i++) {
        v[i] = xr[t + 256*i];
        s += v[i];
        s2 += v[i]*v[i];
    }
#pragma unroll
    for (int m = 16; m; m >>= 1) {
        s  += __shfl_xor_sync(0xffffffffu, s,  m);
        s2 += __shfl_xor_sync(0xffffffffu, s2, m);
    }
    __shared__ float sh[2][8];
    if ((t & 31) == 0) { sh[0][t>>5] = s; sh[1][t>>5] = s2; }
    __syncthreads();
    s = 0.f; s2 = 0.f;
#pragma unroll
    for (int w = 0; w < 8; w++) { s += sh[0][w]; s2 += sh[1][w]; }
    float mu  = s * (1.f/E_);
    float var = s2 * (1.f/E_) - mu*mu;
    float r = rsqrtf(var + 1e-5f);
    size_t rb = (size_t)row * E_;
#pragma unroll
    for (int i = 0; i < 4; i++) {
        int c = t + 256*i;
        float y = (v[i]-mu)*r*g[c] + b[c];
        bf16 h, l;
        bsplit(y, h, l);
        oh[rb + c] = h;
        ol[rb + c] = l;
    }
}

// ---------------------------------------------------------------------------
// Pack Wq/Wk/Wv into [N=3072, K=1024] bf16 hi/lo (K-major, head-concat cols)
// ---------------------------------------------------------------------------
__global__ void pack_qkv_kernel(const float* __restrict__ Wq, const float* __restrict__ Wk,
                                const float* __restrict__ Wv,
                                bf16* __restrict__ oh, bf16* __restrict__ ol)
{
    int idx = blockIdx.x*256 + threadIdx.x;
    int n = idx / E_;
    int e = idx - n*E_;
    const float* W = (n < 1024) ? Wq : (n < 2048 ? Wk : Wv);
    int hd = n & 1023;
    float v = W[(size_t)(hd >> 6)*(E_*DH_) + (size_t)e*DH_ + (hd & 63)];
    bf16 h, l;
    bsplit(v, h, l);
    oh[idx] = h;
    ol[idx] = l;
}

// ---------------------------------------------------------------------------
// Transpose + split: in [K,N] row-major -> out_hi/lo [N,K] bf16 row-major
// ---------------------------------------------------------------------------
__global__ void tsplit_kernel(const float* __restrict__ in, bf16* __restrict__ oh,
                              bf16* __restrict__ ol, int K, int N)
{
    __shared__ float t[32][33];
    int k0 = blockIdx.y*32, n0 = blockIdx.x*32;
    int tx = threadIdx.x, ty = threadIdx.y;
#pragma unroll
    for (int r = ty; r < 32; r += 8)
        t[r][tx] = in[(size_t)(k0+r)*N + n0+tx];
    __syncthreads();
#pragma unroll
    for (int r = ty; r < 32; r += 8) {
        float v = t[tx][r];
        bf16 h, l;
        bsplit(v, h, l);
        size_t o = (size_t)(n0+r)*K + k0+tx;
        oh[o] = h;
        ol[o] = l;
    }
}

// ---------------------------------------------------------------------------
// Split-BF16 GEMM via mma.sync.m16n8k16 (validated round 7).
// EPI: 1 = +bias+res -> C(f32), 2 = relu(+bias) -> Ch/Cl bf16,
//      3 = fp16 out (q-columns, col<1024, pre-scaled by 0.125) -> Hq
// ---------------------------------------------------------------------------
#define STAGE_BYTES 98304        // Ah 16K | Al 16K | Bh 32K | Bl 32K
#define GSMEM (2*STAGE_BYTES)    // 196608

template<int EPI>
__global__ void __launch_bounds__(256, 1) gemm_bf16s(
    const bf16* __restrict__ Ah, const bf16* __restrict__ Al,
    const bf16* __restrict__ Bh, const bf16* __restrict__ Bl,
    float* __restrict__ C, bf16* __restrict__ Ch, bf16* __restrict__ Cl,
    __half* __restrict__ Hq,
    const float* __restrict__ bias, const float* __restrict__ res,
    int K, int N)
{
    extern __shared__ char smc[];
    uint32_t sb = s2u(smc);
    int tid = threadIdx.x;
    int wid = tid >> 5, lane = tid & 31;
    int wm = wid >> 2, wn = wid & 3;          // 2 x 4 warp grid
    int mblk = blockIdx.y * 128, nblk = blockIdx.x * 256;

    int sub = lane >> 3, L = lane & 7;
    int rA = ((sub & 1) << 3) + L, cAadd = sub >> 1;
    int rB = ((sub >> 1) << 3) + L, cBadd = sub & 1;

    uint32_t sAh[2], sAl[2], sBh[2], sBl[2];
#pragma unroll
    for (int b = 0; b < 2; b++) {
        uint32_t base = sb + b * STAGE_BYTES;
        sAh[b] = base;          sAl[b] = base + 16384;
        sBh[b] = base + 32768;  sBl[b] = base + 65536;
    }

    float acc[4][8][4];
#pragma unroll
    for (int mt = 0; mt < 4; mt++)
#pragma unroll
        for (int nt = 0; nt < 8; nt++)
#pragma unroll
            for (int q = 0; q < 4; q++) acc[mt][nt][q] = 0.f;

    auto load_stage = [&](int s, int b) {
        int k0 = s << 6;
        for (int idx = tid; idx < 1024; idx += 256) {
            int r = idx >> 3, q = idx & 7;
            uint32_t off = (uint32_t)(r*128 + ((q ^ (r & 7)) << 4));
            size_t gA = (size_t)(mblk + r) * K + k0 + q*8;
            CP16(sAh[b] + off, Ah + gA);
            CP16(sAl[b] + off, Al + gA);
        }
        for (int idx = tid; idx < 2048; idx += 256) {
            int r = idx >> 3, q = idx & 7;
            uint32_t off = (uint32_t)(r*128 + ((q ^ (r & 7)) << 4));
            size_t gB = (size_t)(nblk + r) * K + k0 + q*8;
            CP16(sBh[b] + off, Bh + gB);
            CP16(sBl[b] + off, Bl + gB);
        }
        CP_COMMIT();
    };

    const int NS = K >> 6;
    load_stage(0, 0);
    load_stage(1, 1);

    for (int i = 0; i < NS; i++) {
        int buf = i & 1;
        if (i + 2 <= NS - 1) CP_WAIT1(); else CP_WAIT0();
        __syncthreads();

#pragma unroll
        for (int ks = 0; ks < 4; ks++) {
            int c0 = 2*ks;
            uint32_t Af[4][4], Bhf[4][4], Blf[4][4];
#pragma unroll
            for (int mt = 0; mt < 4; mt++) {
                int row = wm*64 + mt*16 + rA;
                int ch = c0 + cAadd;
                uint32_t a = sAh[buf] + row*128 + ((ch ^ (row & 7)) << 4);
                LDSM4(Af[mt][0], Af[mt][1], Af[mt][2], Af[mt][3], a);
            }
#pragma unroll
            for (int np = 0; np < 4; np++) {
                int row = wn*64 + np*16 + rB;
                int ch = c0 + cBadd;
                uint32_t sw = (uint32_t)(row*128 + ((ch ^ (row & 7)) << 4));
                LDSM4(Bhf[np][0], Bhf[np][1], Bhf[np][2], Bhf[np][3], sBh[buf] + sw);
            }
#pragma unroll
            for (int mt = 0; mt < 4; mt++)
#pragma unroll
                for (int nt = 0; nt < 8; nt++)
                    MMA_BF16(acc[mt][nt][0], acc[mt][nt][1], acc[mt][nt][2], acc[mt][nt][3],
                             Af[mt][0], Af[mt][1], Af[mt][2], Af[mt][3],
                             Bhf[nt>>1][(nt&1)*2], Bhf[nt>>1][(nt&1)*2+1]);
#pragma unroll
            for (int np = 0; np < 4; np++) {
                int row = wn*64 + np*16 + rB;
                int ch = c0 + cBadd;
                uint32_t sw = (uint32_t)(row*128 + ((ch ^ (row & 7)) << 4));
                LDSM4(Blf[np][0], Blf[np][1], Blf[np][2], Blf[np][3], sBl[buf] + sw);
            }
#pragma unroll
            for (int mt = 0; mt < 4; mt++)
#pragma unroll
                for (int nt = 0; nt < 8; nt++)
                    MMA_BF16(acc[mt][nt][0], acc[mt][nt][1], acc[mt][nt][2], acc[mt][nt][3],
                             Af[mt][0], Af[mt][1], Af[mt][2], Af[mt][3],
                             Blf[nt>>1][(nt&1)*2], Blf[nt>>1][(nt&1)*2+1]);
#pragma unroll
            for (int mt = 0; mt < 4; mt++) {
                int row = wm*64 + mt*16 + rA;
                int ch = c0 + cAadd;
                uint32_t a = sAl[buf] + row*128 + ((ch ^ (row & 7)) << 4);
                LDSM4(Af[mt][0], Af[mt][1], Af[mt][2], Af[mt][3], a);
            }
#pragma unroll
            for (int mt = 0; mt < 4; mt++)
#pragma unroll
                for (int nt = 0; nt < 8; nt++)
                    MMA_BF16(acc[mt][nt][0], acc[mt][nt][1], acc[mt][nt][2], acc[mt][nt][3],
                             Af[mt][0], Af[mt][1], Af[mt][2], Af[mt][3],
                             Bhf[nt>>1][(nt&1)*2], Bhf[nt>>1][(nt&1)*2+1]);
        }

        __syncthreads();
        if (i + 2 < NS) load_stage(i + 2, buf);
    }

    // Epilogue
    int g = lane >> 2, tg = lane & 3;
#pragma unroll
    for (int mt = 0; mt < 4; mt++) {
#pragma unroll
        for (int nt = 0; nt < 8; nt++) {
            int row0 = mblk + wm*64 + mt*16 + g;
            int col  = nblk + wn*64 + nt*8 + 2*tg;
#pragma unroll
            for (int half = 0; half < 2; half++) {
                int row = row0 + half*8;
                float v0 = acc[mt][nt][half*2+0];
                float v1 = acc[mt][nt][half*2+1];
                size_t gi = (size_t)row * N + col;
                if (EPI == 1 || EPI == 2) { v0 += bias[col]; v1 += bias[col+1]; }
                if (EPI == 1) {
                    float2 rv = *(const float2*)&res[gi];
                    v0 += rv.x; v1 += rv.y;
                    float2 o; o.x = v0; o.y = v1;
                    *(float2*)&C[gi] = o;
                } else if (EPI == 2) {
                    v0 = fmaxf(v0, 0.f); v1 = fmaxf(v1, 0.f);
                    bf162 hv, lv;
                    bsplit(v0, hv.x, lv.x);
                    bsplit(v1, hv.y, lv.y);
                    *(bf162*)&Ch[gi] = hv;
                    *(bf162*)&Cl[gi] = lv;
                } else if (EPI == 3) {
                    float sc = (col < 1024) ? 0.125f : 1.f;   // pre-scale q cols
                    *(__half2*)&Hq[gi] = __floats2half2_rn(v0*sc, v1*sc);
                } else {
                    float2 o; o.x = v0; o.y = v1;
                    *(float2*)&C[gi] = o;
                }
            }
        }
    }
}

// ---------------------------------------------------------------------------
// FP16 tensor-core flash attention (m16n8k16; fp16 mantissa == tf32).
// Grid (16, B*H), 256 threads = 8 warps, each owns 16 query rows of the
// 128-row Q tile. qkv is fp16 with q pre-scaled by 1/sqrt(DH).
// Smem rows of 64 halfs (128B, 8 x 16B chunks) with the gemm's XOR swizzle.
// Q frags register-resident; P staged fp16 into the (warp-private) Q slab.
// ---------------------------------------------------------------------------
#define ATTN3_SMEM ((128*64 + 64*64 + 64*64) * 2)   // 32768 bytes

__global__ void __launch_bounds__(256, 2) attn3_kernel(const __half* __restrict__ qkv,
                                                       bf16* __restrict__ oh,
                                                       bf16* __restrict__ ol)
{
    extern __shared__ __half smh[];
    __half* qp = smh;               // [128][64]: Q staging, then P
    __half* ks = qp + 128*64;       // [64][64]:  K tile (rows=key, cols=d)
    __half* vT = ks + 64*64;        // [64][64]:  V transposed (rows=d, cols=key)
    uint32_t qp_u = s2u(qp), ks_u = s2u(ks), vT_u = s2u(vT);

    int tid = threadIdx.x;
    int wid = tid >> 5, lane = tid & 31;
    int qt = (int)(gridDim.x - 1) - (int)blockIdx.x;   // heavy tiles first
    int b = blockIdx.y >> 4, h = blockIdx.y & 15;
    size_t rowbase = (size_t)b * S_;
    int qcol = h*64, kcol = 1024 + h*64, vcol = 2048 + h*64;

    int sub = lane >> 3, L = lane & 7;
    int rA = ((sub & 1) << 3) + L, cA = sub >> 1;
    int rB = ((sub >> 1) << 3) + L, cB = sub & 1;
    int g = lane >> 2, tg = lane & 3;

    // ---- stage Q (pre-scaled fp16; straight swizzled copy) ----
    for (int idx = tid; idx < 1024; idx += 256) {      // 128 rows x 8 chunks
        int r = idx >> 3, q8 = idx & 7;
        int4 v = *(const int4*)&qkv[(rowbase + (size_t)qt*128 + r)*NQKV_ + qcol + q8*8];
        *(int4*)((char*)qp + r*128 + ((q8 ^ (r & 7)) << 4)) = v;
    }
    __syncthreads();

    uint32_t qf[4][4];
#pragma unroll
    for (int k4 = 0; k4 < 4; k4++) {
        int row = wid*16 + rA;
        uint32_t a = qp_u + (uint32_t)(row*128 + (((2*k4 + cA) ^ (row & 7)) << 4));
        LDSM4(qf[k4][0], qf[k4][1], qf[k4][2], qf[k4][3], a);
    }

    float m0 = -1e30f, m1 = -1e30f, l0 = 0.f, l1 = 0.f;
    float of[8][4];
#pragma unroll
    for (int nt = 0; nt < 8; nt++)
#pragma unroll
        for (int j = 0; j < 4; j++) of[nt][j] = 0.f;

    int tmax = 2*qt + 1;
    for (int t = 0; t <= tmax; t++) {
        __syncthreads();   // ks/vT consumed by all warps before overwrite
        // load K (copy) + V (scatter transpose), both fp16
        for (int idx = tid; idx < 512; idx += 256) {   // 64 rows x 8 chunks
            int r = idx >> 3, q8 = idx & 7;
            size_t tok = (rowbase + (size_t)t*64 + r) * NQKV_;
            int4 kv = *(const int4*)&qkv[tok + kcol + q8*8];
            *(int4*)((char*)ks + r*128 + ((q8 ^ (r & 7)) << 4)) = kv;
            union { int4 i4; __half hx[8]; } vv;
            vv.i4 = *(const int4*)&qkv[tok + vcol + q8*8];
#pragma unroll
            for (int j = 0; j < 8; j++) {
                int d = q8*8 + j;
                *(__half*)((char*)vT + d*128 + ((((r >> 3) ^ j) & 7) * 16) + (r & 7)*2) = vv.hx[j];
            }
        }
        __syncthreads();

        // last diagonal tile fully masks warps 0-3
        bool active = !(t == 2*qt + 1 && wid < 4);
        if (active) {
            // ---- S = Q K^T (q pre-scaled) ----
            float s[8][4];
#pragma unroll
            for (int nt = 0; nt < 8; nt++)
#pragma unroll
                for (int j = 0; j < 4; j++) s[nt][j] = 0.f;
#pragma unroll
            for (int k4 = 0; k4 < 4; k4++) {
#pragma unroll
                for (int np = 0; np < 4; np++) {
                    uint32_t bf0, bf1, bf2, bf3;
                    int row = np*16 + rB;
                    uint32_t a = ks_u + (uint32_t)(row*128 + (((2*k4 + cB) ^ (row & 7)) << 4));
                    LDSM4(bf0, bf1, bf2, bf3, a);
                    MMA_F16(s[np*2][0], s[np*2][1], s[np*2][2], s[np*2][3],
                            qf[k4][0], qf[k4][1], qf[k4][2], qf[k4][3], bf0, bf1);
                    MMA_F16(s[np*2+1][0], s[np*2+1][1], s[np*2+1][2], s[np*2+1][3],
                            qf[k4][0], qf[k4][1], qf[k4][2], qf[k4][3], bf2, bf3);
                }
            }

            // ---- causal mask (only the two diagonal tiles) ----
            if (t >= 2*qt) {
                int qr0 = qt*128 + wid*16 + g;
#pragma unroll
                for (int nt = 0; nt < 8; nt++) {
                    int c0 = t*64 + nt*8 + 2*tg;
                    if (c0     > qr0)   s[nt][0] = -1e30f;
                    if (c0 + 1 > qr0)   s[nt][1] = -1e30f;
                    if (c0     > qr0+8) s[nt][2] = -1e30f;
                    if (c0 + 1 > qr0+8) s[nt][3] = -1e30f;
                }
            }

            // ---- online softmax (rows g, g+8; quad-shuffle reductions) ----
            float mm0 = -1e30f, mm1 = -1e30f;
#pragma unroll
            for (int nt = 0; nt < 8; nt++) {
                mm0 = fmaxf(mm0, fmaxf(s[nt][0], s[nt][1]));
                mm1 = fmaxf(mm1, fmaxf(s[nt][2], s[nt][3]));
            }
            mm0 = fmaxf(mm0, __shfl_xor_sync(0xffffffffu, mm0, 1));
            mm0 = fmaxf(mm0, __shfl_xor_sync(0xffffffffu, mm0, 2));
            mm1 = fmaxf(mm1, __shfl_xor_sync(0xffffffffu, mm1, 1));
            mm1 = fmaxf(mm1, __shfl_xor_sync(0xffffffffu, mm1, 2));
            float mn0 = fmaxf(m0, mm0), mn1 = fmaxf(m1, mm1);
            float a0 = expf(m0 - mn0), a1 = expf(m1 - mn1);
            float sum0 = 0.f, sum1 = 0.f;
#pragma unroll
            for (int nt = 0; nt < 8; nt++) {
                s[nt][0] = expf(s[nt][0] - mn0);
                s[nt][1] = expf(s[nt][1] - mn0);
                s[nt][2] = expf(s[nt][2] - mn1);
                s[nt][3] = expf(s[nt][3] - mn1);
                sum0 += s[nt][0] + s[nt][1];
                sum1 += s[nt][2] + s[nt][3];
            }
            sum0 += __shfl_xor_sync(0xffffffffu, sum0, 1);
            sum0 += __shfl_xor_sync(0xffffffffu, sum0, 2);
            sum1 += __shfl_xor_sync(0xffffffffu, sum1, 1);
            sum1 += __shfl_xor_sync(0xffffffffu, sum1, 2);
            l0 = l0*a0 + sum0; m0 = mn0;
            l1 = l1*a1 + sum1; m1 = mn1;
#pragma unroll
            for (int nt = 0; nt < 8; nt++) {
                of[nt][0] *= a0; of[nt][1] *= a0;
                of[nt][2] *= a1; of[nt][3] *= a1;
            }

            // ---- stage P fp16 into own 16-row slab of qp ----
            int pr0 = wid*16 + g;
            int pr1 = pr0 + 8;
#pragma unroll
            for (int nt = 0; nt < 8; nt++) {
                uint32_t a0p = qp_u + (uint32_t)(pr0*128 + (((nt) ^ (pr0 & 7)) << 4) + 4*tg);
                uint32_t a1p = qp_u + (uint32_t)(pr1*128 + (((nt) ^ (pr1 & 7)) << 4) + 4*tg);
                __half2 p0 = __floats2half2_rn(s[nt][0], s[nt][1]);
                __half2 p1 = __floats2half2_rn(s[nt][2], s[nt][3]);
                asm volatile("st.shared.b32 [%0], %1;" :: "r"(a0p), "r"(*(uint32_t*)&p0));
                asm volatile("st.shared.b32 [%0], %1;" :: "r"(a1p), "r"(*(uint32_t*)&p1));
            }
            __syncwarp();

            // ---- O += P V ----
#pragma unroll
            for (int k4 = 0; k4 < 4; k4++) {
                uint32_t pf0, pf1, pf2, pf3;
                int prow = wid*16 + rA;
                uint32_t pa = qp_u + (uint32_t)(prow*128 + (((2*k4 + cA) ^ (prow & 7)) << 4));
                LDSM4(pf0, pf1, pf2, pf3, pa);
#pragma unroll
                for (int np = 0; np < 4; np++) {
                    uint32_t bf0, bf1, bf2, bf3;
                    int row = np*16 + rB;
                    uint32_t a = vT_u + (uint32_t)(row*128 + (((2*k4 + cB) ^ (row & 7)) << 4));
                    LDSM4(bf0, bf1, bf2, bf3, a);
                    MMA_F16(of[np*2][0], of[np*2][1], of[np*2][2], of[np*2][3],
                            pf0, pf1, pf2, pf3, bf0, bf1);
                    MMA_F16(of[np*2+1][0], of[np*2+1][1], of[np*2+1][2], of[np*2+1][3],
                            pf0, pf1, pf2, pf3, bf2, bf3);
                }
            }
        }
    }

    // ---- epilogue: normalize, bf16 hi/lo split, head-concat layout ----
    float inv0 = 1.f / l0, inv1 = 1.f / l1;
    size_t ro0 = rowbase + (size_t)qt*128 + wid*16 + g;
    size_t ro1 = ro0 + 8;
#pragma unroll
    for (int nt = 0; nt < 8; nt++) {
        int col = h*64 + nt*8 + 2*tg;
        float v0 = of[nt][0]*inv0, v1 = of[nt][1]*inv0;
        float v2 = of[nt][2]*inv1, v3 = of[nt][3]*inv1;
        bf162 hv0, lv0, hv1, lv1;
        bsplit(v0, hv0.x, lv0.x);
        bsplit(v1, hv0.y, lv0.y);
        bsplit(v2, hv1.x, lv1.x);
        bsplit(v3, hv1.y, lv1.y);
        *(bf162*)&oh[ro0*E_ + col] = hv0;
        *(bf162*)&ol[ro0*E_ + col] = lv0;
        *(bf162*)&oh[ro1*E_ + col] = hv1;
        *(bf162*)&ol[ro1*E_ + col] = lv1;
    }
}

// ---------------------------------------------------------------------------
// Launch
// ---------------------------------------------------------------------------
extern "C" void kernel_launch(void* const* d_in, const int* in_sizes, int n_in,
                              void* d_out, int out_size)
{
    (void)in_sizes; (void)n_in; (void)out_size;
    const float* x   = (const float*)d_in[0];
    const float* Wq  = (const float*)d_in[1];
    const float* Wk  = (const float*)d_in[2];
    const float* Wv  = (const float*)d_in[3];
    const float* Wo  = (const float*)d_in[4];
    const float* bo  = (const float*)d_in[5];
    const float* g1  = (const float*)d_in[6];
    const float* be1 = (const float*)d_in[7];
    const float* g2  = (const float*)d_in[8];
    const float* be2 = (const float*)d_in[9];
    const float* W1  = (const float*)d_in[10];
    const float* bb1 = (const float*)d_in[11];
    const float* W2  = (const float*)d_in[12];
    const float* bb2 = (const float*)d_in[13];
    float* out = (float*)d_out;

    bf16 *lx_h, *lx_l, *wqkv_h, *wqkv_l, *o_h, *o_l, *lx2_h, *lx2_l;
    bf16 *ffh_h, *ffh_l, *WoT_h, *WoT_l, *W1T_h, *W1T_l, *W2T_h, *W2T_l;
    __half *qkv;
    float *x2;
    cudaGetSymbolAddress((void**)&lx_h,   g_lx_h);
    cudaGetSymbolAddress((void**)&lx_l,   g_lx_l);
    cudaGetSymbolAddress((void**)&wqkv_h, g_wqkv_h);
    cudaGetSymbolAddress((void**)&wqkv_l, g_wqkv_l);
    cudaGetSymbolAddress((void**)&qkv,    g_qkv);
    cudaGetSymbolAddress((void**)&o_h,    g_o_h);
    cudaGetSymbolAddress((void**)&o_l,    g_o_l);
    cudaGetSymbolAddress((void**)&x2,     g_x2);
    cudaGetSymbolAddress((void**)&lx2_h,  g_lx2_h);
    cudaGetSymbolAddress((void**)&lx2_l,  g_lx2_l);
    cudaGetSymbolAddress((void**)&ffh_h,  g_ffh_h);
    cudaGetSymbolAddress((void**)&ffh_l,  g_ffh_l);
    cudaGetSymbolAddress((void**)&WoT_h,  g_WoT_h);
    cudaGetSymbolAddress((void**)&WoT_l,  g_WoT_l);
    cudaGetSymbolAddress((void**)&W1T_h,  g_W1T_h);
    cudaGetSymbolAddress((void**)&W1T_l,  g_W1T_l);
    cudaGetSymbolAddress((void**)&W2T_h,  g_W2T_h);
    cudaGetSymbolAddress((void**)&W2T_l,  g_W2T_l);

    cudaFuncSetAttribute(attn3_kernel, cudaFuncAttributeMaxDynamicSharedMemorySize, ATTN3_SMEM);
    cudaFuncSetAttribute(gemm_bf16s<1>, cudaFuncAttributeMaxDynamicSharedMemorySize, GSMEM);
    cudaFuncSetAttribute(gemm_bf16s<2>, cudaFuncAttributeMaxDynamicSharedMemorySize, GSMEM);
    cudaFuncSetAttribute(gemm_bf16s<3>, cudaFuncAttributeMaxDynamicSharedMemorySize, GSMEM);

    // 1. LN1 -> lx hi/lo (bf16)
    ln_kernel<<<M_, 256>>>(x, g1, be1, lx_h, lx_l);
    // 2. weight prep (bf16 hi/lo)
    pack_qkv_kernel<<<(NQKV_*E_)/256, 256>>>(Wq, Wk, Wv, wqkv_h, wqkv_l);
    tsplit_kernel<<<dim3(E_/32,  E_/32),  dim3(32,8)>>>(Wo, WoT_h, WoT_l, E_,  E_);
    tsplit_kernel<<<dim3(FF_/32, E_/32),  dim3(32,8)>>>(W1, W1T_h, W1T_l, E_,  FF_);
    tsplit_kernel<<<dim3(E_/32,  FF_/32), dim3(32,8)>>>(W2, W2T_h, W2T_l, FF_, E_);
    // 3. qkv = lx @ Wqkv  -> fp16 (q cols pre-scaled by 0.125)
    gemm_bf16s<3><<<dim3(NQKV_/256, M_/128), 256, GSMEM>>>(
        lx_h, lx_l, wqkv_h, wqkv_l, nullptr, nullptr, nullptr, qkv, nullptr, nullptr, E_, NQKV_);
    // 4. attention -> o hi/lo (bf16), fp16 tensor cores
    attn3_kernel<<<dim3(S_/128, B_*H_), 256, ATTN3_SMEM>>>(qkv, o_h, o_l);
    // 5. x2 = x + o @ Wo + bo (f32 out)
    gemm_bf16s<1><<<dim3(E_/256, M_/128), 256, GSMEM>>>(
        o_h, o_l, WoT_h, WoT_l, x2, nullptr, nullptr, nullptr, bo, x, E_, E_);
    // 6. LN2 -> lx2 hi/lo (bf16)
    ln_kernel<<<M_, 256>>>(x2, g2, be2, lx2_h, lx2_l);
    // 7. ffh = relu(lx2 @ W1 + b1) -> bf16 hi/lo
    gemm_bf16s<2><<<dim3(FF_/256, M_/128), 256, GSMEM>>>(
        lx2_h, lx2_l, W1T_h, W1T_l, nullptr, ffh_h, ffh_l, nullptr, bb1, nullptr, E_, FF_);
    // 8. out = x2 + ffh @ W2 + b2 (f32 out)
    gemm_bf16s<1><<<dim3(E_/256, M_/128), 256, GSMEM>>>(
        ffh_h, ffh_l, W2T_h, W2T_l, out, nullptr, nullptr, nullptr, bb2, x2, FF_, E_);
}

// round 9
// speedup vs baseline: 3.4855x; 1.0676x over previous
#include <cuda_runtime.h>
#include <cuda_bf16.h>
#include <cuda_fp16.h>
#include <math.h>
#include <stdint.h>

// Problem constants
#define B_    4
#define S_    2048
#define E_    1024
#define H_    16
#define DH_   64
#define M_    (B_*S_)      // 8192 rows
#define FF_   4096
#define NQKV_ 3072

typedef __nv_bfloat16 bf16;
typedef __nv_bfloat162 bf162;

// ---------------------------------------------------------------------------
// Scratch (static __device__ arrays)
// ---------------------------------------------------------------------------
__device__ __half g_lx_h [(size_t)M_*E_];       // fp16 hi
__device__ __half g_lx_l [(size_t)M_*E_];       // fp16 lo
__device__ __half g_wqkv [(size_t)NQKV_*E_];    // [N=3072, K=1024] single fp16
__device__ __half g_qkv  [(size_t)M_*NQKV_];    // fp16, q-cols pre-scaled
__device__ bf16   g_o_h  [(size_t)M_*E_];
__device__ bf16   g_o_l  [(size_t)M_*E_];
__device__ float  g_x2   [(size_t)M_*E_];
__device__ bf16   g_lx2_h[(size_t)M_*E_];
__device__ bf16   g_lx2_l[(size_t)M_*E_];
__device__ bf16   g_ffh_h[(size_t)M_*FF_];
__device__ bf16   g_ffh_l[(size_t)M_*FF_];
__device__ bf16   g_WoT_h[(size_t)E_*E_];       // [N=1024, K=1024]
__device__ bf16   g_WoT_l[(size_t)E_*E_];
__device__ bf16   g_W1T_h[(size_t)FF_*E_];      // [N=4096, K=1024]
__device__ bf16   g_W1T_l[(size_t)FF_*E_];
__device__ bf16   g_W2T_h[(size_t)E_*FF_];      // [N=1024, K=4096]
__device__ bf16   g_W2T_l[(size_t)E_*FF_];

// ---------------------------------------------------------------------------
// Helpers
// ---------------------------------------------------------------------------
static __device__ __forceinline__ void bsplit(float x, bf16& h, bf16& l) {
    h = __float2bfloat16_rn(x);
    l = __float2bfloat16_rn(x - __bfloat162float(h));
}

static __device__ __forceinline__ void hsplit(float x, __half& h, __half& l) {
    h = __float2half_rn(x);
    l = __float2half_rn(x - __half2float(h));
}

static __device__ __forceinline__ uint32_t s2u(const void* p) {
    uint32_t a;
    asm("{ .reg .u64 t; cvta.to.shared.u64 t, %1; cvt.u32.u64 %0, t; }" : "=r"(a) : "l"(p));
    return a;
}

#define CP16(dst, src) \
    asm volatile("cp.async.cg.shared.global [%0], [%1], 16;" :: "r"(dst), "l"(src))
#define CP_COMMIT() asm volatile("cp.async.commit_group;")
#define CP_WAIT2()  asm volatile("cp.async.wait_group 2;")
#define CP_WAIT1()  asm volatile("cp.async.wait_group 1;")
#define CP_WAIT0()  asm volatile("cp.async.wait_group 0;")

#define LDSM4(r0, r1, r2, r3, addr) \
    asm volatile("ldmatrix.sync.aligned.m8n8.x4.shared.b16 {%0,%1,%2,%3}, [%4];" \
                 : "=r"(r0), "=r"(r1), "=r"(r2), "=r"(r3) : "r"(addr))

#define MMA_BF16(d0, d1, d2, d3, a0, a1, a2, a3, b0, b1) \
    asm volatile("mma.sync.aligned.m16n8k16.row.col.f32.bf16.bf16.f32 " \
                 "{%0,%1,%2,%3}, {%4,%5,%6,%7}, {%8,%9}, {%0,%1,%2,%3};" \
                 : "+f"(d0), "+f"(d1), "+f"(d2), "+f"(d3) \
                 : "r"(a0), "r"(a1), "r"(a2), "r"(a3), "r"(b0), "r"(b1))

#define MMA_F16(d0, d1, d2, d3, a0, a1, a2, a3, b0, b1) \
    asm volatile("mma.sync.aligned.m16n8k16.row.col.f32.f16.f16.f32 " \
                 "{%0,%1,%2,%3}, {%4,%5,%6,%7}, {%8,%9}, {%0,%1,%2,%3};" \
                 : "+f"(d0), "+f"(d1), "+f"(d2), "+f"(d3) \
                 : "r"(a0), "r"(a1), "r"(a2), "r"(a3), "r"(b0), "r"(b1))

// ---------------------------------------------------------------------------
// LayerNorm variants: bf16 hi/lo (LN2) and fp16 hi/lo (LN1 -> QKV gemm)
// ---------------------------------------------------------------------------
template<int F16>
__global__ void ln_kernel(const float* __restrict__ x, const float* __restrict__ g,
                          const float* __restrict__ b,
                          void* __restrict__ oh_, void* __restrict__ ol_)
{
    int row = blockIdx.x;
    int t = threadIdx.x;
    const float* xr = x + (size_t)row * E_;
    float v[4];
    float s = 0.f, s2 = 0.f;
#pragma unroll
    for (int i = 0; i < 4; i++) {
        v[i] = xr[t + 256*i];
        s += v[i];
        s2 += v[i]*v[i];
    }
#pragma unroll
    for (int m = 16; m; m >>= 1) {
        s  += __shfl_xor_sync(0xffffffffu, s,  m);
        s2 += __shfl_xor_sync(0xffffffffu, s2, m);
    }
    __shared__ float sh[2][8];
    if ((t & 31) == 0) { sh[0][t>>5] = s; sh[1][t>>5] = s2; }
    __syncthreads();
    s = 0.f; s2 = 0.f;
#pragma unroll
    for (int w = 0; w < 8; w++) { s += sh[0][w]; s2 += sh[1][w]; }
    float mu  = s * (1.f/E_);
    float var = s2 * (1.f/E_) - mu*mu;
    float r = rsqrtf(var + 1e-5f);
    size_t rb = (size_t)row * E_;
#pragma unroll
    for (int i = 0; i < 4; i++) {
        int c = t + 256*i;
        float y = (v[i]-mu)*r*g[c] + b[c];
        if (F16) {
            __half h, l;
            hsplit(y, h, l);
            ((__half*)oh_)[rb + c] = h;
            ((__half*)ol_)[rb + c] = l;
        } else {
            bf16 h, l;
            bsplit(y, h, l);
            ((bf16*)oh_)[rb + c] = h;
            ((bf16*)ol_)[rb + c] = l;
        }
    }
}

// ---------------------------------------------------------------------------
// Pack Wq/Wk/Wv into [N=3072, K=1024] single fp16 (K-major, head-concat cols)
// ---------------------------------------------------------------------------
__global__ void pack_qkv_kernel(const float* __restrict__ Wq, const float* __restrict__ Wk,
                                const float* __restrict__ Wv, __half* __restrict__ ow)
{
    int idx = blockIdx.x*256 + threadIdx.x;
    int n = idx / E_;
    int e = idx - n*E_;
    const float* W = (n < 1024) ? Wq : (n < 2048 ? Wk : Wv);
    int hd = n & 1023;
    float v = W[(size_t)(hd >> 6)*(E_*DH_) + (size_t)e*DH_ + (hd & 63)];
    ow[idx] = __float2half_rn(v);
}

// ---------------------------------------------------------------------------
// Transpose + split: in [K,N] row-major -> out_hi/lo [N,K] bf16 row-major
// ---------------------------------------------------------------------------
__global__ void tsplit_kernel(const float* __restrict__ in, bf16* __restrict__ oh,
                              bf16* __restrict__ ol, int K, int N)
{
    __shared__ float t[32][33];
    int k0 = blockIdx.y*32, n0 = blockIdx.x*32;
    int tx = threadIdx.x, ty = threadIdx.y;
#pragma unroll
    for (int r = ty; r < 32; r += 8)
        t[r][tx] = in[(size_t)(k0+r)*N + n0+tx];
    __syncthreads();
#pragma unroll
    for (int r = ty; r < 32; r += 8) {
        float v = t[tx][r];
        bf16 h, l;
        bsplit(v, h, l);
        size_t o = (size_t)(n0+r)*K + k0+tx;
        oh[o] = h;
        ol[o] = l;
    }
}

// ---------------------------------------------------------------------------
// QKV GEMM: fp16 asymmetric 2-pass (A = Ah+Al fp16, B single fp16).
// CTA 128x256, warp 64x64, K-chunk 64, 3-stage pipeline (64 KB/stage).
// Output fp16, q columns (col<1024) pre-scaled by 0.125.
// ---------------------------------------------------------------------------
#define QSTAGE 65536             // Ah 16K | Al 16K | B 32K
#define QSMEM (3*QSTAGE)         // 196608

__global__ void __launch_bounds__(256, 1) gemm_qkv_f16(
    const __half* __restrict__ Ah, const __half* __restrict__ Al,
    const __half* __restrict__ Bw, __half* __restrict__ Hq,
    int K, int N)
{
    extern __shared__ char smc[];
    uint32_t sb = s2u(smc);
    int tid = threadIdx.x;
    int wid = tid >> 5, lane = tid & 31;
    int wm = wid >> 2, wn = wid & 3;
    int mblk = blockIdx.y * 128, nblk = blockIdx.x * 256;

    int sub = lane >> 3, L = lane & 7;
    int rA = ((sub & 1) << 3) + L, cAadd = sub >> 1;
    int rB = ((sub >> 1) << 3) + L, cBadd = sub & 1;

    uint32_t sAh[3], sAl[3], sB[3];
#pragma unroll
    for (int b = 0; b < 3; b++) {
        uint32_t base = sb + b * QSTAGE;
        sAh[b] = base;  sAl[b] = base + 16384;  sB[b] = base + 32768;
    }

    float acc[4][8][4];
#pragma unroll
    for (int mt = 0; mt < 4; mt++)
#pragma unroll
        for (int nt = 0; nt < 8; nt++)
#pragma unroll
            for (int q = 0; q < 4; q++) acc[mt][nt][q] = 0.f;

    auto load_stage = [&](int s, int b) {
        int k0 = s << 6;
        for (int idx = tid; idx < 1024; idx += 256) {
            int r = idx >> 3, q = idx & 7;
            uint32_t off = (uint32_t)(r*128 + ((q ^ (r & 7)) << 4));
            size_t gA = (size_t)(mblk + r) * K + k0 + q*8;
            CP16(sAh[b] + off, Ah + gA);
            CP16(sAl[b] + off, Al + gA);
        }
        for (int idx = tid; idx < 2048; idx += 256) {
            int r = idx >> 3, q = idx & 7;
            uint32_t off = (uint32_t)(r*128 + ((q ^ (r & 7)) << 4));
            CP16(sB[b] + off, Bw + (size_t)(nblk + r) * K + k0 + q*8);
        }
        CP_COMMIT();
    };

    const int NS = K >> 6;
    load_stage(0, 0);
    load_stage(1, 1);
    load_stage(2, 2);

    int buf = 0;
    for (int i = 0; i < NS; i++) {
        if (i + 3 <= NS - 1)      CP_WAIT2();
        else if (i + 2 <= NS - 1) CP_WAIT1();
        else                      CP_WAIT0();
        __syncthreads();

#pragma unroll
        for (int ks = 0; ks < 4; ks++) {
            int c0 = 2*ks;
            uint32_t Af[4][4], Bf[4][4];
#pragma unroll
            for (int mt = 0; mt < 4; mt++) {
                int row = wm*64 + mt*16 + rA;
                int ch = c0 + cAadd;
                uint32_t a = sAh[buf] + row*128 + ((ch ^ (row & 7)) << 4);
                LDSM4(Af[mt][0], Af[mt][1], Af[mt][2], Af[mt][3], a);
            }
#pragma unroll
            for (int np = 0; np < 4; np++) {
                int row = wn*64 + np*16 + rB;
                int ch = c0 + cBadd;
                uint32_t sw = (uint32_t)(row*128 + ((ch ^ (row & 7)) << 4));
                LDSM4(Bf[np][0], Bf[np][1], Bf[np][2], Bf[np][3], sB[buf] + sw);
            }
#pragma unroll
            for (int mt = 0; mt < 4; mt++)
#pragma unroll
                for (int nt = 0; nt < 8; nt++)
                    MMA_F16(acc[mt][nt][0], acc[mt][nt][1], acc[mt][nt][2], acc[mt][nt][3],
                            Af[mt][0], Af[mt][1], Af[mt][2], Af[mt][3],
                            Bf[nt>>1][(nt&1)*2], Bf[nt>>1][(nt&1)*2+1]);
#pragma unroll
            for (int mt = 0; mt < 4; mt++) {
                int row = wm*64 + mt*16 + rA;
                int ch = c0 + cAadd;
                uint32_t a = sAl[buf] + row*128 + ((ch ^ (row & 7)) << 4);
                LDSM4(Af[mt][0], Af[mt][1], Af[mt][2], Af[mt][3], a);
            }
#pragma unroll
            for (int mt = 0; mt < 4; mt++)
#pragma unroll
                for (int nt = 0; nt < 8; nt++)
                    MMA_F16(acc[mt][nt][0], acc[mt][nt][1], acc[mt][nt][2], acc[mt][nt][3],
                            Af[mt][0], Af[mt][1], Af[mt][2], Af[mt][3],
                            Bf[nt>>1][(nt&1)*2], Bf[nt>>1][(nt&1)*2+1]);
        }

        __syncthreads();
        if (i + 3 < NS) load_stage(i + 3, buf);
        buf = (buf == 2) ? 0 : buf + 1;
    }

    // Epilogue: fp16 out, q-cols pre-scaled
    int g = lane >> 2, tg = lane & 3;
#pragma unroll
    for (int mt = 0; mt < 4; mt++) {
#pragma unroll
        for (int nt = 0; nt < 8; nt++) {
            int row0 = mblk + wm*64 + mt*16 + g;
            int col  = nblk + wn*64 + nt*8 + 2*tg;
            float sc = (col < 1024) ? 0.125f : 1.f;
#pragma unroll
            for (int half = 0; half < 2; half++) {
                int row = row0 + half*8;
                float v0 = acc[mt][nt][half*2+0] * sc;
                float v1 = acc[mt][nt][half*2+1] * sc;
                *(__half2*)&Hq[(size_t)row * N + col] = __floats2half2_rn(v0, v1);
            }
        }
    }
}

// ---------------------------------------------------------------------------
// Split-BF16 GEMM via mma.sync.m16n8k16 (validated rounds 7-8).
// EPI: 1 = +bias+res -> C(f32), 2 = relu(+bias) -> Ch/Cl bf16
// ---------------------------------------------------------------------------
#define STAGE_BYTES 98304        // Ah 16K | Al 16K | Bh 32K | Bl 32K
#define GSMEM (2*STAGE_BYTES)    // 196608

template<int EPI>
__global__ void __launch_bounds__(256, 1) gemm_bf16s(
    const bf16* __restrict__ Ah, const bf16* __restrict__ Al,
    const bf16* __restrict__ Bh, const bf16* __restrict__ Bl,
    float* __restrict__ C, bf16* __restrict__ Ch, bf16* __restrict__ Cl,
    const float* __restrict__ bias, const float* __restrict__ res,
    int K, int N)
{
    extern __shared__ char smc[];
    uint32_t sb = s2u(smc);
    int tid = threadIdx.x;
    int wid = tid >> 5, lane = tid & 31;
    int wm = wid >> 2, wn = wid & 3;
    int mblk = blockIdx.y * 128, nblk = blockIdx.x * 256;

    int sub = lane >> 3, L = lane & 7;
    int rA = ((sub & 1) << 3) + L, cAadd = sub >> 1;
    int rB = ((sub >> 1) << 3) + L, cBadd = sub & 1;

    uint32_t sAh[2], sAl[2], sBh[2], sBl[2];
#pragma unroll
    for (int b = 0; b < 2; b++) {
        uint32_t base = sb + b * STAGE_BYTES;
        sAh[b] = base;          sAl[b] = base + 16384;
        sBh[b] = base + 32768;  sBl[b] = base + 65536;
    }

    float acc[4][8][4];
#pragma unroll
    for (int mt = 0; mt < 4; mt++)
#pragma unroll
        for (int nt = 0; nt < 8; nt++)
#pragma unroll
            for (int q = 0; q < 4; q++) acc[mt][nt][q] = 0.f;

    auto load_stage = [&](int s, int b) {
        int k0 = s << 6;
        for (int idx = tid; idx < 1024; idx += 256) {
            int r = idx >> 3, q = idx & 7;
            uint32_t off = (uint32_t)(r*128 + ((q ^ (r & 7)) << 4));
            size_t gA = (size_t)(mblk + r) * K + k0 + q*8;
            CP16(sAh[b] + off, Ah + gA);
            CP16(sAl[b] + off, Al + gA);
        }
        for (int idx = tid; idx < 2048; idx += 256) {
            int r = idx >> 3, q = idx & 7;
            uint32_t off = (uint32_t)(r*128 + ((q ^ (r & 7)) << 4));
            size_t gB = (size_t)(nblk + r) * K + k0 + q*8;
            CP16(sBh[b] + off, Bh + gB);
            CP16(sBl[b] + off, Bl + gB);
        }
        CP_COMMIT();
    };

    const int NS = K >> 6;
    load_stage(0, 0);
    load_stage(1, 1);

    for (int i = 0; i < NS; i++) {
        int buf = i & 1;
        if (i + 2 <= NS - 1) CP_WAIT1(); else CP_WAIT0();
        __syncthreads();

#pragma unroll
        for (int ks = 0; ks < 4; ks++) {
            int c0 = 2*ks;
            uint32_t Af[4][4], Bhf[4][4], Blf[4][4];
#pragma unroll
            for (int mt = 0; mt < 4; mt++) {
                int row = wm*64 + mt*16 + rA;
                int ch = c0 + cAadd;
                uint32_t a = sAh[buf] + row*128 + ((ch ^ (row & 7)) << 4);
                LDSM4(Af[mt][0], Af[mt][1], Af[mt][2], Af[mt][3], a);
            }
#pragma unroll
            for (int np = 0; np < 4; np++) {
                int row = wn*64 + np*16 + rB;
                int ch = c0 + cBadd;
                uint32_t sw = (uint32_t)(row*128 + ((ch ^ (row & 7)) << 4));
                LDSM4(Bhf[np][0], Bhf[np][1], Bhf[np][2], Bhf[np][3], sBh[buf] + sw);
            }
#pragma unroll
            for (int mt = 0; mt < 4; mt++)
#pragma unroll
                for (int nt = 0; nt < 8; nt++)
                    MMA_BF16(acc[mt][nt][0], acc[mt][nt][1], acc[mt][nt][2], acc[mt][nt][3],
                             Af[mt][0], Af[mt][1], Af[mt][2], Af[mt][3],
                             Bhf[nt>>1][(nt&1)*2], Bhf[nt>>1][(nt&1)*2+1]);
#pragma unroll
            for (int np = 0; np < 4; np++) {
                int row = wn*64 + np*16 + rB;
                int ch = c0 + cBadd;
                uint32_t sw = (uint32_t)(row*128 + ((ch ^ (row & 7)) << 4));
                LDSM4(Blf[np][0], Blf[np][1], Blf[np][2], Blf[np][3], sBl[buf] + sw);
            }
#pragma unroll
            for (int mt = 0; mt < 4; mt++)
#pragma unroll
                for (int nt = 0; nt < 8; nt++)
                    MMA_BF16(acc[mt][nt][0], acc[mt][nt][1], acc[mt][nt][2], acc[mt][nt][3],
                             Af[mt][0], Af[mt][1], Af[mt][2], Af[mt][3],
                             Blf[nt>>1][(nt&1)*2], Blf[nt>>1][(nt&1)*2+1]);
#pragma unroll
            for (int mt = 0; mt < 4; mt++) {
                int row = wm*64 + mt*16 + rA;
                int ch = c0 + cAadd;
                uint32_t a = sAl[buf] + row*128 + ((ch ^ (row & 7)) << 4);
                LDSM4(Af[mt][0], Af[mt][1], Af[mt][2], Af[mt][3], a);
            }
#pragma unroll
            for (int mt = 0; mt < 4; mt++)
#pragma unroll
                for (int nt = 0; nt < 8; nt++)
                    MMA_BF16(acc[mt][nt][0], acc[mt][nt][1], acc[mt][nt][2], acc[mt][nt][3],
                             Af[mt][0], Af[mt][1], Af[mt][2], Af[mt][3],
                             Bhf[nt>>1][(nt&1)*2], Bhf[nt>>1][(nt&1)*2+1]);
        }

        __syncthreads();
        if (i + 2 < NS) load_stage(i + 2, buf);
    }

    // Epilogue
    int g = lane >> 2, tg = lane & 3;
#pragma unroll
    for (int mt = 0; mt < 4; mt++) {
#pragma unroll
        for (int nt = 0; nt < 8; nt++) {
            int row0 = mblk + wm*64 + mt*16 + g;
            int col  = nblk + wn*64 + nt*8 + 2*tg;
#pragma unroll
            for (int half = 0; half < 2; half++) {
                int row = row0 + half*8;
                float v0 = acc[mt][nt][half*2+0] + bias[col];
                float v1 = acc[mt][nt][half*2+1] + bias[col+1];
                size_t gi = (size_t)row * N + col;
                if (EPI == 1) {
                    float2 rv = *(const float2*)&res[gi];
                    v0 += rv.x; v1 += rv.y;
                    float2 o; o.x = v0; o.y = v1;
                    *(float2*)&C[gi] = o;
                } else {
                    v0 = fmaxf(v0, 0.f); v1 = fmaxf(v1, 0.f);
                    bf162 hv, lv;
                    bsplit(v0, hv.x, lv.x);
                    bsplit(v1, hv.y, lv.y);
                    *(bf162*)&Ch[gi] = hv;
                    *(bf162*)&Cl[gi] = lv;
                }
            }
        }
    }
}

// ---------------------------------------------------------------------------
// FP16 tensor-core flash attention (validated round 8).
// ---------------------------------------------------------------------------
#define ATTN3_SMEM ((128*64 + 64*64 + 64*64) * 2)   // 32768 bytes

__global__ void __launch_bounds__(256, 2) attn3_kernel(const __half* __restrict__ qkv,
                                                       bf16* __restrict__ oh,
                                                       bf16* __restrict__ ol)
{
    extern __shared__ __half smh[];
    __half* qp = smh;               // [128][64]: Q staging, then P
    __half* ks = qp + 128*64;       // [64][64]:  K tile
    __half* vT = ks + 64*64;        // [64][64]:  V transposed
    uint32_t qp_u = s2u(qp), ks_u = s2u(ks), vT_u = s2u(vT);

    int tid = threadIdx.x;
    int wid = tid >> 5, lane = tid & 31;
    int qt = (int)(gridDim.x - 1) - (int)blockIdx.x;   // heavy tiles first
    int b = blockIdx.y >> 4, h = blockIdx.y & 15;
    size_t rowbase = (size_t)b * S_;
    int qcol = h*64, kcol = 1024 + h*64, vcol = 2048 + h*64;

    int sub = lane >> 3, L = lane & 7;
    int rA = ((sub & 1) << 3) + L, cA = sub >> 1;
    int rB = ((sub >> 1) << 3) + L, cB = sub & 1;
    int g = lane >> 2, tg = lane & 3;

    for (int idx = tid; idx < 1024; idx += 256) {
        int r = idx >> 3, q8 = idx & 7;
        int4 v = *(const int4*)&qkv[(rowbase + (size_t)qt*128 + r)*NQKV_ + qcol + q8*8];
        *(int4*)((char*)qp + r*128 + ((q8 ^ (r & 7)) << 4)) = v;
    }
    __syncthreads();

    uint32_t qf[4][4];
#pragma unroll
    for (int k4 = 0; k4 < 4; k4++) {
        int row = wid*16 + rA;
        uint32_t a = qp_u + (uint32_t)(row*128 + (((2*k4 + cA) ^ (row & 7)) << 4));
        LDSM4(qf[k4][0], qf[k4][1], qf[k4][2], qf[k4][3], a);
    }

    float m0 = -1e30f, m1 = -1e30f, l0 = 0.f, l1 = 0.f;
    float of[8][4];
#pragma unroll
    for (int nt = 0; nt < 8; nt++)
#pragma unroll
        for (int j = 0; j < 4; j++) of[nt][j] = 0.f;

    int tmax = 2*qt + 1;
    for (int t = 0; t <= tmax; t++) {
        __syncthreads();
        for (int idx = tid; idx < 512; idx += 256) {
            int r = idx >> 3, q8 = idx & 7;
            size_t tok = (rowbase + (size_t)t*64 + r) * NQKV_;
            int4 kv = *(const int4*)&qkv[tok + kcol + q8*8];
            *(int4*)((char*)ks + r*128 + ((q8 ^ (r & 7)) << 4)) = kv;
            union { int4 i4; __half hx[8]; } vv;
            vv.i4 = *(const int4*)&qkv[tok + vcol + q8*8];
#pragma unroll
            for (int j = 0; j < 8; j++) {
                int d = q8*8 + j;
                *(__half*)((char*)vT + d*128 + ((((r >> 3) ^ j) & 7) * 16) + (r & 7)*2) = vv.hx[j];
            }
        }
        __syncthreads();

        bool active = !(t == 2*qt + 1 && wid < 4);
        if (active) {
            float s[8][4];
#pragma unroll
            for (int nt = 0; nt < 8; nt++)
#pragma unroll
                for (int j = 0; j < 4; j++) s[nt][j] = 0.f;
#pragma unroll
            for (int k4 = 0; k4 < 4; k4++) {
#pragma unroll
                for (int np = 0; np < 4; np++) {
                    uint32_t bf0, bf1, bf2, bf3;
                    int row = np*16 + rB;
                    uint32_t a = ks_u + (uint32_t)(row*128 + (((2*k4 + cB) ^ (row & 7)) << 4));
                    LDSM4(bf0, bf1, bf2, bf3, a);
                    MMA_F16(s[np*2][0], s[np*2][1], s[np*2][2], s[np*2][3],
                            qf[k4][0], qf[k4][1], qf[k4][2], qf[k4][3], bf0, bf1);
                    MMA_F16(s[np*2+1][0], s[np*2+1][1], s[np*2+1][2], s[np*2+1][3],
                            qf[k4][0], qf[k4][1], qf[k4][2], qf[k4][3], bf2, bf3);
                }
            }

            if (t >= 2*qt) {
                int qr0 = qt*128 + wid*16 + g;
#pragma unroll
                for (int nt = 0; nt < 8; nt++) {
                    int c0 = t*64 + nt*8 + 2*tg;
                    if (c0     > qr0)   s[nt][0] = -1e30f;
                    if (c0 + 1 > qr0)   s[nt][1] = -1e30f;
                    if (c0     > qr0+8) s[nt][2] = -1e30f;
                    if (c0 + 1 > qr0+8) s[nt][3] = -1e30f;
                }
            }

            float mm0 = -1e30f, mm1 = -1e30f;
#pragma unroll
            for (int nt = 0; nt < 8; nt++) {
                mm0 = fmaxf(mm0, fmaxf(s[nt][0], s[nt][1]));
                mm1 = fmaxf(mm1, fmaxf(s[nt][2], s[nt][3]));
            }
            mm0 = fmaxf(mm0, __shfl_xor_sync(0xffffffffu, mm0, 1));
            mm0 = fmaxf(mm0, __shfl_xor_sync(0xffffffffu, mm0, 2));
            mm1 = fmaxf(mm1, __shfl_xor_sync(0xffffffffu, mm1, 1));
            mm1 = fmaxf(mm1, __shfl_xor_sync(0xffffffffu, mm1, 2));
            float mn0 = fmaxf(m0, mm0), mn1 = fmaxf(m1, mm1);
            float a0 = expf(m0 - mn0), a1 = expf(m1 - mn1);
            float sum0 = 0.f, sum1 = 0.f;
#pragma unroll
            for (int nt = 0; nt < 8; nt++) {
                s[nt][0] = expf(s[nt][0] - mn0);
                s[nt][1] = expf(s[nt][1] - mn0);
                s[nt][2] = expf(s[nt][2] - mn1);
                s[nt][3] = expf(s[nt][3] - mn1);
                sum0 += s[nt][0] + s[nt][1];
                sum1 += s[nt][2] + s[nt][3];
            }
            sum0 += __shfl_xor_sync(0xffffffffu, sum0, 1);
            sum0 += __shfl_xor_sync(0xffffffffu, sum0, 2);
            sum1 += __shfl_xor_sync(0xffffffffu, sum1, 1);
            sum1 += __shfl_xor_sync(0xffffffffu, sum1, 2);
            l0 = l0*a0 + sum0; m0 = mn0;
            l1 = l1*a1 + sum1; m1 = mn1;
#pragma unroll
            for (int nt = 0; nt < 8; nt++) {
                of[nt][0] *= a0; of[nt][1] *= a0;
                of[nt][2] *= a1; of[nt][3] *= a1;
            }

            int pr0 = wid*16 + g;
            int pr1 = pr0 + 8;
#pragma unroll
            for (int nt = 0; nt < 8; nt++) {
                uint32_t a0p = qp_u + (uint32_t)(pr0*128 + (((nt) ^ (pr0 & 7)) << 4) + 4*tg);
                uint32_t a1p = qp_u + (uint32_t)(pr1*128 + (((nt) ^ (pr1 & 7)) << 4) + 4*tg);
                __half2 p0 = __floats2half2_rn(s[nt][0], s[nt][1]);
                __half2 p1 = __floats2half2_rn(s[nt][2], s[nt][3]);
                asm volatile("st.shared.b32 [%0], %1;" :: "r"(a0p), "r"(*(uint32_t*)&p0));
                asm volatile("st.shared.b32 [%0], %1;" :: "r"(a1p), "r"(*(uint32_t*)&p1));
            }
            __syncwarp();

#pragma unroll
            for (int k4 = 0; k4 < 4; k4++) {
                uint32_t pf0, pf1, pf2, pf3;
                int prow = wid*16 + rA;
                uint32_t pa = qp_u + (uint32_t)(prow*128 + (((2*k4 + cA) ^ (prow & 7)) << 4));
                LDSM4(pf0, pf1, pf2, pf3, pa);
#pragma unroll
                for (int np = 0; np < 4; np++) {
                    uint32_t bf0, bf1, bf2, bf3;
                    int row = np*16 + rB;
                    uint32_t a = vT_u + (uint32_t)(row*128 + (((2*k4 + cB) ^ (row & 7)) << 4));
                    LDSM4(bf0, bf1, bf2, bf3, a);
                    MMA_F16(of[np*2][0], of[np*2][1], of[np*2][2], of[np*2][3],
                            pf0, pf1, pf2, pf3, bf0, bf1);
                    MMA_F16(of[np*2+1][0], of[np*2+1][1], of[np*2+1][2], of[np*2+1][3],
                            pf0, pf1, pf2, pf3, bf2, bf3);
                }
            }
        }
    }

    float inv0 = 1.f / l0, inv1 = 1.f / l1;
    size_t ro0 = rowbase + (size_t)qt*128 + wid*16 + g;
    size_t ro1 = ro0 + 8;
#pragma unroll
    for (int nt = 0; nt < 8; nt++) {
        int col = h*64 + nt*8 + 2*tg;
        float v0 = of[nt][0]*inv0, v1 = of[nt][1]*inv0;
        float v2 = of[nt][2]*inv1, v3 = of[nt][3]*inv1;
        bf162 hv0, lv0, hv1, lv1;
        bsplit(v0, hv0.x, lv0.x);
        bsplit(v1, hv0.y, lv0.y);
        bsplit(v2, hv1.x, lv1.x);
        bsplit(v3, hv1.y, lv1.y);
        *(bf162*)&oh[ro0*E_ + col] = hv0;
        *(bf162*)&ol[ro0*E_ + col] = lv0;
        *(bf162*)&oh[ro1*E_ + col] = hv1;
        *(bf162*)&ol[ro1*E_ + col] = lv1;
    }
}

// ---------------------------------------------------------------------------
// Launch
// ---------------------------------------------------------------------------
extern "C" void kernel_launch(void* const* d_in, const int* in_sizes, int n_in,
                              void* d_out, int out_size)
{
    (void)in_sizes; (void)n_in; (void)out_size;
    const float* x   = (const float*)d_in[0];
    const float* Wq  = (const float*)d_in[1];
    const float* Wk  = (const float*)d_in[2];
    const float* Wv  = (const float*)d_in[3];
    const float* Wo  = (const float*)d_in[4];
    const float* bo  = (const float*)d_in[5];
    const float* g1  = (const float*)d_in[6];
    const float* be1 = (const float*)d_in[7];
    const float* g2  = (const float*)d_in[8];
    const float* be2 = (const float*)d_in[9];
    const float* W1  = (const float*)d_in[10];
    const float* bb1 = (const float*)d_in[11];
    const float* W2  = (const float*)d_in[12];
    const float* bb2 = (const float*)d_in[13];
    float* out = (float*)d_out;

    __half *lx_h, *lx_l, *wqkv, *qkv;
    bf16 *o_h, *o_l, *lx2_h, *lx2_l, *ffh_h, *ffh_l;
    bf16 *WoT_h, *WoT_l, *W1T_h, *W1T_l, *W2T_h, *W2T_l;
    float *x2;
    cudaGetSymbolAddress((void**)&lx_h,   g_lx_h);
    cudaGetSymbolAddress((void**)&lx_l,   g_lx_l);
    cudaGetSymbolAddress((void**)&wqkv,   g_wqkv);
    cudaGetSymbolAddress((void**)&qkv,    g_qkv);
    cudaGetSymbolAddress((void**)&o_h,    g_o_h);
    cudaGetSymbolAddress((void**)&o_l,    g_o_l);
    cudaGetSymbolAddress((void**)&x2,     g_x2);
    cudaGetSymbolAddress((void**)&lx2_h,  g_lx2_h);
    cudaGetSymbolAddress((void**)&lx2_l,  g_lx2_l);
    cudaGetSymbolAddress((void**)&ffh_h,  g_ffh_h);
    cudaGetSymbolAddress((void**)&ffh_l,  g_ffh_l);
    cudaGetSymbolAddress((void**)&WoT_h,  g_WoT_h);
    cudaGetSymbolAddress((void**)&WoT_l,  g_WoT_l);
    cudaGetSymbolAddress((void**)&W1T_h,  g_W1T_h);
    cudaGetSymbolAddress((void**)&W1T_l,  g_W1T_l);
    cudaGetSymbolAddress((void**)&W2T_h,  g_W2T_h);
    cudaGetSymbolAddress((void**)&W2T_l,  g_W2T_l);

    cudaFuncSetAttribute(attn3_kernel, cudaFuncAttributeMaxDynamicSharedMemorySize, ATTN3_SMEM);
    cudaFuncSetAttribute(gemm_qkv_f16, cudaFuncAttributeMaxDynamicSharedMemorySize, QSMEM);
    cudaFuncSetAttribute(gemm_bf16s<1>, cudaFuncAttributeMaxDynamicSharedMemorySize, GSMEM);
    cudaFuncSetAttribute(gemm_bf16s<2>, cudaFuncAttributeMaxDynamicSharedMemorySize, GSMEM);

    // 1. LN1 -> lx hi/lo (fp16)
    ln_kernel<1><<<M_, 256>>>(x, g1, be1, lx_h, lx_l);
    // 2. weight prep
    pack_qkv_kernel<<<(NQKV_*E_)/256, 256>>>(Wq, Wk, Wv, wqkv);
    tsplit_kernel<<<dim3(E_/32,  E_/32),  dim3(32,8)>>>(Wo, WoT_h, WoT_l, E_,  E_);
    tsplit_kernel<<<dim3(FF_/32, E_/32),  dim3(32,8)>>>(W1, W1T_h, W1T_l, E_,  FF_);
    tsplit_kernel<<<dim3(E_/32,  FF_/32), dim3(32,8)>>>(W2, W2T_h, W2T_l, FF_, E_);
    // 3. qkv = lx @ Wqkv  (fp16 2-pass, q cols pre-scaled)
    gemm_qkv_f16<<<dim3(NQKV_/256, M_/128), 256, QSMEM>>>(
        lx_h, lx_l, wqkv, qkv, E_, NQKV_);
    // 4. attention -> o hi/lo (bf16)
    attn3_kernel<<<dim3(S_/128, B_*H_), 256, ATTN3_SMEM>>>(qkv, o_h, o_l);
    // 5. x2 = x + o @ Wo + bo (f32 out)
    gemm_bf16s<1><<<dim3(E_/256, M_/128), 256, GSMEM>>>(
        o_h, o_l, WoT_h, WoT_l, x2, nullptr, nullptr, bo, x, E_, E_);
    // 6. LN2 -> lx2 hi/lo (bf16)
    ln_kernel<0><<<M_, 256>>>(x2, g2, be2, lx2_h, lx2_l);
    // 7. ffh = relu(lx2 @ W1 + b1) -> bf16 hi/lo
    gemm_bf16s<2><<<dim3(FF_/256, M_/128), 256, GSMEM>>>(
        lx2_h, lx2_l, W1T_h, W1T_l, nullptr, ffh_h, ffh_l, bb1, nullptr, E_, FF_);
    // 8. out = x2 + ffh @ W2 + b2 (f32 out)
    gemm_bf16s<1><<<dim3(E_/256, M_/128), 256, GSMEM>>>(
        ffh_h, ffh_l, W2T_h, W2T_l, out, nullptr, nullptr, bb2, x2, FF_, E_);
}

// round 12
// speedup vs baseline: 4.2182x; 1.2102x over previous
#include <cuda_runtime.h>
#include <cuda_fp16.h>
#include <math.h>
#include <stdint.h>

// Problem constants
#define B_    4
#define S_    2048
#define E_    1024
#define H_    16
#define DH_   64
#define M_    (B_*S_)      // 8192 rows
#define FF_   4096
#define NQKV_ 3072

// ---------------------------------------------------------------------------
// Scratch (static __device__ arrays)
// ---------------------------------------------------------------------------
__device__ __half g_lx_h [(size_t)M_*E_];       // fp16 hi
__device__ __half g_lx_l [(size_t)M_*E_];       // fp16 lo
__device__ __half g_wqkv [(size_t)NQKV_*E_];    // [N=3072, K=1024] fp16
__device__ __half g_qkv  [(size_t)M_*NQKV_];    // fp16, q-cols pre-scaled
__device__ __half g_o_h  [(size_t)M_*E_];
__device__ __half g_o_l  [(size_t)M_*E_];
__device__ float  g_x2   [(size_t)M_*E_];
__device__ __half g_lx2_h[(size_t)M_*E_];
__device__ __half g_lx2_l[(size_t)M_*E_];
__device__ __half g_ffh_h[(size_t)M_*FF_];
__device__ __half g_ffh_l[(size_t)M_*FF_];
__device__ __half g_WoT  [(size_t)E_*E_];       // [N=1024, K=1024] fp16
__device__ __half g_W1T  [(size_t)FF_*E_];      // [N=4096, K=1024] fp16
__device__ __half g_W2T  [(size_t)E_*FF_];      // [N=1024, K=4096] fp16

// ---------------------------------------------------------------------------
// Helpers
// ---------------------------------------------------------------------------
static __device__ __forceinline__ void hsplit(float x, __half& h, __half& l) {
    h = __float2half_rn(x);
    l = __float2half_rn(x - __half2float(h));
}

static __device__ __forceinline__ uint32_t s2u(const void* p) {
    uint32_t a;
    asm("{ .reg .u64 t; cvta.to.shared.u64 t, %1; cvt.u32.u64 %0, t; }" : "=r"(a) : "l"(p));
    return a;
}

#define CP16(dst, src) \
    asm volatile("cp.async.cg.shared.global [%0], [%1], 16;" :: "r"(dst), "l"(src))
#define CP_COMMIT() asm volatile("cp.async.commit_group;")
#define CP_WAIT2()  asm volatile("cp.async.wait_group 2;")
#define CP_WAIT1()  asm volatile("cp.async.wait_group 1;")
#define CP_WAIT0()  asm volatile("cp.async.wait_group 0;")

#define LDSM4(r0, r1, r2, r3, addr) \
    asm volatile("ldmatrix.sync.aligned.m8n8.x4.shared.b16 {%0,%1,%2,%3}, [%4];" \
                 : "=r"(r0), "=r"(r1), "=r"(r2), "=r"(r3) : "r"(addr))

#define MMA_F16(d0, d1, d2, d3, a0, a1, a2, a3, b0, b1) \
    asm volatile("mma.sync.aligned.m16n8k16.row.col.f32.f16.f16.f32 " \
                 "{%0,%1,%2,%3}, {%4,%5,%6,%7}, {%8,%9}, {%0,%1,%2,%3};" \
                 : "+f"(d0), "+f"(d1), "+f"(d2), "+f"(d3) \
                 : "r"(a0), "r"(a1), "r"(a2), "r"(a3), "r"(b0), "r"(b1))

// ---------------------------------------------------------------------------
// LayerNorm -> fp16 hi/lo
// ---------------------------------------------------------------------------
__global__ void ln_kernel(const float* __restrict__ x, const float* __restrict__ g,
                          const float* __restrict__ b,
                          __half* __restrict__ oh, __half* __restrict__ ol)
{
    int row = blockIdx.x;
    int t = threadIdx.x;
    const float* xr = x + (size_t)row * E_;
    float v[4];
    float s = 0.f, s2 = 0.f;
#pragma unroll
    for (int i = 0; i < 4; i++) {
        v[i] = xr[t + 256*i];
        s += v[i];
        s2 += v[i]*v[i];
    }
#pragma unroll
    for (int m = 16; m; m >>= 1) {
        s  += __shfl_xor_sync(0xffffffffu, s,  m);
        s2 += __shfl_xor_sync(0xffffffffu, s2, m);
    }
    __shared__ float sh[2][8];
    if ((t & 31) == 0) { sh[0][t>>5] = s; sh[1][t>>5] = s2; }
    __syncthreads();
    s = 0.f; s2 = 0.f;
#pragma unroll
    for (int w = 0; w < 8; w++) { s += sh[0][w]; s2 += sh[1][w]; }
    float mu  = s * (1.f/E_);
    float var = s2 * (1.f/E_) - mu*mu;
    float r = rsqrtf(var + 1e-5f);
    size_t rb = (size_t)row * E_;
#pragma unroll
    for (int i = 0; i < 4; i++) {
        int c = t + 256*i;
        float y = (v[i]-mu)*r*g[c] + b[c];
        __half h, l;
        hsplit(y, h, l);
        oh[rb + c] = h;
        ol[rb + c] = l;
    }
}

// ---------------------------------------------------------------------------
// Pack Wq/Wk/Wv into [N=3072, K=1024] single fp16 (K-major, head-concat cols)
// ---------------------------------------------------------------------------
__global__ void pack_qkv_kernel(const float* __restrict__ Wq, const float* __restrict__ Wk,
                                const float* __restrict__ Wv, __half* __restrict__ ow)
{
    int idx = blockIdx.x*256 + threadIdx.x;
    int n = idx / E_;
    int e = idx - n*E_;
    const float* W = (n < 1024) ? Wq : (n < 2048 ? Wk : Wv);
    int hd = n & 1023;
    float v = W[(size_t)(hd >> 6)*(E_*DH_) + (size_t)e*DH_ + (hd & 63)];
    ow[idx] = __float2half_rn(v);
}

// ---------------------------------------------------------------------------
// Transpose: in [K,N] row-major f32 -> out [N,K] row-major fp16
// ---------------------------------------------------------------------------
__global__ void ttrans_kernel(const float* __restrict__ in, __half* __restrict__ ow,
                              int K, int N)
{
    __shared__ float t[32][33];
    int k0 = blockIdx.y*32, n0 = blockIdx.x*32;
    int tx = threadIdx.x, ty = threadIdx.y;
#pragma unroll
    for (int r = ty; r < 32; r += 8)
        t[r][tx] = in[(size_t)(k0+r)*N + n0+tx];
    __syncthreads();
#pragma unroll
    for (int r = ty; r < 32; r += 8)
        ow[(size_t)(n0+r)*K + k0+tx] = __float2half_rn(t[tx][r]);
}

// ---------------------------------------------------------------------------
// Unified fp16 asymmetric 2-pass GEMM (A = Ah+Al fp16, B single fp16).
// CTA 128x256, warp 64x64, K-chunk 64, 3-stage pipeline (64 KB/stage).
// EPI: 0 = fp16 out, q-cols (col<1024) pre-scaled by 0.125  (QKV)
//      1 = +bias[col]+res -> C f32                           (Wo, FF2)
//      2 = relu(+bias) -> Ch/Cl fp16 hi/lo                   (FF1)
// ---------------------------------------------------------------------------
#define QSTAGE 65536             // Ah 16K | Al 16K | B 32K
#define QSMEM (3*QSTAGE)         // 196608

template<int EPI>
__global__ void __launch_bounds__(256, 1) gemm_f16s(
    const __half* __restrict__ Ah, const __half* __restrict__ Al,
    const __half* __restrict__ Bw,
    float* __restrict__ C, __half* __restrict__ Ch, __half* __restrict__ Cl,
    const float* __restrict__ bias, const float* __restrict__ res,
    int K, int N)
{
    extern __shared__ char smc[];
    uint32_t sb = s2u(smc);
    int tid = threadIdx.x;
    int wid = tid >> 5, lane = tid & 31;
    int wm = wid >> 2, wn = wid & 3;
    int mblk = blockIdx.y * 128, nblk = blockIdx.x * 256;

    int sub = lane >> 3, L = lane & 7;
    int rA = ((sub & 1) << 3) + L, cAadd = sub >> 1;
    int rB = ((sub >> 1) << 3) + L, cBadd = sub & 1;

    uint32_t sAh[3], sAl[3], sB[3];
#pragma unroll
    for (int b = 0; b < 3; b++) {
        uint32_t base = sb + b * QSTAGE;
        sAh[b] = base;  sAl[b] = base + 16384;  sB[b] = base + 32768;
    }

    float acc[4][8][4];
#pragma unroll
    for (int mt = 0; mt < 4; mt++)
#pragma unroll
        for (int nt = 0; nt < 8; nt++)
#pragma unroll
            for (int q = 0; q < 4; q++) acc[mt][nt][q] = 0.f;

    auto load_stage = [&](int s, int b) {
        int k0 = s << 6;
        for (int idx = tid; idx < 1024; idx += 256) {
            int r = idx >> 3, q = idx & 7;
            uint32_t off = (uint32_t)(r*128 + ((q ^ (r & 7)) << 4));
            size_t gA = (size_t)(mblk + r) * K + k0 + q*8;
            CP16(sAh[b] + off, Ah + gA);
            CP16(sAl[b] + off, Al + gA);
        }
        for (int idx = tid; idx < 2048; idx += 256) {
            int r = idx >> 3, q = idx & 7;
            uint32_t off = (uint32_t)(r*128 + ((q ^ (r & 7)) << 4));
            CP16(sB[b] + off, Bw + (size_t)(nblk + r) * K + k0 + q*8);
        }
        CP_COMMIT();
    };

    const int NS = K >> 6;
    load_stage(0, 0);
    load_stage(1, 1);
    load_stage(2, 2);

    int buf = 0;
    for (int i = 0; i < NS; i++) {
        if (i + 3 <= NS - 1)      CP_WAIT2();
        else if (i + 2 <= NS - 1) CP_WAIT1();
        else                      CP_WAIT0();
        __syncthreads();

#pragma unroll
        for (int ks = 0; ks < 4; ks++) {
            int c0 = 2*ks;
            uint32_t Af[4][4], Bf[4][4];
#pragma unroll
            for (int mt = 0; mt < 4; mt++) {
                int row = wm*64 + mt*16 + rA;
                int ch = c0 + cAadd;
                uint32_t a = sAh[buf] + row*128 + ((ch ^ (row & 7)) << 4);
                LDSM4(Af[mt][0], Af[mt][1], Af[mt][2], Af[mt][3], a);
            }
#pragma unroll
            for (int np = 0; np < 4; np++) {
                int row = wn*64 + np*16 + rB;
                int ch = c0 + cBadd;
                uint32_t sw = (uint32_t)(row*128 + ((ch ^ (row & 7)) << 4));
                LDSM4(Bf[np][0], Bf[np][1], Bf[np][2], Bf[np][3], sB[buf] + sw);
            }
#pragma unroll
            for (int mt = 0; mt < 4; mt++)
#pragma unroll
                for (int nt = 0; nt < 8; nt++)
                    MMA_F16(acc[mt][nt][0], acc[mt][nt][1], acc[mt][nt][2], acc[mt][nt][3],
                            Af[mt][0], Af[mt][1], Af[mt][2], Af[mt][3],
                            Bf[nt>>1][(nt&1)*2], Bf[nt>>1][(nt&1)*2+1]);
#pragma unroll
            for (int mt = 0; mt < 4; mt++) {
                int row = wm*64 + mt*16 + rA;
                int ch = c0 + cAadd;
                uint32_t a = sAl[buf] + row*128 + ((ch ^ (row & 7)) << 4);
                LDSM4(Af[mt][0], Af[mt][1], Af[mt][2], Af[mt][3], a);
            }
#pragma unroll
            for (int mt = 0; mt < 4; mt++)
#pragma unroll
                for (int nt = 0; nt < 8; nt++)
                    MMA_F16(acc[mt][nt][0], acc[mt][nt][1], acc[mt][nt][2], acc[mt][nt][3],
                            Af[mt][0], Af[mt][1], Af[mt][2], Af[mt][3],
                            Bf[nt>>1][(nt&1)*2], Bf[nt>>1][(nt&1)*2+1]);
        }

        __syncthreads();
        if (i + 3 < NS) load_stage(i + 3, buf);
        buf = (buf == 2) ? 0 : buf + 1;
    }

    // Epilogue
    int g = lane >> 2, tg = lane & 3;
#pragma unroll
    for (int mt = 0; mt < 4; mt++) {
#pragma unroll
        for (int nt = 0; nt < 8; nt++) {
            int row0 = mblk + wm*64 + mt*16 + g;
            int col  = nblk + wn*64 + nt*8 + 2*tg;
#pragma unroll
            for (int half = 0; half < 2; half++) {
                int row = row0 + half*8;
                float v0 = acc[mt][nt][half*2+0];
                float v1 = acc[mt][nt][half*2+1];
                size_t gi = (size_t)row * N + col;
                if (EPI == 0) {
                    float sc = (col < 1024) ? 0.125f : 1.f;
                    *(__half2*)&Ch[gi] = __floats2half2_rn(v0*sc, v1*sc);
                } else if (EPI == 1) {
                    v0 += bias[col]; v1 += bias[col+1];
                    float2 rv = *(const float2*)&res[gi];
                    v0 += rv.x; v1 += rv.y;
                    float2 o; o.x = v0; o.y = v1;
                    *(float2*)&C[gi] = o;
                } else {
                    v0 = fmaxf(v0 + bias[col], 0.f);
                    v1 = fmaxf(v1 + bias[col+1], 0.f);
                    __half2 hv, lv;
                    hsplit(v0, hv.x, lv.x);
                    hsplit(v1, hv.y, lv.y);
                    *(__half2*)&Ch[gi] = hv;
                    *(__half2*)&Cl[gi] = lv;
                }
            }
        }
    }
}

// ---------------------------------------------------------------------------
// FP16 tensor-core flash attention (validated rounds 8-9).
// Epilogue emits fp16 hi/lo.
// ---------------------------------------------------------------------------
#define ATTN3_SMEM ((128*64 + 64*64 + 64*64) * 2)   // 32768 bytes

__global__ void __launch_bounds__(256, 2) attn3_kernel(const __half* __restrict__ qkv,
                                                       __half* __restrict__ oh,
                                                       __half* __restrict__ ol)
{
    extern __shared__ __half smh[];
    __half* qp = smh;               // [128][64]: Q staging, then P
    __half* ks = qp + 128*64;       // [64][64]:  K tile
    __half* vT = ks + 64*64;        // [64][64]:  V transposed
    uint32_t qp_u = s2u(qp), ks_u = s2u(ks), vT_u = s2u(vT);

    int tid = threadIdx.x;
    int wid = tid >> 5, lane = tid & 31;
    int qt = (int)(gridDim.x - 1) - (int)blockIdx.x;   // heavy tiles first
    int b = blockIdx.y >> 4, h = blockIdx.y & 15;
    size_t rowbase = (size_t)b * S_;
    int qcol = h*64, kcol = 1024 + h*64, vcol = 2048 + h*64;

    int sub = lane >> 3, L = lane & 7;
    int rA = ((sub & 1) << 3) + L, cA = sub >> 1;
    int rB = ((sub >> 1) << 3) + L, cB = sub & 1;
    int g = lane >> 2, tg = lane & 3;

    for (int idx = tid; idx < 1024; idx += 256) {
        int r = idx >> 3, q8 = idx & 7;
        int4 v = *(const int4*)&qkv[(rowbase + (size_t)qt*128 + r)*NQKV_ + qcol + q8*8];
        *(int4*)((char*)qp + r*128 + ((q8 ^ (r & 7)) << 4)) = v;
    }
    __syncthreads();

    uint32_t qf[4][4];
#pragma unroll
    for (int k4 = 0; k4 < 4; k4++) {
        int row = wid*16 + rA;
        uint32_t a = qp_u + (uint32_t)(row*128 + (((2*k4 + cA) ^ (row & 7)) << 4));
        LDSM4(qf[k4][0], qf[k4][1], qf[k4][2], qf[k4][3], a);
    }

    float m0 = -1e30f, m1 = -1e30f, l0 = 0.f, l1 = 0.f;
    float of[8][4];
#pragma unroll
    for (int nt = 0; nt < 8; nt++)
#pragma unroll
        for (int j = 0; j < 4; j++) of[nt][j] = 0.f;

    int tmax = 2*qt + 1;
    for (int t = 0; t <= tmax; t++) {
        __syncthreads();
        for (int idx = tid; idx < 512; idx += 256) {
            int r = idx >> 3, q8 = idx & 7;
            size_t tok = (rowbase + (size_t)t*64 + r) * NQKV_;
            int4 kv = *(const int4*)&qkv[tok + kcol + q8*8];
            *(int4*)((char*)ks + r*128 + ((q8 ^ (r & 7)) << 4)) = kv;
            union { int4 i4; __half hx[8]; } vv;
            vv.i4 = *(const int4*)&qkv[tok + vcol + q8*8];
#pragma unroll
            for (int j = 0; j < 8; j++) {
                int d = q8*8 + j;
                *(__half*)((char*)vT + d*128 + ((((r >> 3) ^ j) & 7) * 16) + (r & 7)*2) = vv.hx[j];
            }
        }
        __syncthreads();

        bool active = !(t == 2*qt + 1 && wid < 4);
        if (active) {
            float s[8][4];
#pragma unroll
            for (int nt = 0; nt < 8; nt++)
#pragma unroll
                for (int j = 0; j < 4; j++) s[nt][j] = 0.f;
#pragma unroll
            for (int k4 = 0; k4 < 4; k4++) {
#pragma unroll
                for (int np = 0; np < 4; np++) {
                    uint32_t bf0, bf1, bf2, bf3;
                    int row = np*16 + rB;
                    uint32_t a = ks_u + (uint32_t)(row*128 + (((2*k4 + cB) ^ (row & 7)) << 4));
                    LDSM4(bf0, bf1, bf2, bf3, a);
                    MMA_F16(s[np*2][0], s[np*2][1], s[np*2][2], s[np*2][3],
                            qf[k4][0], qf[k4][1], qf[k4][2], qf[k4][3], bf0, bf1);
                    MMA_F16(s[np*2+1][0], s[np*2+1][1], s[np*2+1][2], s[np*2+1][3],
                            qf[k4][0], qf[k4][1], qf[k4][2], qf[k4][3], bf2, bf3);
                }
            }

            if (t >= 2*qt) {
                int qr0 = qt*128 + wid*16 + g;
#pragma unroll
                for (int nt = 0; nt < 8; nt++) {
                    int c0 = t*64 + nt*8 + 2*tg;
                    if (c0     > qr0)   s[nt][0] = -1e30f;
                    if (c0 + 1 > qr0)   s[nt][1] = -1e30f;
                    if (c0     > qr0+8) s[nt][2] = -1e30f;
                    if (c0 + 1 > qr0+8) s[nt][3] = -1e30f;
                }
            }

            float mm0 = -1e30f, mm1 = -1e30f;
#pragma unroll
            for (int nt = 0; nt < 8; nt++) {
                mm0 = fmaxf(mm0, fmaxf(s[nt][0], s[nt][1]));
                mm1 = fmaxf(mm1, fmaxf(s[nt][2], s[nt][3]));
            }
            mm0 = fmaxf(mm0, __shfl_xor_sync(0xffffffffu, mm0, 1));
            mm0 = fmaxf(mm0, __shfl_xor_sync(0xffffffffu, mm0, 2));
            mm1 = fmaxf(mm1, __shfl_xor_sync(0xffffffffu, mm1, 1));
            mm1 = fmaxf(mm1, __shfl_xor_sync(0xffffffffu, mm1, 2));
            float mn0 = fmaxf(m0, mm0), mn1 = fmaxf(m1, mm1);
            float a0 = expf(m0 - mn0), a1 = expf(m1 - mn1);
            float sum0 = 0.f, sum1 = 0.f;
#pragma unroll
            for (int nt = 0; nt < 8; nt++) {
                s[nt][0] = expf(s[nt][0] - mn0);
                s[nt][1] = expf(s[nt][1] - mn0);
                s[nt][2] = expf(s[nt][2] - mn1);
                s[nt][3] = expf(s[nt][3] - mn1);
                sum0 += s[nt][0] + s[nt][1];
                sum1 += s[nt][2] + s[nt][3];
            }
            sum0 += __shfl_xor_sync(0xffffffffu, sum0, 1);
            sum0 += __shfl_xor_sync(0xffffffffu, sum0, 2);
            sum1 += __shfl_xor_sync(0xffffffffu, sum1, 1);
            sum1 += __shfl_xor_sync(0xffffffffu, sum1, 2);
            l0 = l0*a0 + sum0; m0 = mn0;
            l1 = l1*a1 + sum1; m1 = mn1;
#pragma unroll
            for (int nt = 0; nt < 8; nt++) {
                of[nt][0] *= a0; of[nt][1] *= a0;
                of[nt][2] *= a1; of[nt][3] *= a1;
            }

            int pr0 = wid*16 + g;
            int pr1 = pr0 + 8;
#pragma unroll
            for (int nt = 0; nt < 8; nt++) {
                uint32_t a0p = qp_u + (uint32_t)(pr0*128 + (((nt) ^ (pr0 & 7)) << 4) + 4*tg);
                uint32_t a1p = qp_u + (uint32_t)(pr1*128 + (((nt) ^ (pr1 & 7)) << 4) + 4*tg);
                __half2 p0 = __floats2half2_rn(s[nt][0], s[nt][1]);
                __half2 p1 = __floats2half2_rn(s[nt][2], s[nt][3]);
                asm volatile("st.shared.b32 [%0], %1;" :: "r"(a0p), "r"(*(uint32_t*)&p0));
                asm volatile("st.shared.b32 [%0], %1;" :: "r"(a1p), "r"(*(uint32_t*)&p1));
            }
            __syncwarp();

#pragma unroll
            for (int k4 = 0; k4 < 4; k4++) {
                uint32_t pf0, pf1, pf2, pf3;
                int prow = wid*16 + rA;
                uint32_t pa = qp_u + (uint32_t)(prow*128 + (((2*k4 + cA) ^ (prow & 7)) << 4));
                LDSM4(pf0, pf1, pf2, pf3, pa);
#pragma unroll
                for (int np = 0; np < 4; np++) {
                    uint32_t bf0, bf1, bf2, bf3;
                    int row = np*16 + rB;
                    uint32_t a = vT_u + (uint32_t)(row*128 + (((2*k4 + cB) ^ (row & 7)) << 4));
                    LDSM4(bf0, bf1, bf2, bf3, a);
                    MMA_F16(of[np*2][0], of[np*2][1], of[np*2][2], of[np*2][3],
                            pf0, pf1, pf2, pf3, bf0, bf1);
                    MMA_F16(of[np*2+1][0], of[np*2+1][1], of[np*2+1][2], of[np*2+1][3],
                            pf0, pf1, pf2, pf3, bf2, bf3);
                }
            }
        }
    }

    float inv0 = 1.f / l0, inv1 = 1.f / l1;
    size_t ro0 = rowbase + (size_t)qt*128 + wid*16 + g;
    size_t ro1 = ro0 + 8;
#pragma unroll
    for (int nt = 0; nt < 8; nt++) {
        int col = h*64 + nt*8 + 2*tg;
        float v0 = of[nt][0]*inv0, v1 = of[nt][1]*inv0;
        float v2 = of[nt][2]*inv1, v3 = of[nt][3]*inv1;
        __half2 hv0, lv0, hv1, lv1;
        hsplit(v0, hv0.x, lv0.x);
        hsplit(v1, hv0.y, lv0.y);
        hsplit(v2, hv1.x, lv1.x);
        hsplit(v3, hv1.y, lv1.y);
        *(__half2*)&oh[ro0*E_ + col] = hv0;
        *(__half2*)&ol[ro0*E_ + col] = lv0;
        *(__half2*)&oh[ro1*E_ + col] = hv1;
        *(__half2*)&ol[ro1*E_ + col] = lv1;
    }
}

// ---------------------------------------------------------------------------
// Launch
// ---------------------------------------------------------------------------
extern "C" void kernel_launch(void* const* d_in, const int* in_sizes, int n_in,
                              void* d_out, int out_size)
{
    (void)in_sizes; (void)n_in; (void)out_size;
    const float* x   = (const float*)d_in[0];
    const float* Wq  = (const float*)d_in[1];
    const float* Wk  = (const float*)d_in[2];
    const float* Wv  = (const float*)d_in[3];
    const float* Wo  = (const float*)d_in[4];
    const float* bo  = (const float*)d_in[5];
    const float* g1  = (const float*)d_in[6];
    const float* be1 = (const float*)d_in[7];
    const float* g2  = (const float*)d_in[8];
    const float* be2 = (const float*)d_in[9];
    const float* W1  = (const float*)d_in[10];
    const float* bb1 = (const float*)d_in[11];
    const float* W2  = (const float*)d_in[12];
    const float* bb2 = (const float*)d_in[13];
    float* out = (float*)d_out;

    __half *lx_h, *lx_l, *wqkv, *qkv, *o_h, *o_l, *lx2_h, *lx2_l;
    __half *ffh_h, *ffh_l, *WoT, *W1T, *W2T;
    float *x2;
    cudaGetSymbolAddress((void**)&lx_h,   g_lx_h);
    cudaGetSymbolAddress((void**)&lx_l,   g_lx_l);
    cudaGetSymbolAddress((void**)&wqkv,   g_wqkv);
    cudaGetSymbolAddress((void**)&qkv,    g_qkv);
    cudaGetSymbolAddress((void**)&o_h,    g_o_h);
    cudaGetSymbolAddress((void**)&o_l,    g_o_l);
    cudaGetSymbolAddress((void**)&x2,     g_x2);
    cudaGetSymbolAddress((void**)&lx2_h,  g_lx2_h);
    cudaGetSymbolAddress((void**)&lx2_l,  g_lx2_l);
    cudaGetSymbolAddress((void**)&ffh_h,  g_ffh_h);
    cudaGetSymbolAddress((void**)&ffh_l,  g_ffh_l);
    cudaGetSymbolAddress((void**)&WoT,    g_WoT);
    cudaGetSymbolAddress((void**)&W1T,    g_W1T);
    cudaGetSymbolAddress((void**)&W2T,    g_W2T);

    cudaFuncSetAttribute(attn3_kernel, cudaFuncAttributeMaxDynamicSharedMemorySize, ATTN3_SMEM);
    cudaFuncSetAttribute(gemm_f16s<0>, cudaFuncAttributeMaxDynamicSharedMemorySize, QSMEM);
    cudaFuncSetAttribute(gemm_f16s<1>, cudaFuncAttributeMaxDynamicSharedMemorySize, QSMEM);
    cudaFuncSetAttribute(gemm_f16s<2>, cudaFuncAttributeMaxDynamicSharedMemorySize, QSMEM);

    // 1. LN1 -> lx hi/lo (fp16)
    ln_kernel<<<M_, 256>>>(x, g1, be1, lx_h, lx_l);
    // 2. weight prep (fp16)
    pack_qkv_kernel<<<(NQKV_*E_)/256, 256>>>(Wq, Wk, Wv, wqkv);
    ttrans_kernel<<<dim3(E_/32,  E_/32),  dim3(32,8)>>>(Wo, WoT, E_,  E_);
    ttrans_kernel<<<dim3(FF_/32, E_/32),  dim3(32,8)>>>(W1, W1T, E_,  FF_);
    ttrans_kernel<<<dim3(E_/32,  FF_/32), dim3(32,8)>>>(W2, W2T, FF_, E_);
    // 3. qkv = lx @ Wqkv (fp16 2-pass, q cols pre-scaled)
    gemm_f16s<0><<<dim3(NQKV_/256, M_/128), 256, QSMEM>>>(
        lx_h, lx_l, wqkv, nullptr, qkv, nullptr, nullptr, nullptr, E_, NQKV_);
    // 4. attention -> o hi/lo (fp16)
    attn3_kernel<<<dim3(S_/128, B_*H_), 256, ATTN3_SMEM>>>(qkv, o_h, o_l);
    // 5. x2 = x + o @ Wo + bo (f32 out)
    gemm_f16s<1><<<dim3(E_/256, M_/128), 256, QSMEM>>>(
        o_h, o_l, WoT, x2, nullptr, nullptr, bo, x, E_, E_);
    // 6. LN2 -> lx2 hi/lo (fp16)
    ln_kernel<<<M_, 256>>>(x2, g2, be2, lx2_h, lx2_l);
    // 7. ffh = relu(lx2 @ W1 + b1) -> fp16 hi/lo
    gemm_f16s<2><<<dim3(FF_/256, M_/128), 256, QSMEM>>>(
        lx2_h, lx2_l, W1T, nullptr, ffh_h, ffh_l, bb1, nullptr, E_, FF_);
    // 8. out = x2 + ffh @ W2 + b2 (f32 out)
    gemm_f16s<1><<<dim3(E_/256, M_/128), 256, QSMEM>>>(
        ffh_h, ffh_l, W2T, out, nullptr, nullptr, bb2, x2, FF_, E_);
}

// round 14
// speedup vs baseline: 5.8454x; 1.3858x over previous
#include <cuda_runtime.h>
#include <cuda_fp16.h>
#include <math.h>
#include <stdint.h>

// Problem constants
#define B_    4
#define S_    2048
#define E_    1024
#define H_    16
#define DH_   64
#define M_    (B_*S_)      // 8192 rows
#define FF_   4096
#define NQKV_ 3072

// ---------------------------------------------------------------------------
// Scratch (static __device__ arrays)
// ---------------------------------------------------------------------------
__device__ __half g_lx  [(size_t)M_*E_];        // fp16
__device__ __half g_wqkv[(size_t)NQKV_*E_];     // [N=3072, K=1024] fp16
__device__ __half g_qkv [(size_t)M_*NQKV_];     // fp16, q-cols pre-scaled
__device__ __half g_o   [(size_t)M_*E_];
__device__ float  g_x2  [(size_t)M_*E_];
__device__ __half g_lx2 [(size_t)M_*E_];
__device__ __half g_ffh [(size_t)M_*FF_];
__device__ __half g_WoT [(size_t)E_*E_];        // [N=1024, K=1024] fp16
__device__ __half g_W1T [(size_t)FF_*E_];       // [N=4096, K=1024] fp16
__device__ __half g_W2T [(size_t)E_*FF_];       // [N=1024, K=4096] fp16

// ---------------------------------------------------------------------------
// Helpers
// ---------------------------------------------------------------------------
static __device__ __forceinline__ uint32_t s2u(const void* p) {
    uint32_t a;
    asm("{ .reg .u64 t; cvta.to.shared.u64 t, %1; cvt.u32.u64 %0, t; }" : "=r"(a) : "l"(p));
    return a;
}

#define CP16(dst, src) \
    asm volatile("cp.async.cg.shared.global [%0], [%1], 16;" :: "r"(dst), "l"(src))
#define CP_COMMIT() asm volatile("cp.async.commit_group;")
#define CP_WAIT3()  asm volatile("cp.async.wait_group 3;")
#define CP_WAIT2()  asm volatile("cp.async.wait_group 2;")
#define CP_WAIT1()  asm volatile("cp.async.wait_group 1;")
#define CP_WAIT0()  asm volatile("cp.async.wait_group 0;")

#define LDSM4(r0, r1, r2, r3, addr) \
    asm volatile("ldmatrix.sync.aligned.m8n8.x4.shared.b16 {%0,%1,%2,%3}, [%4];" \
                 : "=r"(r0), "=r"(r1), "=r"(r2), "=r"(r3) : "r"(addr))

#define MMA_F16(d0, d1, d2, d3, a0, a1, a2, a3, b0, b1) \
    asm volatile("mma.sync.aligned.m16n8k16.row.col.f32.f16.f16.f32 " \
                 "{%0,%1,%2,%3}, {%4,%5,%6,%7}, {%8,%9}, {%0,%1,%2,%3};" \
                 : "+f"(d0), "+f"(d1), "+f"(d2), "+f"(d3) \
                 : "r"(a0), "r"(a1), "r"(a2), "r"(a3), "r"(b0), "r"(b1))

// ---------------------------------------------------------------------------
// LayerNorm -> single fp16
// ---------------------------------------------------------------------------
__global__ void ln_kernel(const float* __restrict__ x, const float* __restrict__ g,
                          const float* __restrict__ b, __half* __restrict__ o)
{
    int row = blockIdx.x;
    int t = threadIdx.x;
    const float* xr = x + (size_t)row * E_;
    float v[4];
    float s = 0.f, s2 = 0.f;
#pragma unroll
    for (int i = 0; i < 4; i++) {
        v[i] = xr[t + 256*i];
        s += v[i];
        s2 += v[i]*v[i];
    }
#pragma unroll
    for (int m = 16; m; m >>= 1) {
        s  += __shfl_xor_sync(0xffffffffu, s,  m);
        s2 += __shfl_xor_sync(0xffffffffu, s2, m);
    }
    __shared__ float sh[2][8];
    if ((t & 31) == 0) { sh[0][t>>5] = s; sh[1][t>>5] = s2; }
    __syncthreads();
    s = 0.f; s2 = 0.f;
#pragma unroll
    for (int w = 0; w < 8; w++) { s += sh[0][w]; s2 += sh[1][w]; }
    float mu  = s * (1.f/E_);
    float var = s2 * (1.f/E_) - mu*mu;
    float r = rsqrtf(var + 1e-5f);
    size_t rb = (size_t)row * E_;
#pragma unroll
    for (int i = 0; i < 4; i++) {
        int c = t + 256*i;
        o[rb + c] = __float2half_rn((v[i]-mu)*r*g[c] + b[c]);
    }
}

// ---------------------------------------------------------------------------
// Pack Wq/Wk/Wv into [N=3072, K=1024] fp16 (K-major, head-concat cols)
// ---------------------------------------------------------------------------
__global__ void pack_qkv_kernel(const float* __restrict__ Wq, const float* __restrict__ Wk,
                                const float* __restrict__ Wv, __half* __restrict__ ow)
{
    int idx = blockIdx.x*256 + threadIdx.x;
    int n = idx / E_;
    int e = idx - n*E_;
    const float* W = (n < 1024) ? Wq : (n < 2048 ? Wk : Wv);
    int hd = n & 1023;
    float v = W[(size_t)(hd >> 6)*(E_*DH_) + (size_t)e*DH_ + (hd & 63)];
    ow[idx] = __float2half_rn(v);
}

// ---------------------------------------------------------------------------
// Transpose: in [K,N] row-major f32 -> out [N,K] row-major fp16
// ---------------------------------------------------------------------------
__global__ void ttrans_kernel(const float* __restrict__ in, __half* __restrict__ ow,
                              int K, int N)
{
    __shared__ float t[32][33];
    int k0 = blockIdx.y*32, n0 = blockIdx.x*32;
    int tx = threadIdx.x, ty = threadIdx.y;
#pragma unroll
    for (int r = ty; r < 32; r += 8)
        t[r][tx] = in[(size_t)(k0+r)*N + n0+tx];
    __syncthreads();
#pragma unroll
    for (int r = ty; r < 32; r += 8)
        ow[(size_t)(n0+r)*K + k0+tx] = __float2half_rn(t[tx][r]);
}

// ---------------------------------------------------------------------------
// Plain fp16 HGEMM (A fp16, B fp16, fp32 accumulate).
// CTA 128x256, warp 64x64, K-chunk 64, 4-stage pipeline (48 KB/stage).
// EPI: 0 = fp16 out, q-cols (col<1024) pre-scaled by 0.125  (QKV)
//      1 = +bias[col]+res -> C f32                           (Wo, FF2)
//      2 = relu(+bias) -> Ch fp16                            (FF1)
// ---------------------------------------------------------------------------
#define QSTAGE 49152             // A 16K | B 32K
#define QSMEM (4*QSTAGE)         // 196608

template<int EPI>
__global__ void __launch_bounds__(256, 1) gemm_f16(
    const __half* __restrict__ A, const __half* __restrict__ Bw,
    float* __restrict__ C, __half* __restrict__ Ch,
    const float* __restrict__ bias, const float* __restrict__ res,
    int K, int N)
{
    extern __shared__ char smc[];
    uint32_t sb = s2u(smc);
    int tid = threadIdx.x;
    int wid = tid >> 5, lane = tid & 31;
    int wm = wid >> 2, wn = wid & 3;
    int mblk = blockIdx.y * 128, nblk = blockIdx.x * 256;

    int sub = lane >> 3, L = lane & 7;
    int rA = ((sub & 1) << 3) + L, cAadd = sub >> 1;
    int rB = ((sub >> 1) << 3) + L, cBadd = sub & 1;

    uint32_t sA[4], sB[4];
#pragma unroll
    for (int b = 0; b < 4; b++) {
        uint32_t base = sb + b * QSTAGE;
        sA[b] = base;  sB[b] = base + 16384;
    }

    float acc[4][8][4];
#pragma unroll
    for (int mt = 0; mt < 4; mt++)
#pragma unroll
        for (int nt = 0; nt < 8; nt++)
#pragma unroll
            for (int q = 0; q < 4; q++) acc[mt][nt][q] = 0.f;

    auto load_stage = [&](int s, int b) {
        int k0 = s << 6;
        for (int idx = tid; idx < 1024; idx += 256) {
            int r = idx >> 3, q = idx & 7;
            uint32_t off = (uint32_t)(r*128 + ((q ^ (r & 7)) << 4));
            CP16(sA[b] + off, A + (size_t)(mblk + r) * K + k0 + q*8);
        }
        for (int idx = tid; idx < 2048; idx += 256) {
            int r = idx >> 3, q = idx & 7;
            uint32_t off = (uint32_t)(r*128 + ((q ^ (r & 7)) << 4));
            CP16(sB[b] + off, Bw + (size_t)(nblk + r) * K + k0 + q*8);
        }
        CP_COMMIT();
    };

    const int NS = K >> 6;
    load_stage(0, 0);
    load_stage(1, 1);
    load_stage(2, 2);
    load_stage(3, 3);

    for (int i = 0; i < NS; i++) {
        int buf = i & 3;
        if (i + 4 <= NS)      CP_WAIT3();
        else if (i + 3 <= NS) CP_WAIT2();
        else if (i + 2 <= NS) CP_WAIT1();
        else                  CP_WAIT0();
        __syncthreads();

#pragma unroll
        for (int ks = 0; ks < 4; ks++) {
            int c0 = 2*ks;
            uint32_t Af[4][4], Bf[4][4];
#pragma unroll
            for (int mt = 0; mt < 4; mt++) {
                int row = wm*64 + mt*16 + rA;
                int ch = c0 + cAadd;
                uint32_t a = sA[buf] + row*128 + ((ch ^ (row & 7)) << 4);
                LDSM4(Af[mt][0], Af[mt][1], Af[mt][2], Af[mt][3], a);
            }
#pragma unroll
            for (int np = 0; np < 4; np++) {
                int row = wn*64 + np*16 + rB;
                int ch = c0 + cBadd;
                uint32_t sw = (uint32_t)(row*128 + ((ch ^ (row & 7)) << 4));
                LDSM4(Bf[np][0], Bf[np][1], Bf[np][2], Bf[np][3], sB[buf] + sw);
            }
#pragma unroll
            for (int mt = 0; mt < 4; mt++)
#pragma unroll
                for (int nt = 0; nt < 8; nt++)
                    MMA_F16(acc[mt][nt][0], acc[mt][nt][1], acc[mt][nt][2], acc[mt][nt][3],
                            Af[mt][0], Af[mt][1], Af[mt][2], Af[mt][3],
                            Bf[nt>>1][(nt&1)*2], Bf[nt>>1][(nt&1)*2+1]);
        }

        __syncthreads();
        if (i + 4 < NS) load_stage(i + 4, buf);
    }

    // Epilogue
    int g = lane >> 2, tg = lane & 3;
#pragma unroll
    for (int mt = 0; mt < 4; mt++) {
#pragma unroll
        for (int nt = 0; nt < 8; nt++) {
            int row0 = mblk + wm*64 + mt*16 + g;
            int col  = nblk + wn*64 + nt*8 + 2*tg;
#pragma unroll
            for (int half = 0; half < 2; half++) {
                int row = row0 + half*8;
                float v0 = acc[mt][nt][half*2+0];
                float v1 = acc[mt][nt][half*2+1];
                size_t gi = (size_t)row * N + col;
                if (EPI == 0) {
                    float sc = (col < 1024) ? 0.125f : 1.f;
                    *(__half2*)&Ch[gi] = __floats2half2_rn(v0*sc, v1*sc);
                } else if (EPI == 1) {
                    v0 += bias[col]; v1 += bias[col+1];
                    float2 rv = *(const float2*)&res[gi];
                    v0 += rv.x; v1 += rv.y;
                    float2 o; o.x = v0; o.y = v1;
                    *(float2*)&C[gi] = o;
                } else {
                    v0 = fmaxf(v0 + bias[col], 0.f);
                    v1 = fmaxf(v1 + bias[col+1], 0.f);
                    *(__half2*)&Ch[gi] = __floats2half2_rn(v0, v1);
                }
            }
        }
    }
}

// ---------------------------------------------------------------------------
// FP16 tensor-core flash attention (validated rounds 8-12).
// Epilogue emits single fp16.
// ---------------------------------------------------------------------------
#define ATTN3_SMEM ((128*64 + 64*64 + 64*64) * 2)   // 32768 bytes

__global__ void __launch_bounds__(256, 2) attn3_kernel(const __half* __restrict__ qkv,
                                                       __half* __restrict__ oh)
{
    extern __shared__ __half smh[];
    __half* qp = smh;               // [128][64]: Q staging, then P
    __half* ks = qp + 128*64;       // [64][64]:  K tile
    __half* vT = ks + 64*64;        // [64][64]:  V transposed
    uint32_t qp_u = s2u(qp), ks_u = s2u(ks), vT_u = s2u(vT);

    int tid = threadIdx.x;
    int wid = tid >> 5, lane = tid & 31;
    int qt = (int)(gridDim.x - 1) - (int)blockIdx.x;   // heavy tiles first
    int b = blockIdx.y >> 4, h = blockIdx.y & 15;
    size_t rowbase = (size_t)b * S_;
    int qcol = h*64, kcol = 1024 + h*64, vcol = 2048 + h*64;

    int sub = lane >> 3, L = lane & 7;
    int rA = ((sub & 1) << 3) + L, cA = sub >> 1;
    int rB = ((sub >> 1) << 3) + L, cB = sub & 1;
    int g = lane >> 2, tg = lane & 3;

    for (int idx = tid; idx < 1024; idx += 256) {
        int r = idx >> 3, q8 = idx & 7;
        int4 v = *(const int4*)&qkv[(rowbase + (size_t)qt*128 + r)*NQKV_ + qcol + q8*8];
        *(int4*)((char*)qp + r*128 + ((q8 ^ (r & 7)) << 4)) = v;
    }
    __syncthreads();

    uint32_t qf[4][4];
#pragma unroll
    for (int k4 = 0; k4 < 4; k4++) {
        int row = wid*16 + rA;
        uint32_t a = qp_u + (uint32_t)(row*128 + (((2*k4 + cA) ^ (row & 7)) << 4));
        LDSM4(qf[k4][0], qf[k4][1], qf[k4][2], qf[k4][3], a);
    }

    float m0 = -1e30f, m1 = -1e30f, l0 = 0.f, l1 = 0.f;
    float of[8][4];
#pragma unroll
    for (int nt = 0; nt < 8; nt++)
#pragma unroll
        for (int j = 0; j < 4; j++) of[nt][j] = 0.f;

    int tmax = 2*qt + 1;
    for (int t = 0; t <= tmax; t++) {
        __syncthreads();
        for (int idx = tid; idx < 512; idx += 256) {
            int r = idx >> 3, q8 = idx & 7;
            size_t tok = (rowbase + (size_t)t*64 + r) * NQKV_;
            int4 kv = *(const int4*)&qkv[tok + kcol + q8*8];
            *(int4*)((char*)ks + r*128 + ((q8 ^ (r & 7)) << 4)) = kv;
            union { int4 i4; __half hx[8]; } vv;
            vv.i4 = *(const int4*)&qkv[tok + vcol + q8*8];
#pragma unroll
            for (int j = 0; j < 8; j++) {
                int d = q8*8 + j;
                *(__half*)((char*)vT + d*128 + ((((r >> 3) ^ j) & 7) * 16) + (r & 7)*2) = vv.hx[j];
            }
        }
        __syncthreads();

        bool active = !(t == 2*qt + 1 && wid < 4);
        if (active) {
            float s[8][4];
#pragma unroll
            for (int nt = 0; nt < 8; nt++)
#pragma unroll
                for (int j = 0; j < 4; j++) s[nt][j] = 0.f;
#pragma unroll
            for (int k4 = 0; k4 < 4; k4++) {
#pragma unroll
                for (int np = 0; np < 4; np++) {
                    uint32_t bf0, bf1, bf2, bf3;
                    int row = np*16 + rB;
                    uint32_t a = ks_u + (uint32_t)(row*128 + (((2*k4 + cB) ^ (row & 7)) << 4));
                    LDSM4(bf0, bf1, bf2, bf3, a);
                    MMA_F16(s[np*2][0], s[np*2][1], s[np*2][2], s[np*2][3],
                            qf[k4][0], qf[k4][1], qf[k4][2], qf[k4][3], bf0, bf1);
                    MMA_F16(s[np*2+1][0], s[np*2+1][1], s[np*2+1][2], s[np*2+1][3],
                            qf[k4][0], qf[k4][1], qf[k4][2], qf[k4][3], bf2, bf3);
                }
            }

            if (t >= 2*qt) {
                int qr0 = qt*128 + wid*16 + g;
#pragma unroll
                for (int nt = 0; nt < 8; nt++) {
                    int c0 = t*64 + nt*8 + 2*tg;
                    if (c0     > qr0)   s[nt][0] = -1e30f;
                    if (c0 + 1 > qr0)   s[nt][1] = -1e30f;
                    if (c0     > qr0+8) s[nt][2] = -1e30f;
                    if (c0 + 1 > qr0+8) s[nt][3] = -1e30f;
                }
            }

            float mm0 = -1e30f, mm1 = -1e30f;
#pragma unroll
            for (int nt = 0; nt < 8; nt++) {
                mm0 = fmaxf(mm0, fmaxf(s[nt][0], s[nt][1]));
                mm1 = fmaxf(mm1, fmaxf(s[nt][2], s[nt][3]));
            }
            mm0 = fmaxf(mm0, __shfl_xor_sync(0xffffffffu, mm0, 1));
            mm0 = fmaxf(mm0, __shfl_xor_sync(0xffffffffu, mm0, 2));
            mm1 = fmaxf(mm1, __shfl_xor_sync(0xffffffffu, mm1, 1));
            mm1 = fmaxf(mm1, __shfl_xor_sync(0xffffffffu, mm1, 2));
            float mn0 = fmaxf(m0, mm0), mn1 = fmaxf(m1, mm1);
            float a0 = expf(m0 - mn0), a1 = expf(m1 - mn1);
            float sum0 = 0.f, sum1 = 0.f;
#pragma unroll
            for (int nt = 0; nt < 8; nt++) {
                s[nt][0] = expf(s[nt][0] - mn0);
                s[nt][1] = expf(s[nt][1] - mn0);
                s[nt][2] = expf(s[nt][2] - mn1);
                s[nt][3] = expf(s[nt][3] - mn1);
                sum0 += s[nt][0] + s[nt][1];
                sum1 += s[nt][2] + s[nt][3];
            }
            sum0 += __shfl_xor_sync(0xffffffffu, sum0, 1);
            sum0 += __shfl_xor_sync(0xffffffffu, sum0, 2);
            sum1 += __shfl_xor_sync(0xffffffffu, sum1, 1);
            sum1 += __shfl_xor_sync(0xffffffffu, sum1, 2);
            l0 = l0*a0 + sum0; m0 = mn0;
            l1 = l1*a1 + sum1; m1 = mn1;
#pragma unroll
            for (int nt = 0; nt < 8; nt++) {
                of[nt][0] *= a0; of[nt][1] *= a0;
                of[nt][2] *= a1; of[nt][3] *= a1;
            }

            int pr0 = wid*16 + g;
            int pr1 = pr0 + 8;
#pragma unroll
            for (int nt = 0; nt < 8; nt++) {
                uint32_t a0p = qp_u + (uint32_t)(pr0*128 + (((nt) ^ (pr0 & 7)) << 4) + 4*tg);
                uint32_t a1p = qp_u + (uint32_t)(pr1*128 + (((nt) ^ (pr1 & 7)) << 4) + 4*tg);
                __half2 p0 = __floats2half2_rn(s[nt][0], s[nt][1]);
                __half2 p1 = __floats2half2_rn(s[nt][2], s[nt][3]);
                asm volatile("st.shared.b32 [%0], %1;" :: "r"(a0p), "r"(*(uint32_t*)&p0));
                asm volatile("st.shared.b32 [%0], %1;" :: "r"(a1p), "r"(*(uint32_t*)&p1));
            }
            __syncwarp();

#pragma unroll
            for (int k4 = 0; k4 < 4; k4++) {
                uint32_t pf0, pf1, pf2, pf3;
                int prow = wid*16 + rA;
                uint32_t pa = qp_u + (uint32_t)(prow*128 + (((2*k4 + cA) ^ (prow & 7)) << 4));
                LDSM4(pf0, pf1, pf2, pf3, pa);
#pragma unroll
                for (int np = 0; np < 4; np++) {
                    uint32_t bf0, bf1, bf2, bf3;
                    int row = np*16 + rB;
                    uint32_t a = vT_u + (uint32_t)(row*128 + (((2*k4 + cB) ^ (row & 7)) << 4));
                    LDSM4(bf0, bf1, bf2, bf3, a);
                    MMA_F16(of[np*2][0], of[np*2][1], of[np*2][2], of[np*2][3],
                            pf0, pf1, pf2, pf3, bf0, bf1);
                    MMA_F16(of[np*2+1][0], of[np*2+1][1], of[np*2+1][2], of[np*2+1][3],
                            pf0, pf1, pf2, pf3, bf2, bf3);
                }
            }
        }
    }

    float inv0 = 1.f / l0, inv1 = 1.f / l1;
    size_t ro0 = rowbase + (size_t)qt*128 + wid*16 + g;
    size_t ro1 = ro0 + 8;
#pragma unroll
    for (int nt = 0; nt < 8; nt++) {
        int col = h*64 + nt*8 + 2*tg;
        *(__half2*)&oh[ro0*E_ + col] = __floats2half2_rn(of[nt][0]*inv0, of[nt][1]*inv0);
        *(__half2*)&oh[ro1*E_ + col] = __floats2half2_rn(of[nt][2]*inv1, of[nt][3]*inv1);
    }
}

// ---------------------------------------------------------------------------
// Launch
// ---------------------------------------------------------------------------
extern "C" void kernel_launch(void* const* d_in, const int* in_sizes, int n_in,
                              void* d_out, int out_size)
{
    (void)in_sizes; (void)n_in; (void)out_size;
    const float* x   = (const float*)d_in[0];
    const float* Wq  = (const float*)d_in[1];
    const float* Wk  = (const float*)d_in[2];
    const float* Wv  = (const float*)d_in[3];
    const float* Wo  = (const float*)d_in[4];
    const float* bo  = (const float*)d_in[5];
    const float* g1  = (const float*)d_in[6];
    const float* be1 = (const float*)d_in[7];
    const float* g2  = (const float*)d_in[8];
    const float* be2 = (const float*)d_in[9];
    const float* W1  = (const float*)d_in[10];
    const float* bb1 = (const float*)d_in[11];
    const float* W2  = (const float*)d_in[12];
    const float* bb2 = (const float*)d_in[13];
    float* out = (float*)d_out;

    __half *lx, *wqkv, *qkv, *o, *lx2, *ffh, *WoT, *W1T, *W2T;
    float *x2;
    cudaGetSymbolAddress((void**)&lx,   g_lx);
    cudaGetSymbolAddress((void**)&wqkv, g_wqkv);
    cudaGetSymbolAddress((void**)&qkv,  g_qkv);
    cudaGetSymbolAddress((void**)&o,    g_o);
    cudaGetSymbolAddress((void**)&x2,   g_x2);
    cudaGetSymbolAddress((void**)&lx2,  g_lx2);
    cudaGetSymbolAddress((void**)&ffh,  g_ffh);
    cudaGetSymbolAddress((void**)&WoT,  g_WoT);
    cudaGetSymbolAddress((void**)&W1T,  g_W1T);
    cudaGetSymbolAddress((void**)&W2T,  g_W2T);

    cudaFuncSetAttribute(attn3_kernel, cudaFuncAttributeMaxDynamicSharedMemorySize, ATTN3_SMEM);
    cudaFuncSetAttribute(gemm_f16<0>, cudaFuncAttributeMaxDynamicSharedMemorySize, QSMEM);
    cudaFuncSetAttribute(gemm_f16<1>, cudaFuncAttributeMaxDynamicSharedMemorySize, QSMEM);
    cudaFuncSetAttribute(gemm_f16<2>, cudaFuncAttributeMaxDynamicSharedMemorySize, QSMEM);

    // 1. LN1 -> lx (fp16)
    ln_kernel<<<M_, 256>>>(x, g1, be1, lx);
    // 2. weight prep (fp16)
    pack_qkv_kernel<<<(NQKV_*E_)/256, 256>>>(Wq, Wk, Wv, wqkv);
    ttrans_kernel<<<dim3(E_/32,  E_/32),  dim3(32,8)>>>(Wo, WoT, E_,  E_);
    ttrans_kernel<<<dim3(FF_/32, E_/32),  dim3(32,8)>>>(W1, W1T, E_,  FF_);
    ttrans_kernel<<<dim3(E_/32,  FF_/32), dim3(32,8)>>>(W2, W2T, FF_, E_);
    // 3. qkv = lx @ Wqkv (fp16, q cols pre-scaled)
    gemm_f16<0><<<dim3(NQKV_/256, M_/128), 256, QSMEM>>>(
        lx, wqkv, nullptr, qkv, nullptr, nullptr, E_, NQKV_);
    // 4. attention -> o (fp16)
    attn3_kernel<<<dim3(S_/128, B_*H_), 256, ATTN3_SMEM>>>(qkv, o);
    // 5. x2 = x + o @ Wo + bo (f32 out)
    gemm_f16<1><<<dim3(E_/256, M_/128), 256, QSMEM>>>(
        o, WoT, x2, nullptr, bo, x, E_, E_);
    // 6. LN2 -> lx2 (fp16)
    ln_kernel<<<M_, 256>>>(x2, g2, be2, lx2);
    // 7. ffh = relu(lx2 @ W1 + b1) -> fp16
    gemm_f16<2><<<dim3(FF_/256, M_/128), 256, QSMEM>>>(
        lx2, W1T, nullptr, ffh, bb1, nullptr, E_, FF_);
    // 8. out = x2 + ffh @ W2 + b2 (f32 out)
    gemm_f16<1><<<dim3(E_/256, M_/128), 256, QSMEM>>>(
        ffh, W2T, out, nullptr, bb2, x2, FF_, E_);
}

// round 16
// speedup vs baseline: 6.3953x; 1.0941x over previous
#include <cuda_runtime.h>
#include <cuda_fp16.h>
#include <math.h>
#include <stdint.h>

// Problem constants
#define B_    4
#define S_    2048
#define E_    1024
#define H_    16
#define DH_   64
#define M_    (B_*S_)      // 8192 rows
#define FF_   4096
#define NQKV_ 3072

// ---------------------------------------------------------------------------
// Scratch (static __device__ arrays)
// ---------------------------------------------------------------------------
__device__ __half g_lx  [(size_t)M_*E_];        // fp16
__device__ __half g_wqkv[(size_t)NQKV_*E_];     // [N=3072, K=1024] fp16
__device__ __half g_qkv [(size_t)M_*NQKV_];     // fp16, q-cols pre-scaled
__device__ __half g_o   [(size_t)M_*E_];
__device__ float  g_x2  [(size_t)M_*E_];
__device__ __half g_lx2 [(size_t)M_*E_];
__device__ __half g_ffh [(size_t)M_*FF_];
__device__ __half g_WoT [(size_t)E_*E_];        // [N=1024, K=1024] fp16
__device__ __half g_W1T [(size_t)FF_*E_];       // [N=4096, K=1024] fp16
__device__ __half g_W2T [(size_t)E_*FF_];       // [N=1024, K=4096] fp16

// ---------------------------------------------------------------------------
// Helpers
// ---------------------------------------------------------------------------
static __device__ __forceinline__ uint32_t s2u(const void* p) {
    uint32_t a;
    asm("{ .reg .u64 t; cvta.to.shared.u64 t, %1; cvt.u32.u64 %0, t; }" : "=r"(a) : "l"(p));
    return a;
}

#define CP16(dst, src) \
    asm volatile("cp.async.cg.shared.global [%0], [%1], 16;" :: "r"(dst), "l"(src))
#define CP_COMMIT() asm volatile("cp.async.commit_group;")
#define CP_WAIT3()  asm volatile("cp.async.wait_group 3;")
#define CP_WAIT2()  asm volatile("cp.async.wait_group 2;")
#define CP_WAIT1()  asm volatile("cp.async.wait_group 1;")
#define CP_WAIT0()  asm volatile("cp.async.wait_group 0;")

#define LDSM4(r0, r1, r2, r3, addr) \
    asm volatile("ldmatrix.sync.aligned.m8n8.x4.shared.b16 {%0,%1,%2,%3}, [%4];" \
                 : "=r"(r0), "=r"(r1), "=r"(r2), "=r"(r3) : "r"(addr))

#define LDSM4T(r0, r1, r2, r3, addr) \
    asm volatile("ldmatrix.sync.aligned.m8n8.x4.trans.shared.b16 {%0,%1,%2,%3}, [%4];" \
                 : "=r"(r0), "=r"(r1), "=r"(r2), "=r"(r3) : "r"(addr))

#define MMA_F16(d0, d1, d2, d3, a0, a1, a2, a3, b0, b1) \
    asm volatile("mma.sync.aligned.m16n8k16.row.col.f32.f16.f16.f32 " \
                 "{%0,%1,%2,%3}, {%4,%5,%6,%7}, {%8,%9}, {%0,%1,%2,%3};" \
                 : "+f"(d0), "+f"(d1), "+f"(d2), "+f"(d3) \
                 : "r"(a0), "r"(a1), "r"(a2), "r"(a3), "r"(b0), "r"(b1))

// ---------------------------------------------------------------------------
// LayerNorm -> single fp16
// ---------------------------------------------------------------------------
__global__ void ln_kernel(const float* __restrict__ x, const float* __restrict__ g,
                          const float* __restrict__ b, __half* __restrict__ o)
{
    int row = blockIdx.x;
    int t = threadIdx.x;
    const float* xr = x + (size_t)row * E_;
    float v[4];
    float s = 0.f, s2 = 0.f;
#pragma unroll
    for (int i = 0; i < 4; i++) {
        v[i] = xr[t + 256*i];
        s += v[i];
        s2 += v[i]*v[i];
    }
#pragma unroll
    for (int m = 16; m; m >>= 1) {
        s  += __shfl_xor_sync(0xffffffffu, s,  m);
        s2 += __shfl_xor_sync(0xffffffffu, s2, m);
    }
    __shared__ float sh[2][8];
    if ((t & 31) == 0) { sh[0][t>>5] = s; sh[1][t>>5] = s2; }
    __syncthreads();
    s = 0.f; s2 = 0.f;
#pragma unroll
    for (int w = 0; w < 8; w++) { s += sh[0][w]; s2 += sh[1][w]; }
    float mu  = s * (1.f/E_);
    float var = s2 * (1.f/E_) - mu*mu;
    float r = rsqrtf(var + 1e-5f);
    size_t rb = (size_t)row * E_;
#pragma unroll
    for (int i = 0; i < 4; i++) {
        int c = t + 256*i;
        o[rb + c] = __float2half_rn((v[i]-mu)*r*g[c] + b[c]);
    }
}

// ---------------------------------------------------------------------------
// Pack Wq/Wk/Wv into [N=3072, K=1024] fp16 (K-major, head-concat cols)
// ---------------------------------------------------------------------------
__global__ void pack_qkv_kernel(const float* __restrict__ Wq, const float* __restrict__ Wk,
                                const float* __restrict__ Wv, __half* __restrict__ ow)
{
    int idx = blockIdx.x*256 + threadIdx.x;
    int n = idx / E_;
    int e = idx - n*E_;
    const float* W = (n < 1024) ? Wq : (n < 2048 ? Wk : Wv);
    int hd = n & 1023;
    float v = W[(size_t)(hd >> 6)*(E_*DH_) + (size_t)e*DH_ + (hd & 63)];
    ow[idx] = __float2half_rn(v);
}

// ---------------------------------------------------------------------------
// Transpose: in [K,N] row-major f32 -> out [N,K] row-major fp16
// ---------------------------------------------------------------------------
__global__ void ttrans_kernel(const float* __restrict__ in, __half* __restrict__ ow,
                              int K, int N)
{
    __shared__ float t[32][33];
    int k0 = blockIdx.y*32, n0 = blockIdx.x*32;
    int tx = threadIdx.x, ty = threadIdx.y;
#pragma unroll
    for (int r = ty; r < 32; r += 8)
        t[r][tx] = in[(size_t)(k0+r)*N + n0+tx];
    __syncthreads();
#pragma unroll
    for (int r = ty; r < 32; r += 8)
        ow[(size_t)(n0+r)*K + k0+tx] = __float2half_rn(t[tx][r]);
}

// ---------------------------------------------------------------------------
// Plain fp16 HGEMM (validated round 13, unchanged).
// EPI: 0 = fp16 out (q-cols pre-scaled), 1 = +bias+res f32, 2 = relu fp16
// ---------------------------------------------------------------------------
#define QSTAGE 49152             // A 16K | B 32K
#define QSMEM (4*QSTAGE)         // 196608

template<int EPI>
__global__ void __launch_bounds__(256, 1) gemm_f16(
    const __half* __restrict__ A, const __half* __restrict__ Bw,
    float* __restrict__ C, __half* __restrict__ Ch,
    const float* __restrict__ bias, const float* __restrict__ res,
    int K, int N)
{
    extern __shared__ char smc[];
    uint32_t sb = s2u(smc);
    int tid = threadIdx.x;
    int wid = tid >> 5, lane = tid & 31;
    int wm = wid >> 2, wn = wid & 3;
    int mblk = blockIdx.y * 128, nblk = blockIdx.x * 256;

    int sub = lane >> 3, L = lane & 7;
    int rA = ((sub & 1) << 3) + L, cAadd = sub >> 1;
    int rB = ((sub >> 1) << 3) + L, cBadd = sub & 1;

    uint32_t sA[4], sB[4];
#pragma unroll
    for (int b = 0; b < 4; b++) {
        uint32_t base = sb + b * QSTAGE;
        sA[b] = base;  sB[b] = base + 16384;
    }

    float acc[4][8][4];
#pragma unroll
    for (int mt = 0; mt < 4; mt++)
#pragma unroll
        for (int nt = 0; nt < 8; nt++)
#pragma unroll
            for (int q = 0; q < 4; q++) acc[mt][nt][q] = 0.f;

    auto load_stage = [&](int s, int b) {
        int k0 = s << 6;
        for (int idx = tid; idx < 1024; idx += 256) {
            int r = idx >> 3, q = idx & 7;
            uint32_t off = (uint32_t)(r*128 + ((q ^ (r & 7)) << 4));
            CP16(sA[b] + off, A + (size_t)(mblk + r) * K + k0 + q*8);
        }
        for (int idx = tid; idx < 2048; idx += 256) {
            int r = idx >> 3, q = idx & 7;
            uint32_t off = (uint32_t)(r*128 + ((q ^ (r & 7)) << 4));
            CP16(sB[b] + off, Bw + (size_t)(nblk + r) * K + k0 + q*8);
        }
        CP_COMMIT();
    };

    const int NS = K >> 6;
    load_stage(0, 0);
    load_stage(1, 1);
    load_stage(2, 2);
    load_stage(3, 3);

    for (int i = 0; i < NS; i++) {
        int buf = i & 3;
        if (i + 4 <= NS)      CP_WAIT3();
        else if (i + 3 <= NS) CP_WAIT2();
        else if (i + 2 <= NS) CP_WAIT1();
        else                  CP_WAIT0();
        __syncthreads();

#pragma unroll
        for (int ks = 0; ks < 4; ks++) {
            int c0 = 2*ks;
            uint32_t Af[4][4], Bf[4][4];
#pragma unroll
            for (int mt = 0; mt < 4; mt++) {
                int row = wm*64 + mt*16 + rA;
                int ch = c0 + cAadd;
                uint32_t a = sA[buf] + row*128 + ((ch ^ (row & 7)) << 4);
                LDSM4(Af[mt][0], Af[mt][1], Af[mt][2], Af[mt][3], a);
            }
#pragma unroll
            for (int np = 0; np < 4; np++) {
                int row = wn*64 + np*16 + rB;
                int ch = c0 + cBadd;
                uint32_t sw = (uint32_t)(row*128 + ((ch ^ (row & 7)) << 4));
                LDSM4(Bf[np][0], Bf[np][1], Bf[np][2], Bf[np][3], sB[buf] + sw);
            }
#pragma unroll
            for (int mt = 0; mt < 4; mt++)
#pragma unroll
                for (int nt = 0; nt < 8; nt++)
                    MMA_F16(acc[mt][nt][0], acc[mt][nt][1], acc[mt][nt][2], acc[mt][nt][3],
                            Af[mt][0], Af[mt][1], Af[mt][2], Af[mt][3],
                            Bf[nt>>1][(nt&1)*2], Bf[nt>>1][(nt&1)*2+1]);
        }

        __syncthreads();
        if (i + 4 < NS) load_stage(i + 4, buf);
    }

    // Epilogue
    int g = lane >> 2, tg = lane & 3;
#pragma unroll
    for (int mt = 0; mt < 4; mt++) {
#pragma unroll
        for (int nt = 0; nt < 8; nt++) {
            int row0 = mblk + wm*64 + mt*16 + g;
            int col  = nblk + wn*64 + nt*8 + 2*tg;
#pragma unroll
            for (int half = 0; half < 2; half++) {
                int row = row0 + half*8;
                float v0 = acc[mt][nt][half*2+0];
                float v1 = acc[mt][nt][half*2+1];
                size_t gi = (size_t)row * N + col;
                if (EPI == 0) {
                    float sc = (col < 1024) ? 0.125f : 1.f;
                    *(__half2*)&Ch[gi] = __floats2half2_rn(v0*sc, v1*sc);
                } else if (EPI == 1) {
                    v0 += bias[col]; v1 += bias[col+1];
                    float2 rv = *(const float2*)&res[gi];
                    v0 += rv.x; v1 += rv.y;
                    float2 o; o.x = v0; o.y = v1;
                    *(float2*)&C[gi] = o;
                } else {
                    v0 = fmaxf(v0 + bias[col], 0.f);
                    v1 = fmaxf(v1 + bias[col+1], 0.f);
                    *(__half2*)&Ch[gi] = __floats2half2_rn(v0, v1);
                }
            }
        }
    }
}

// ---------------------------------------------------------------------------
// FP16 flash attention v4: cp.async double-buffered K/V tiles + trans-ldmatrix
// V (no scatter transpose). Same math as validated attn3 -> bit-identical
// output. Smem: qp[128][64] (Q then P), ks[2][64][64], vs[2][64][64].
// ---------------------------------------------------------------------------
#define ATTN4_SMEM ((128*64 + 4*64*64) * 2)   // 49152 bytes

__global__ void __launch_bounds__(256, 2) attn4_kernel(const __half* __restrict__ qkv,
                                                       __half* __restrict__ oh)
{
    extern __shared__ __half smh[];
    uint32_t qp_u = s2u(smh);
    uint32_t ks_u[2], vs_u[2];
    ks_u[0] = qp_u + 16384;
    ks_u[1] = ks_u[0] + 8192;
    vs_u[0] = ks_u[1] + 8192;
    vs_u[1] = vs_u[0] + 8192;

    int tid = threadIdx.x;
    int wid = tid >> 5, lane = tid & 31;
    int qt = (int)(gridDim.x - 1) - (int)blockIdx.x;   // heavy tiles first
    int b = blockIdx.y >> 4, h = blockIdx.y & 15;
    size_t rowbase = (size_t)b * S_;
    int qcol = h*64, kcol = 1024 + h*64, vcol = 2048 + h*64;

    int sub = lane >> 3, L = lane & 7;
    int rA = ((sub & 1) << 3) + L, cA = sub >> 1;      // also V-trans addressing
    int rB = ((sub >> 1) << 3) + L, cB = sub & 1;
    int g = lane >> 2, tg = lane & 3;

    // ---- stage Q via cp.async ----
    for (int idx = tid; idx < 1024; idx += 256) {
        int r = idx >> 3, q8 = idx & 7;
        uint32_t off = (uint32_t)(r*128 + ((q8 ^ (r & 7)) << 4));
        CP16(qp_u + off, qkv + (rowbase + (size_t)qt*128 + r)*NQKV_ + qcol + q8*8);
    }
    CP_COMMIT();

    auto load_kv = [&](int t, int bufi) {
        for (int idx = tid; idx < 512; idx += 256) {
            int r = idx >> 3, q8 = idx & 7;
            uint32_t off = (uint32_t)(r*128 + ((q8 ^ (r & 7)) << 4));
            size_t tok = (rowbase + (size_t)t*64 + r) * NQKV_;
            CP16(ks_u[bufi] + off, qkv + tok + kcol + q8*8);
            CP16(vs_u[bufi] + off, qkv + tok + vcol + q8*8);
        }
        CP_COMMIT();
    };

    load_kv(0, 0);
    CP_WAIT1();          // Q landed (kv0 may still fly)
    __syncthreads();

    uint32_t qf[4][4];
#pragma unroll
    for (int k4 = 0; k4 < 4; k4++) {
        int row = wid*16 + rA;
        uint32_t a = qp_u + (uint32_t)(row*128 + (((2*k4 + cA) ^ (row & 7)) << 4));
        LDSM4(qf[k4][0], qf[k4][1], qf[k4][2], qf[k4][3], a);
    }

    float m0 = -1e30f, m1 = -1e30f, l0 = 0.f, l1 = 0.f;
    float of[8][4];
#pragma unroll
    for (int nt = 0; nt < 8; nt++)
#pragma unroll
        for (int j = 0; j < 4; j++) of[nt][j] = 0.f;

    int tmax = 2*qt + 1;
    for (int t = 0; t <= tmax; t++) {
        int buf = t & 1;
        __syncthreads();                       // closes consumers of buf^1
        if (t + 1 <= tmax) load_kv(t + 1, buf ^ 1);
        if (t + 1 <= tmax) CP_WAIT1(); else CP_WAIT0();   // tile t landed
        __syncthreads();                       // visibility to all warps

        bool active = !(t == 2*qt + 1 && wid < 4);
        if (active) {
            // ---- S = Q K^T (q pre-scaled) ----
            float s[8][4];
#pragma unroll
            for (int nt = 0; nt < 8; nt++)
#pragma unroll
                for (int j = 0; j < 4; j++) s[nt][j] = 0.f;
#pragma unroll
            for (int k4 = 0; k4 < 4; k4++) {
#pragma unroll
                for (int np = 0; np < 4; np++) {
                    uint32_t bf0, bf1, bf2, bf3;
                    int row = np*16 + rB;
                    uint32_t a = ks_u[buf] + (uint32_t)(row*128 + (((2*k4 + cB) ^ (row & 7)) << 4));
                    LDSM4(bf0, bf1, bf2, bf3, a);
                    MMA_F16(s[np*2][0], s[np*2][1], s[np*2][2], s[np*2][3],
                            qf[k4][0], qf[k4][1], qf[k4][2], qf[k4][3], bf0, bf1);
                    MMA_F16(s[np*2+1][0], s[np*2+1][1], s[np*2+1][2], s[np*2+1][3],
                            qf[k4][0], qf[k4][1], qf[k4][2], qf[k4][3], bf2, bf3);
                }
            }

            // ---- causal mask (two diagonal tiles only) ----
            if (t >= 2*qt) {
                int qr0 = qt*128 + wid*16 + g;
#pragma unroll
                for (int nt = 0; nt < 8; nt++) {
                    int c0 = t*64 + nt*8 + 2*tg;
                    if (c0     > qr0)   s[nt][0] = -1e30f;
                    if (c0 + 1 > qr0)   s[nt][1] = -1e30f;
                    if (c0     > qr0+8) s[nt][2] = -1e30f;
                    if (c0 + 1 > qr0+8) s[nt][3] = -1e30f;
                }
            }

            // ---- online softmax (rows g, g+8; quad shuffles) ----
            float mm0 = -1e30f, mm1 = -1e30f;
#pragma unroll
            for (int nt = 0; nt < 8; nt++) {
                mm0 = fmaxf(mm0, fmaxf(s[nt][0], s[nt][1]));
                mm1 = fmaxf(mm1, fmaxf(s[nt][2], s[nt][3]));
            }
            mm0 = fmaxf(mm0, __shfl_xor_sync(0xffffffffu, mm0, 1));
            mm0 = fmaxf(mm0, __shfl_xor_sync(0xffffffffu, mm0, 2));
            mm1 = fmaxf(mm1, __shfl_xor_sync(0xffffffffu, mm1, 1));
            mm1 = fmaxf(mm1, __shfl_xor_sync(0xffffffffu, mm1, 2));
            float mn0 = fmaxf(m0, mm0), mn1 = fmaxf(m1, mm1);
            float a0 = expf(m0 - mn0), a1 = expf(m1 - mn1);
            float sum0 = 0.f, sum1 = 0.f;
#pragma unroll
            for (int nt = 0; nt < 8; nt++) {
                s[nt][0] = expf(s[nt][0] - mn0);
                s[nt][1] = expf(s[nt][1] - mn0);
                s[nt][2] = expf(s[nt][2] - mn1);
                s[nt][3] = expf(s[nt][3] - mn1);
                sum0 += s[nt][0] + s[nt][1];
                sum1 += s[nt][2] + s[nt][3];
            }
            sum0 += __shfl_xor_sync(0xffffffffu, sum0, 1);
            sum0 += __shfl_xor_sync(0xffffffffu, sum0, 2);
            sum1 += __shfl_xor_sync(0xffffffffu, sum1, 1);
            sum1 += __shfl_xor_sync(0xffffffffu, sum1, 2);
            l0 = l0*a0 + sum0; m0 = mn0;
            l1 = l1*a1 + sum1; m1 = mn1;
#pragma unroll
            for (int nt = 0; nt < 8; nt++) {
                of[nt][0] *= a0; of[nt][1] *= a0;
                of[nt][2] *= a1; of[nt][3] *= a1;
            }

            // ---- stage P fp16 into own 16-row slab of qp ----
            int pr0 = wid*16 + g;
            int pr1 = pr0 + 8;
#pragma unroll
            for (int nt = 0; nt < 8; nt++) {
                uint32_t a0p = qp_u + (uint32_t)(pr0*128 + (((nt) ^ (pr0 & 7)) << 4) + 4*tg);
                uint32_t a1p = qp_u + (uint32_t)(pr1*128 + (((nt) ^ (pr1 & 7)) << 4) + 4*tg);
                __half2 p0 = __floats2half2_rn(s[nt][0], s[nt][1]);
                __half2 p1 = __floats2half2_rn(s[nt][2], s[nt][3]);
                asm volatile("st.shared.b32 [%0], %1;" :: "r"(a0p), "r"(*(uint32_t*)&p0));
                asm volatile("st.shared.b32 [%0], %1;" :: "r"(a1p), "r"(*(uint32_t*)&p1));
            }
            __syncwarp();

            // ---- O += P V  (V row-major, trans-ldmatrix B frags) ----
#pragma unroll
            for (int k4 = 0; k4 < 4; k4++) {
                uint32_t pf0, pf1, pf2, pf3;
                int prow = wid*16 + rA;
                uint32_t pa = qp_u + (uint32_t)(prow*128 + (((2*k4 + cA) ^ (prow & 7)) << 4));
                LDSM4(pf0, pf1, pf2, pf3, pa);
#pragma unroll
                for (int np = 0; np < 4; np++) {
                    uint32_t bf0, bf1, bf2, bf3;
                    int vrow = k4*16 + rA;                 // key index
                    int vch  = np*2 + cA;                  // d chunk
                    uint32_t a = vs_u[buf] + (uint32_t)(vrow*128 + ((vch ^ (vrow & 7)) << 4));
                    LDSM4T(bf0, bf1, bf2, bf3, a);
                    MMA_F16(of[np*2][0], of[np*2][1], of[np*2][2], of[np*2][3],
                            pf0, pf1, pf2, pf3, bf0, bf1);
                    MMA_F16(of[np*2+1][0], of[np*2+1][1], of[np*2+1][2], of[np*2+1][3],
                            pf0, pf1, pf2, pf3, bf2, bf3);
                }
            }
        }
    }

    float inv0 = 1.f / l0, inv1 = 1.f / l1;
    size_t ro0 = rowbase + (size_t)qt*128 + wid*16 + g;
    size_t ro1 = ro0 + 8;
#pragma unroll
    for (int nt = 0; nt < 8; nt++) {
        int col = h*64 + nt*8 + 2*tg;
        *(__half2*)&oh[ro0*E_ + col] = __floats2half2_rn(of[nt][0]*inv0, of[nt][1]*inv0);
        *(__half2*)&oh[ro1*E_ + col] = __floats2half2_rn(of[nt][2]*inv1, of[nt][3]*inv1);
    }
}

// ---------------------------------------------------------------------------
// Launch
// ---------------------------------------------------------------------------
extern "C" void kernel_launch(void* const* d_in, const int* in_sizes, int n_in,
                              void* d_out, int out_size)
{
    (void)in_sizes; (void)n_in; (void)out_size;
    const float* x   = (const float*)d_in[0];
    const float* Wq  = (const float*)d_in[1];
    const float* Wk  = (const float*)d_in[2];
    const float* Wv  = (const float*)d_in[3];
    const float* Wo  = (const float*)d_in[4];
    const float* bo  = (const float*)d_in[5];
    const float* g1  = (const float*)d_in[6];
    const float* be1 = (const float*)d_in[7];
    const float* g2  = (const float*)d_in[8];
    const float* be2 = (const float*)d_in[9];
    const float* W1  = (const float*)d_in[10];
    const float* bb1 = (const float*)d_in[11];
    const float* W2  = (const float*)d_in[12];
    const float* bb2 = (const float*)d_in[13];
    float* out = (float*)d_out;

    __half *lx, *wqkv, *qkv, *o, *lx2, *ffh, *WoT, *W1T, *W2T;
    float *x2;
    cudaGetSymbolAddress((void**)&lx,   g_lx);
    cudaGetSymbolAddress((void**)&wqkv, g_wqkv);
    cudaGetSymbolAddress((void**)&qkv,  g_qkv);
    cudaGetSymbolAddress((void**)&o,    g_o);
    cudaGetSymbolAddress((void**)&x2,   g_x2);
    cudaGetSymbolAddress((void**)&lx2,  g_lx2);
    cudaGetSymbolAddress((void**)&ffh,  g_ffh);
    cudaGetSymbolAddress((void**)&WoT,  g_WoT);
    cudaGetSymbolAddress((void**)&W1T,  g_W1T);
    cudaGetSymbolAddress((void**)&W2T,  g_W2T);

    cudaFuncSetAttribute(attn4_kernel, cudaFuncAttributeMaxDynamicSharedMemorySize, ATTN4_SMEM);
    cudaFuncSetAttribute(gemm_f16<0>, cudaFuncAttributeMaxDynamicSharedMemorySize, QSMEM);
    cudaFuncSetAttribute(gemm_f16<1>, cudaFuncAttributeMaxDynamicSharedMemorySize, QSMEM);
    cudaFuncSetAttribute(gemm_f16<2>, cudaFuncAttributeMaxDynamicSharedMemorySize, QSMEM);

    // 1. LN1 -> lx (fp16)
    ln_kernel<<<M_, 256>>>(x, g1, be1, lx);
    // 2. weight prep (fp16)
    pack_qkv_kernel<<<(NQKV_*E_)/256, 256>>>(Wq, Wk, Wv, wqkv);
    ttrans_kernel<<<dim3(E_/32,  E_/32),  dim3(32,8)>>>(Wo, WoT, E_,  E_);
    ttrans_kernel<<<dim3(FF_/32, E_/32),  dim3(32,8)>>>(W1, W1T, E_,  FF_);
    ttrans_kernel<<<dim3(E_/32,  FF_/32), dim3(32,8)>>>(W2, W2T, FF_, E_);
    // 3. qkv = lx @ Wqkv (fp16, q cols pre-scaled)
    gemm_f16<0><<<dim3(NQKV_/256, M_/128), 256, QSMEM>>>(
        lx, wqkv, nullptr, qkv, nullptr, nullptr, E_, NQKV_);
    // 4. attention -> o (fp16)
    attn4_kernel<<<dim3(S_/128, B_*H_), 256, ATTN4_SMEM>>>(qkv, o);
    // 5. x2 = x + o @ Wo + bo (f32 out)
    gemm_f16<1><<<dim3(E_/256, M_/128), 256, QSMEM>>>(
        o, WoT, x2, nullptr, bo, x, E_, E_);
    // 6. LN2 -> lx2 (fp16)
    ln_kernel<<<M_, 256>>>(x2, g2, be2, lx2);
    // 7. ffh = relu(lx2 @ W1 + b1) -> fp16
    gemm_f16<2><<<dim3(FF_/256, M_/128), 256, QSMEM>>>(
        lx2, W1T, nullptr, ffh, bb1, nullptr, E_, FF_);
    // 8. out = x2 + ffh @ W2 + b2 (f32 out)
    gemm_f16<1><<<dim3(E_/256, M_/128), 256, QSMEM>>>(
        ffh, W2T, out, nullptr, bb2, x2, FF_, E_);
}

// round 17
// speedup vs baseline: 6.5364x; 1.0221x over previous
#include <cuda_runtime.h>
#include <cuda_fp16.h>
#include <math.h>
#include <stdint.h>

// Problem constants
#define B_    4
#define S_    2048
#define E_    1024
#define H_    16
#define DH_   64
#define M_    (B_*S_)      // 8192 rows
#define FF_   4096
#define NQKV_ 3072

// ---------------------------------------------------------------------------
// Scratch (static __device__ arrays)
// ---------------------------------------------------------------------------
__device__ __half g_lx  [(size_t)M_*E_];        // fp16
__device__ __half g_wqkv[(size_t)NQKV_*E_];     // [N=3072, K=1024] fp16
__device__ __half g_qkv [(size_t)M_*NQKV_];     // fp16, q-cols pre-scaled
__device__ __half g_o   [(size_t)M_*E_];
__device__ float  g_x2  [(size_t)M_*E_];
__device__ __half g_lx2 [(size_t)M_*E_];
__device__ __half g_ffh [(size_t)M_*FF_];
__device__ __half g_WoT [(size_t)E_*E_];        // [N=1024, K=1024] fp16
__device__ __half g_W1T [(size_t)FF_*E_];       // [N=4096, K=1024] fp16
__device__ __half g_W2T [(size_t)E_*FF_];       // [N=1024, K=4096] fp16

// ---------------------------------------------------------------------------
// Helpers
// ---------------------------------------------------------------------------
static __device__ __forceinline__ uint32_t s2u(const void* p) {
    uint32_t a;
    asm("{ .reg .u64 t; cvta.to.shared.u64 t, %1; cvt.u32.u64 %0, t; }" : "=r"(a) : "l"(p));
    return a;
}

#define CP16(dst, src) \
    asm volatile("cp.async.cg.shared.global [%0], [%1], 16;" :: "r"(dst), "l"(src))
#define CP_COMMIT() asm volatile("cp.async.commit_group;")
#define CP_WAIT2()  asm volatile("cp.async.wait_group 2;")
#define CP_WAIT1()  asm volatile("cp.async.wait_group 1;")
#define CP_WAIT0()  asm volatile("cp.async.wait_group 0;")

#define LDSM4(r0, r1, r2, r3, addr) \
    asm volatile("ldmatrix.sync.aligned.m8n8.x4.shared.b16 {%0,%1,%2,%3}, [%4];" \
                 : "=r"(r0), "=r"(r1), "=r"(r2), "=r"(r3) : "r"(addr))

#define LDSM4T(r0, r1, r2, r3, addr) \
    asm volatile("ldmatrix.sync.aligned.m8n8.x4.trans.shared.b16 {%0,%1,%2,%3}, [%4];" \
                 : "=r"(r0), "=r"(r1), "=r"(r2), "=r"(r3) : "r"(addr))

#define MMA_F16(d0, d1, d2, d3, a0, a1, a2, a3, b0, b1) \
    asm volatile("mma.sync.aligned.m16n8k16.row.col.f32.f16.f16.f32 " \
                 "{%0,%1,%2,%3}, {%4,%5,%6,%7}, {%8,%9}, {%0,%1,%2,%3};" \
                 : "+f"(d0), "+f"(d1), "+f"(d2), "+f"(d3) \
                 : "r"(a0), "r"(a1), "r"(a2), "r"(a3), "r"(b0), "r"(b1))

// ---------------------------------------------------------------------------
// LayerNorm -> single fp16 (standalone; used for LN2)
// ---------------------------------------------------------------------------
static __device__ __forceinline__ void ln_row(const float* __restrict__ x,
                                              const float* __restrict__ g,
                                              const float* __restrict__ b,
                                              __half* __restrict__ o,
                                              int row, int t, float* shred)
{
    const float* xr = x + (size_t)row * E_;
    float v[4];
    float s = 0.f, s2 = 0.f;
#pragma unroll
    for (int i = 0; i < 4; i++) {
        v[i] = xr[t + 256*i];
        s += v[i];
        s2 += v[i]*v[i];
    }
#pragma unroll
    for (int m = 16; m; m >>= 1) {
        s  += __shfl_xor_sync(0xffffffffu, s,  m);
        s2 += __shfl_xor_sync(0xffffffffu, s2, m);
    }
    if ((t & 31) == 0) { shred[t>>5] = s; shred[8 + (t>>5)] = s2; }
    __syncthreads();
    s = 0.f; s2 = 0.f;
#pragma unroll
    for (int w = 0; w < 8; w++) { s += shred[w]; s2 += shred[8 + w]; }
    float mu  = s * (1.f/E_);
    float var = s2 * (1.f/E_) - mu*mu;
    float r = rsqrtf(var + 1e-5f);
    size_t rb = (size_t)row * E_;
#pragma unroll
    for (int i = 0; i < 4; i++) {
        int c = t + 256*i;
        o[rb + c] = __float2half_rn((v[i]-mu)*r*g[c] + b[c]);
    }
}

__global__ void ln_kernel(const float* __restrict__ x, const float* __restrict__ g,
                          const float* __restrict__ b, __half* __restrict__ o)
{
    __shared__ float shred[16];
    ln_row(x, g, b, o, blockIdx.x, threadIdx.x, shred);
}

// ---------------------------------------------------------------------------
// Transpose tile helper: in [K,N] f32 -> out [N,K] fp16, 32x32 tile
// ---------------------------------------------------------------------------
static __device__ __forceinline__ void ttrans_tile(const float* __restrict__ in,
                                                   __half* __restrict__ ow,
                                                   int K, int N, int id, int tid,
                                                   float* tbuf /* 32*33 floats */)
{
    int nx = id % (N >> 5), ky = id / (N >> 5);
    int k0 = ky*32, n0 = nx*32;
    int tx = tid & 31, ty = tid >> 5;
#pragma unroll
    for (int r = ty; r < 32; r += 8)
        tbuf[r*33 + tx] = in[(size_t)(k0+r)*N + n0+tx];
    __syncthreads();
#pragma unroll
    for (int r = ty; r < 32; r += 8)
        ow[(size_t)(n0+r)*K + k0+tx] = __float2half_rn(tbuf[tx*33 + r]);
}

// ---------------------------------------------------------------------------
// Merged prep: LN1 + pack_qkv + transpose(Wo,W1,W2), one launch, 256 thr/blk
// ---------------------------------------------------------------------------
#define LN1_BLKS   M_                       // 8192
#define PACK_BLKS  ((NQKV_*E_)/256)         // 12288
#define WO_BLKS    ((E_/32)*(E_/32))        // 1024
#define W1_BLKS    ((FF_/32)*(E_/32))       // 4096
#define W2_BLKS    ((E_/32)*(FF_/32))       // 4096
#define PREP_BLKS  (LN1_BLKS + PACK_BLKS + WO_BLKS + W1_BLKS + W2_BLKS)  // 29696

__global__ void prep_kernel(const float* __restrict__ x, const float* __restrict__ g1,
                            const float* __restrict__ be1, __half* __restrict__ lx,
                            const float* __restrict__ Wq, const float* __restrict__ Wk,
                            const float* __restrict__ Wv, __half* __restrict__ wqkv,
                            const float* __restrict__ Wo, __half* __restrict__ WoT,
                            const float* __restrict__ W1, __half* __restrict__ W1T,
                            const float* __restrict__ W2, __half* __restrict__ W2T)
{
    __shared__ float tbuf[32*33];
    int bid = blockIdx.x;
    int tid = threadIdx.x;
    if (bid < LN1_BLKS) {
        ln_row(x, g1, be1, lx, bid, tid, tbuf);
        return;
    }
    bid -= LN1_BLKS;
    if (bid < PACK_BLKS) {
        int idx = bid*256 + tid;
        int n = idx / E_;
        int e = idx - n*E_;
        const float* W = (n < 1024) ? Wq : (n < 2048 ? Wk : Wv);
        int hd = n & 1023;
        float v = W[(size_t)(hd >> 6)*(E_*DH_) + (size_t)e*DH_ + (hd & 63)];
        wqkv[idx] = __float2half_rn(v);
        return;
    }
    bid -= PACK_BLKS;
    if (bid < WO_BLKS) { ttrans_tile(Wo, WoT, E_,  E_,  bid, tid, tbuf); return; }
    bid -= WO_BLKS;
    if (bid < W1_BLKS) { ttrans_tile(W1, W1T, E_,  FF_, bid, tid, tbuf); return; }
    bid -= W1_BLKS;
    ttrans_tile(W2, W2T, FF_, E_, bid, tid, tbuf);
}

// ---------------------------------------------------------------------------
// Plain fp16 HGEMM, single-sync multistage mainloop (4 buffers, 3 preloaded).
// Ordering per iter: wait(stage i) -> sync -> compute(buf i%4)
//                    -> issue load(stage i+3 -> buf (i+3)%4 == (i-1)%4).
// The single barrier both publishes waited cp.async data and certifies all
// warps finished compute(i-1) on the buffer the new load overwrites.
// EPI: 0 = fp16 out (q-cols pre-scaled), 1 = +bias+res f32, 2 = relu fp16
// ---------------------------------------------------------------------------
#define QSTAGE 49152             // A 16K | B 32K
#define QSMEM (4*QSTAGE)         // 196608

template<int EPI>
__global__ void __launch_bounds__(256, 1) gemm_f16(
    const __half* __restrict__ A, const __half* __restrict__ Bw,
    float* __restrict__ C, __half* __restrict__ Ch,
    const float* __restrict__ bias, const float* __restrict__ res,
    int K, int N)
{
    extern __shared__ char smc[];
    uint32_t sb = s2u(smc);
    int tid = threadIdx.x;
    int wid = tid >> 5, lane = tid & 31;
    int wm = wid >> 2, wn = wid & 3;
    int mblk = blockIdx.y * 128, nblk = blockIdx.x * 256;

    int sub = lane >> 3, L = lane & 7;
    int rA = ((sub & 1) << 3) + L, cAadd = sub >> 1;
    int rB = ((sub >> 1) << 3) + L, cBadd = sub & 1;

    uint32_t sA[4], sB[4];
#pragma unroll
    for (int b = 0; b < 4; b++) {
        uint32_t base = sb + b * QSTAGE;
        sA[b] = base;  sB[b] = base + 16384;
    }

    float acc[4][8][4];
#pragma unroll
    for (int mt = 0; mt < 4; mt++)
#pragma unroll
        for (int nt = 0; nt < 8; nt++)
#pragma unroll
            for (int q = 0; q < 4; q++) acc[mt][nt][q] = 0.f;

    auto load_stage = [&](int s, int b) {
        int k0 = s << 6;
        for (int idx = tid; idx < 1024; idx += 256) {
            int r = idx >> 3, q = idx & 7;
            uint32_t off = (uint32_t)(r*128 + ((q ^ (r & 7)) << 4));
            CP16(sA[b] + off, A + (size_t)(mblk + r) * K + k0 + q*8);
        }
        for (int idx = tid; idx < 2048; idx += 256) {
            int r = idx >> 3, q = idx & 7;
            uint32_t off = (uint32_t)(r*128 + ((q ^ (r & 7)) << 4));
            CP16(sB[b] + off, Bw + (size_t)(nblk + r) * K + k0 + q*8);
        }
        CP_COMMIT();
    };

    const int NS = K >> 6;
    load_stage(0, 0);
    load_stage(1, 1);
    load_stage(2, 2);

    for (int i = 0; i < NS; i++) {
        int buf = i & 3;
        if (i + 2 < NS)      CP_WAIT2();
        else if (i + 1 < NS) CP_WAIT1();
        else                 CP_WAIT0();
        __syncthreads();

#pragma unroll
        for (int ks = 0; ks < 4; ks++) {
            int c0 = 2*ks;
            uint32_t Af[4][4], Bf[4][4];
#pragma unroll
            for (int mt = 0; mt < 4; mt++) {
                int row = wm*64 + mt*16 + rA;
                int ch = c0 + cAadd;
                uint32_t a = sA[buf] + row*128 + ((ch ^ (row & 7)) << 4);
                LDSM4(Af[mt][0], Af[mt][1], Af[mt][2], Af[mt][3], a);
            }
#pragma unroll
            for (int np = 0; np < 4; np++) {
                int row = wn*64 + np*16 + rB;
                int ch = c0 + cBadd;
                uint32_t sw = (uint32_t)(row*128 + ((ch ^ (row & 7)) << 4));
                LDSM4(Bf[np][0], Bf[np][1], Bf[np][2], Bf[np][3], sB[buf] + sw);
            }
#pragma unroll
            for (int mt = 0; mt < 4; mt++)
#pragma unroll
                for (int nt = 0; nt < 8; nt++)
                    MMA_F16(acc[mt][nt][0], acc[mt][nt][1], acc[mt][nt][2], acc[mt][nt][3],
                            Af[mt][0], Af[mt][1], Af[mt][2], Af[mt][3],
                            Bf[nt>>1][(nt&1)*2], Bf[nt>>1][(nt&1)*2+1]);
        }

        if (i + 3 < NS) load_stage(i + 3, (i + 3) & 3);
    }

    // Epilogue
    int g = lane >> 2, tg = lane & 3;
#pragma unroll
    for (int mt = 0; mt < 4; mt++) {
#pragma unroll
        for (int nt = 0; nt < 8; nt++) {
            int row0 = mblk + wm*64 + mt*16 + g;
            int col  = nblk + wn*64 + nt*8 + 2*tg;
#pragma unroll
            for (int half = 0; half < 2; half++) {
                int row = row0 + half*8;
                float v0 = acc[mt][nt][half*2+0];
                float v1 = acc[mt][nt][half*2+1];
                size_t gi = (size_t)row * N + col;
                if (EPI == 0) {
                    float sc = (col < 1024) ? 0.125f : 1.f;
                    *(__half2*)&Ch[gi] = __floats2half2_rn(v0*sc, v1*sc);
                } else if (EPI == 1) {
                    v0 += bias[col]; v1 += bias[col+1];
                    float2 rv = *(const float2*)&res[gi];
                    v0 += rv.x; v1 += rv.y;
                    float2 o; o.x = v0; o.y = v1;
                    *(float2*)&C[gi] = o;
                } else {
                    v0 = fmaxf(v0 + bias[col], 0.f);
                    v1 = fmaxf(v1 + bias[col+1], 0.f);
                    *(__half2*)&Ch[gi] = __floats2half2_rn(v0, v1);
                }
            }
        }
    }
}

// ---------------------------------------------------------------------------
// FP16 flash attention v5: 3-deep K/V ring, single sync per key tile.
// Ordering per tile t: wait(kv t) -> sync -> compute(buf t%3)
//                      -> issue load(kv t+2 -> buf (t+2)%3 == (t-1)%3).
// Math identical to validated attn4 (bit-identical output).
// Smem: qp[128][64] (Q then P), ks[3][64][64], vs[3][64][64] = 65536 B.
// ---------------------------------------------------------------------------
#define ATTN5_SMEM ((128*64 + 6*64*64) * 2)   // 65536 bytes

__global__ void __launch_bounds__(256, 2) attn5_kernel(const __half* __restrict__ qkv,
                                                       __half* __restrict__ oh)
{
    extern __shared__ __half smh[];
    uint32_t qp_u = s2u(smh);
    uint32_t ks_u[3], vs_u[3];
#pragma unroll
    for (int i = 0; i < 3; i++) {
        ks_u[i] = qp_u + 16384 + i * 16384;
        vs_u[i] = ks_u[i] + 8192;
    }

    int tid = threadIdx.x;
    int wid = tid >> 5, lane = tid & 31;
    int qt = (int)(gridDim.x - 1) - (int)blockIdx.x;   // heavy tiles first
    int b = blockIdx.y >> 4, h = blockIdx.y & 15;
    size_t rowbase = (size_t)b * S_;
    int qcol = h*64, kcol = 1024 + h*64, vcol = 2048 + h*64;

    int sub = lane >> 3, L = lane & 7;
    int rA = ((sub & 1) << 3) + L, cA = sub >> 1;      // also V-trans addressing
    int rB = ((sub >> 1) << 3) + L, cB = sub & 1;
    int g = lane >> 2, tg = lane & 3;

    // ---- stage Q via cp.async ----
    for (int idx = tid; idx < 1024; idx += 256) {
        int r = idx >> 3, q8 = idx & 7;
        uint32_t off = (uint32_t)(r*128 + ((q8 ^ (r & 7)) << 4));
        CP16(qp_u + off, qkv + (rowbase + (size_t)qt*128 + r)*NQKV_ + qcol + q8*8);
    }
    CP_COMMIT();

    auto load_kv = [&](int t, int bufi) {
        for (int idx = tid; idx < 512; idx += 256) {
            int r = idx >> 3, q8 = idx & 7;
            uint32_t off = (uint32_t)(r*128 + ((q8 ^ (r & 7)) << 4));
            size_t tok = (rowbase + (size_t)t*64 + r) * NQKV_;
            CP16(ks_u[bufi] + off, qkv + tok + kcol + q8*8);
            CP16(vs_u[bufi] + off, qkv + tok + vcol + q8*8);
        }
        CP_COMMIT();
    };

    int tmax = 2*qt + 1;                 // tmax >= 1 always
    load_kv(0, 0);
    load_kv(1, 1);
    CP_WAIT2();          // Q landed (kv0, kv1 may still fly)
    __syncthreads();

    uint32_t qf[4][4];
#pragma unroll
    for (int k4 = 0; k4 < 4; k4++) {
        int row = wid*16 + rA;
        uint32_t a = qp_u + (uint32_t)(row*128 + (((2*k4 + cA) ^ (row & 7)) << 4));
        LDSM4(qf[k4][0], qf[k4][1], qf[k4][2], qf[k4][3], a);
    }

    float m0 = -1e30f, m1 = -1e30f, l0 = 0.f, l1 = 0.f;
    float of[8][4];
#pragma unroll
    for (int nt = 0; nt < 8; nt++)
#pragma unroll
        for (int j = 0; j < 4; j++) of[nt][j] = 0.f;

    int buf = 0;
    for (int t = 0; t <= tmax; t++) {
        if (t < tmax) CP_WAIT1(); else CP_WAIT0();
        __syncthreads();

        bool active = !(t == 2*qt + 1 && wid < 4);
        if (active) {
            // ---- S = Q K^T (q pre-scaled) ----
            float s[8][4];
#pragma unroll
            for (int nt = 0; nt < 8; nt++)
#pragma unroll
                for (int j = 0; j < 4; j++) s[nt][j] = 0.f;
#pragma unroll
            for (int k4 = 0; k4 < 4; k4++) {
#pragma unroll
                for (int np = 0; np < 4; np++) {
                    uint32_t bf0, bf1, bf2, bf3;
                    int row = np*16 + rB;
                    uint32_t a = ks_u[buf] + (uint32_t)(row*128 + (((2*k4 + cB) ^ (row & 7)) << 4));
                    LDSM4(bf0, bf1, bf2, bf3, a);
                    MMA_F16(s[np*2][0], s[np*2][1], s[np*2][2], s[np*2][3],
                            qf[k4][0], qf[k4][1], qf[k4][2], qf[k4][3], bf0, bf1);
                    MMA_F16(s[np*2+1][0], s[np*2+1][1], s[np*2+1][2], s[np*2+1][3],
                            qf[k4][0], qf[k4][1], qf[k4][2], qf[k4][3], bf2, bf3);
                }
            }

            // ---- causal mask (two diagonal tiles only) ----
            if (t >= 2*qt) {
                int qr0 = qt*128 + wid*16 + g;
#pragma unroll
                for (int nt = 0; nt < 8; nt++) {
                    int c0 = t*64 + nt*8 + 2*tg;
                    if (c0     > qr0)   s[nt][0] = -1e30f;
                    if (c0 + 1 > qr0)   s[nt][1] = -1e30f;
                    if (c0     > qr0+8) s[nt][2] = -1e30f;
                    if (c0 + 1 > qr0+8) s[nt][3] = -1e30f;
                }
            }

            // ---- online softmax (rows g, g+8; quad shuffles) ----
            float mm0 = -1e30f, mm1 = -1e30f;
#pragma unroll
            for (int nt = 0; nt < 8; nt++) {
                mm0 = fmaxf(mm0, fmaxf(s[nt][0], s[nt][1]));
                mm1 = fmaxf(mm1, fmaxf(s[nt][2], s[nt][3]));
            }
            mm0 = fmaxf(mm0, __shfl_xor_sync(0xffffffffu, mm0, 1));
            mm0 = fmaxf(mm0, __shfl_xor_sync(0xffffffffu, mm0, 2));
            mm1 = fmaxf(mm1, __shfl_xor_sync(0xffffffffu, mm1, 1));
            mm1 = fmaxf(mm1, __shfl_xor_sync(0xffffffffu, mm1, 2));
            float mn0 = fmaxf(m0, mm0), mn1 = fmaxf(m1, mm1);
            float a0 = expf(m0 - mn0), a1 = expf(m1 - mn1);
            float sum0 = 0.f, sum1 = 0.f;
#pragma unroll
            for (int nt = 0; nt < 8; nt++) {
                s[nt][0] = expf(s[nt][0] - mn0);
                s[nt][1] = expf(s[nt][1] - mn0);
                s[nt][2] = expf(s[nt][2] - mn1);
                s[nt][3] = expf(s[nt][3] - mn1);
                sum0 += s[nt][0] + s[nt][1];
                sum1 += s[nt][2] + s[nt][3];
            }
            sum0 += __shfl_xor_sync(0xffffffffu, sum0, 1);
            sum0 += __shfl_xor_sync(0xffffffffu, sum0, 2);
            sum1 += __shfl_xor_sync(0xffffffffu, sum1, 1);
            sum1 += __shfl_xor_sync(0xffffffffu, sum1, 2);
            l0 = l0*a0 + sum0; m0 = mn0;
            l1 = l1*a1 + sum1; m1 = mn1;
#pragma unroll
            for (int nt = 0; nt < 8; nt++) {
                of[nt][0] *= a0; of[nt][1] *= a0;
                of[nt][2] *= a1; of[nt][3] *= a1;
            }

            // ---- stage P fp16 into own 16-row slab of qp ----
            int pr0 = wid*16 + g;
            int pr1 = pr0 + 8;
#pragma unroll
            for (int nt = 0; nt < 8; nt++) {
                uint32_t a0p = qp_u + (uint32_t)(pr0*128 + (((nt) ^ (pr0 & 7)) << 4) + 4*tg);
                uint32_t a1p = qp_u + (uint32_t)(pr1*128 + (((nt) ^ (pr1 & 7)) << 4) + 4*tg);
                __half2 p0 = __floats2half2_rn(s[nt][0], s[nt][1]);
                __half2 p1 = __floats2half2_rn(s[nt][2], s[nt][3]);
                asm volatile("st.shared.b32 [%0], %1;" :: "r"(a0p), "r"(*(uint32_t*)&p0));
                asm volatile("st.shared.b32 [%0], %1;" :: "r"(a1p), "r"(*(uint32_t*)&p1));
            }
            __syncwarp();

            // ---- O += P V  (V row-major, trans-ldmatrix B frags) ----
#pragma unroll
            for (int k4 = 0; k4 < 4; k4++) {
                uint32_t pf0, pf1, pf2, pf3;
                int prow = wid*16 + rA;
                uint32_t pa = qp_u + (uint32_t)(prow*128 + (((2*k4 + cA) ^ (prow & 7)) << 4));
                LDSM4(pf0, pf1, pf2, pf3, pa);
#pragma unroll
                for (int np = 0; np < 4; np++) {
                    uint32_t bf0, bf1, bf2, bf3;
                    int vrow = k4*16 + rA;                 // key index
                    int vch  = np*2 + cA;                  // d chunk
                    uint32_t a = vs_u[buf] + (uint32_t)(vrow*128 + ((vch ^ (vrow & 7)) << 4));
                    LDSM4T(bf0, bf1, bf2, bf3, a);
                    MMA_F16(of[np*2][0], of[np*2][1], of[np*2][2], of[np*2][3],
                            pf0, pf1, pf2, pf3, bf0, bf1);
                    MMA_F16(of[np*2+1][0], of[np*2+1][1], of[np*2+1][2], of[np*2+1][3],
                            pf0, pf1, pf2, pf3, bf2, bf3);
                }
            }
        }

        // issue next-next tile into buf (t+2)%3 == (t-1)%3 (closed by this
        // iteration's barrier)
        if (t + 2 <= tmax) {
            int lb = buf + 2; if (lb >= 3) lb -= 3;
            load_kv(t + 2, lb);
        }
        buf = (buf == 2) ? 0 : buf + 1;
    }

    float inv0 = 1.f / l0, inv1 = 1.f / l1;
    size_t ro0 = rowbase + (size_t)qt*128 + wid*16 + g;
    size_t ro1 = ro0 + 8;
#pragma unroll
    for (int nt = 0; nt < 8; nt++) {
        int col = h*64 + nt*8 + 2*tg;
        *(__half2*)&oh[ro0*E_ + col] = __floats2half2_rn(of[nt][0]*inv0, of[nt][1]*inv0);
        *(__half2*)&oh[ro1*E_ + col] = __floats2half2_rn(of[nt][2]*inv1, of[nt][3]*inv1);
    }
}

// ---------------------------------------------------------------------------
// Launch
// ---------------------------------------------------------------------------
extern "C" void kernel_launch(void* const* d_in, const int* in_sizes, int n_in,
                              void* d_out, int out_size)
{
    (void)in_sizes; (void)n_in; (void)out_size;
    const float* x   = (const float*)d_in[0];
    const float* Wq  = (const float*)d_in[1];
    const float* Wk  = (const float*)d_in[2];
    const float* Wv  = (const float*)d_in[3];
    const float* Wo  = (const float*)d_in[4];
    const float* bo  = (const float*)d_in[5];
    const float* g1  = (const float*)d_in[6];
    const float* be1 = (const float*)d_in[7];
    const float* g2  = (const float*)d_in[8];
    const float* be2 = (const float*)d_in[9];
    const float* W1  = (const float*)d_in[10];
    const float* bb1 = (const float*)d_in[11];
    const float* W2  = (const float*)d_in[12];
    const float* bb2 = (const float*)d_in[13];
    float* out = (float*)d_out;

    __half *lx, *wqkv, *qkv, *o, *lx2, *ffh, *WoT, *W1T, *W2T;
    float *x2;
    cudaGetSymbolAddress((void**)&lx,   g_lx);
    cudaGetSymbolAddress((void**)&wqkv, g_wqkv);
    cudaGetSymbolAddress((void**)&qkv,  g_qkv);
    cudaGetSymbolAddress((void**)&o,    g_o);
    cudaGetSymbolAddress((void**)&x2,   g_x2);
    cudaGetSymbolAddress((void**)&lx2,  g_lx2);
    cudaGetSymbolAddress((void**)&ffh,  g_ffh);
    cudaGetSymbolAddress((void**)&WoT,  g_WoT);
    cudaGetSymbolAddress((void**)&W1T,  g_W1T);
    cudaGetSymbolAddress((void**)&W2T,  g_W2T);

    cudaFuncSetAttribute(attn5_kernel, cudaFuncAttributeMaxDynamicSharedMemorySize, ATTN5_SMEM);
    cudaFuncSetAttribute(gemm_f16<0>, cudaFuncAttributeMaxDynamicSharedMemorySize, QSMEM);
    cudaFuncSetAttribute(gemm_f16<1>, cudaFuncAttributeMaxDynamicSharedMemorySize, QSMEM);
    cudaFuncSetAttribute(gemm_f16<2>, cudaFuncAttributeMaxDynamicSharedMemorySize, QSMEM);

    // 1. merged prep: LN1 + pack qkv weights + transpose Wo/W1/W2
    prep_kernel<<<PREP_BLKS, 256>>>(x, g1, be1, lx, Wq, Wk, Wv, wqkv,
                                    Wo, WoT, W1, W1T, W2, W2T);
    // 2. qkv = lx @ Wqkv (fp16, q cols pre-scaled)
    gemm_f16<0><<<dim3(NQKV_/256, M_/128), 256, QSMEM>>>(
        lx, wqkv, nullptr, qkv, nullptr, nullptr, E_, NQKV_);
    // 3. attention -> o (fp16)
    attn5_kernel<<<dim3(S_/128, B_*H_), 256, ATTN5_SMEM>>>(qkv, o);
    // 4. x2 = x + o @ Wo + bo (f32 out)
    gemm_f16<1><<<dim3(E_/256, M_/128), 256, QSMEM>>>(
        o, WoT, x2, nullptr, bo, x, E_, E_);
    // 5. LN2 -> lx2 (fp16)
    ln_kernel<<<M_, 256>>>(x2, g2, be2, lx2);
    // 6. ffh = relu(lx2 @ W1 + b1) -> fp16
    gemm_f16<2><<<dim3(FF_/256, M_/128), 256, QSMEM>>>(
        lx2, W1T, nullptr, ffh, bb1, nullptr, E_, FF_);
    // 7. out = x2 + ffh @ W2 + b2 (f32 out)
    gemm_f16<1><<<dim3(E_/256, M_/128), 256, QSMEM>>>(
        ffh, W2T, out, nullptr, bb2, x2, FF_, E_);
}